// round 11
// baseline (speedup 1.0000x reference)
#include <cuda_runtime.h>
#include <cuda_fp16.h>
#include <math.h>
#include <stdint.h>

#define B_SZ   16384
#define H_SZ   512
#define NODES  9
#define ROWS   (B_SZ * NODES)         // 147456
#define BH     (ROWS * H_SZ)          // 75497472

// ---------------- scratch (device globals; no allocation) ----------------
__device__ __half g_mh[BH], g_ml[BH];
__device__ __half g_ah[BH], g_al[BH];
__device__ __half g_nh[BH], g_nl[BH];
__device__ __half g_xh[B_SZ * H_SZ], g_xl[B_SZ * H_SZ];
__device__ float  g_f[2ull * BH];     // QV combined output: ROWS x 1024

// weights [N,K] K-major, K=512, hi/lo half pairs
#define OFF_WIN   0                    // 4608*512
#define OFF_WDR   2359296
#define OFF_WHYP  2621440
#define OFF_QUAT  2883584
#define OFF_WAV   3145728
#define OFF_ATT   3407872              // per layer: {Bt_qk, Bt_vo} contiguous (1024x512)
#define OFF_WOUT  6553600              // 128*512
#define WTS_TOTAL 6619136
__device__ __half g_wh[WTS_TOTAL], g_wl[WTS_TOTAL];

// ============================================================================
// helpers
// ============================================================================
__device__ __forceinline__ uint32_t smem_u32(const void* p) {
    uint32_t a;
    asm("{ .reg .u64 t; cvta.to.shared.u64 t, %1; cvt.u32.u64 %0, t; }" : "=r"(a) : "l"(p));
    return a;
}
__device__ __forceinline__ void cp_async16(uint32_t dst, const void* src) {
    asm volatile("cp.async.cg.shared.global [%0], [%1], 16;" :: "r"(dst), "l"(src) : "memory");
}
__device__ __forceinline__ void cp_commit() {
    asm volatile("cp.async.commit_group;" ::: "memory");
}
__device__ __forceinline__ void cp_wait1() {
    asm volatile("cp.async.wait_group 1;" ::: "memory");
}
__device__ __forceinline__ void ldm_x4(uint32_t addr, uint32_t& r0, uint32_t& r1,
                                       uint32_t& r2, uint32_t& r3) {
    asm volatile("ldmatrix.sync.aligned.m8n8.x4.shared.b16 {%0,%1,%2,%3}, [%4];"
                 : "=r"(r0), "=r"(r1), "=r"(r2), "=r"(r3) : "r"(addr));
}
__device__ __forceinline__ void mma_f16(float* c, const uint32_t* a, const uint32_t* b) {
    asm volatile(
        "mma.sync.aligned.m16n8k16.row.col.f32.f16.f16.f32 "
        "{%0,%1,%2,%3}, {%4,%5,%6,%7}, {%8,%9}, {%0,%1,%2,%3};"
        : "+f"(c[0]), "+f"(c[1]), "+f"(c[2]), "+f"(c[3])
        : "r"(a[0]), "r"(a[1]), "r"(a[2]), "r"(a[3]), "r"(b[0]), "r"(b[1]));
}
__device__ __forceinline__ void split2(float d0, float d1, __half2& h, __half2& l) {
    __half h0 = __float2half_rn(d0), h1 = __float2half_rn(d1);
    h = __halves2half2(h0, h1);
    l = __floats2half2_rn(d0 - __half2float(h0), d1 - __half2float(h1));
}

// ============================================================================
// fp16x3 GEMM: C[M,N] = A[M,512] @ Bt[N,512]^T   (term-major MMA ordering)
// EPI: 0 fp32 C; 1 bias+lrelu -> HL; 2 bias+tanh -> HL; 3 bias -> fp32
// BM=64, BN=128, 256 thr, 8 warps (2x4), warp 32x32, 2-stage, 2 CTAs/SM
// ============================================================================
#define A_ST 8192
#define B_ST 16384
#define HG_SMEM (2 * (2 * A_ST + 2 * B_ST) + 1024)

template<int EPI>
__global__ __launch_bounds__(256, 2)
void hgemm3(const __half* __restrict__ Ah, const __half* __restrict__ Al,
            const __half* __restrict__ Bh, const __half* __restrict__ Bl,
            const float* __restrict__ bias, float* __restrict__ C,
            __half* __restrict__ Ch, __half* __restrict__ Cl,
            int N, int lda)
{
    extern __shared__ char smraw[];
    const uint32_t base = (smem_u32(smraw) + 1023) & ~1023u;
    const uint32_t sAh = base;
    const uint32_t sAl = base + 2 * A_ST;
    const uint32_t sBh = base + 4 * A_ST;
    const uint32_t sBl = base + 4 * A_ST + 2 * B_ST;

    const int col0 = blockIdx.x * 128;
    const int row0 = blockIdx.y * 64;

    const int tid    = threadIdx.x;
    const int lane   = tid & 31;
    const int wid    = tid >> 5;
    const int warp_m = wid >> 2;
    const int warp_n = wid & 3;

    const int lm = tid >> 3;
    const int lq = tid & 7;

    const int mat = lane >> 3;
    const int mr  = lane & 7;
    int rbA[2], s7A[2];
    #pragma unroll
    for (int mf = 0; mf < 2; ++mf) {
        int m = warp_m * 32 + mf * 16 + (mat & 1) * 8 + mr;
        rbA[mf] = m * 128; s7A[mf] = m & 7;
    }
    const int qaA = mat >> 1;
    int rbB[2], s7B[2];
    #pragma unroll
    for (int p = 0; p < 2; ++p) {
        int n = warp_n * 32 + (2 * p + (mat >> 1)) * 8 + mr;
        rbB[p] = n * 128; s7B[p] = n & 7;
    }
    const int qaB = mat & 1;

    float acc[2][4][4];
    #pragma unroll
    for (int i = 0; i < 2; ++i)
        #pragma unroll
        for (int j = 0; j < 4; ++j)
            #pragma unroll
            for (int k = 0; k < 4; ++k) acc[i][j][k] = 0.f;

    #pragma unroll
    for (int st = 0; st < 2; ++st) {
        #pragma unroll
        for (int i = 0; i < 2; ++i) {
            const int row = lm + i * 32;
            const uint32_t d = st * A_ST + row * 128 + (((lq ^ (row & 7)) << 4));
            const size_t oa = (size_t)(row0 + row) * lda + st * 64 + lq * 8;
            cp_async16(sAh + d, Ah + oa);
            cp_async16(sAl + d, Al + oa);
        }
        #pragma unroll
        for (int i = 0; i < 4; ++i) {
            const int row = lm + i * 32;
            const uint32_t d = st * B_ST + row * 128 + (((lq ^ (row & 7)) << 4));
            const size_t ob = (size_t)(col0 + row) * 512 + st * 64 + lq * 8;
            cp_async16(sBh + d, Bh + ob);
            cp_async16(sBl + d, Bl + ob);
        }
        cp_commit();
    }

    #pragma unroll 1
    for (int t = 0; t < 8; ++t) {
        cp_wait1();
        __syncthreads();

        const uint32_t pAh = sAh + (t & 1) * A_ST;
        const uint32_t pAl = sAl + (t & 1) * A_ST;
        const uint32_t pBh = sBh + (t & 1) * B_ST;
        const uint32_t pBl = sBl + (t & 1) * B_ST;

        #pragma unroll
        for (int ks = 0; ks < 4; ++ks) {
            uint32_t ah[2][4], al[2][4];
            #pragma unroll
            for (int mf = 0; mf < 2; ++mf) {
                const uint32_t off = rbA[mf] + (((2 * ks + qaA) ^ s7A[mf]) << 4);
                ldm_x4(pAh + off, ah[mf][0], ah[mf][1], ah[mf][2], ah[mf][3]);
                ldm_x4(pAl + off, al[mf][0], al[mf][1], al[mf][2], al[mf][3]);
            }
            #pragma unroll
            for (int p = 0; p < 2; ++p) {
                uint32_t bh[2][2], bl[2][2];
                const uint32_t off = rbB[p] + (((2 * ks + qaB) ^ s7B[p]) << 4);
                ldm_x4(pBh + off, bh[0][0], bh[0][1], bh[1][0], bh[1][1]);
                ldm_x4(pBl + off, bl[0][0], bl[0][1], bl[1][0], bl[1][1]);
                // term-major: 4 independent accs between same-acc reuse
                #pragma unroll
                for (int mf = 0; mf < 2; ++mf)
                    #pragma unroll
                    for (int q = 0; q < 2; ++q)
                        mma_f16(acc[mf][2 * p + q], ah[mf], bh[q]);
                #pragma unroll
                for (int mf = 0; mf < 2; ++mf)
                    #pragma unroll
                    for (int q = 0; q < 2; ++q)
                        mma_f16(acc[mf][2 * p + q], ah[mf], bl[q]);
                #pragma unroll
                for (int mf = 0; mf < 2; ++mf)
                    #pragma unroll
                    for (int q = 0; q < 2; ++q)
                        mma_f16(acc[mf][2 * p + q], al[mf], bh[q]);
            }
        }
        __syncthreads();
        if (t + 2 < 8) {
            const int st = t & 1;
            #pragma unroll
            for (int i = 0; i < 2; ++i) {
                const int row = lm + i * 32;
                const uint32_t d = st * A_ST + row * 128 + (((lq ^ (row & 7)) << 4));
                const size_t oa = (size_t)(row0 + row) * lda + (t + 2) * 64 + lq * 8;
                cp_async16(sAh + d, Ah + oa);
                cp_async16(sAl + d, Al + oa);
            }
            #pragma unroll
            for (int i = 0; i < 4; ++i) {
                const int row = lm + i * 32;
                const uint32_t d = st * B_ST + row * 128 + (((lq ^ (row & 7)) << 4));
                const size_t ob = (size_t)(col0 + row) * 512 + (t + 2) * 64 + lq * 8;
                cp_async16(sBh + d, Bh + ob);
                cp_async16(sBl + d, Bl + ob);
            }
        }
        cp_commit();
    }

    const int g  = lane >> 2;
    const int t4 = lane & 3;
    #pragma unroll
    for (int mf = 0; mf < 2; ++mf) {
        #pragma unroll
        for (int nf = 0; nf < 4; ++nf) {
            const int r1 = row0 + warp_m * 32 + mf * 16 + g;
            const int cc = col0 + warp_n * 32 + nf * 8 + t4 * 2;
            float d[4] = {acc[mf][nf][0], acc[mf][nf][1], acc[mf][nf][2], acc[mf][nf][3]};
            if (EPI != 0) {
                float b0 = __ldg(bias + cc), b1 = __ldg(bias + cc + 1);
                d[0] += b0; d[1] += b1; d[2] += b0; d[3] += b1;
                #pragma unroll
                for (int i = 0; i < 4; ++i) {
                    if (EPI == 1)      d[i] = d[i] > 0.f ? d[i] : 0.01f * d[i];
                    else if (EPI == 2) d[i] = tanhf(d[i]);
                }
            }
            if (EPI == 0 || EPI == 3) {
                *(float2*)(C + (size_t)r1 * N + cc)       = make_float2(d[0], d[1]);
                *(float2*)(C + (size_t)(r1 + 8) * N + cc) = make_float2(d[2], d[3]);
            } else {
                __half2 h, l;
                split2(d[0], d[1], h, l);
                *(__half2*)(Ch + (size_t)r1 * N + cc) = h;
                *(__half2*)(Cl + (size_t)r1 * N + cc) = l;
                split2(d[2], d[3], h, l);
                *(__half2*)(Ch + (size_t)(r1 + 8) * N + cc) = h;
                *(__half2*)(Cl + (size_t)(r1 + 8) * N + cc) = l;
            }
        }
    }
}

// ============================================================================
// weight prep (non-attention weights)
// ============================================================================
__constant__ int   c_which[16] = {0,1,2,3, 1,0,3,2, 2,3,0,1, 3,2,1,0};
__constant__ float c_sign [16] = {1.f,-1.f,-1.f,-1.f,
                                  1.f, 1.f, 1.f,-1.f,
                                  1.f,-1.f, 1.f, 1.f,
                                  1.f, 1.f,-1.f, 1.f};

__global__ void prep_weights(
    const float* __restrict__ W_in,  const float* __restrict__ W_dr,
    const float* __restrict__ W_hyp, const float* __restrict__ Wq_r,
    const float* __restrict__ Wq_i,  const float* __restrict__ Wq_j,
    const float* __restrict__ Wq_k,  const float* __restrict__ W_low,
    const float* __restrict__ W_high,const float* __restrict__ W_out,
    __half* __restrict__ oh, __half* __restrict__ ol)
{
    int idx = blockIdx.x * 256 + threadIdx.x;
    if (idx >= WTS_TOTAL) return;
    if (idx >= OFF_ATT && idx < OFF_WOUT) return;   // filled by combine_attn
    float v;
    if (idx < OFF_WDR) {
        int n = idx >> 9, k = idx & 511;
        v = W_in[(size_t)k * 4608 + n];
    } else if (idx < OFF_WHYP) {
        int r = idx - OFF_WDR, n = r >> 9, k = r & 511;
        v = W_dr[(size_t)k * 512 + n];
    } else if (idx < OFF_QUAT) {
        int r = idx - OFF_WHYP, n = r >> 9, k = r & 511;
        v = W_hyp[(size_t)k * 512 + n];
    } else if (idx < OFF_WAV) {
        int r = idx - OFF_QUAT, n = r >> 9, k = r & 511;
        int co = n >> 7, ho = n & 127, ci = k >> 7, hi = k & 127;
        const float* mats[4] = {Wq_r, Wq_i, Wq_j, Wq_k};
        int sel = co * 4 + ci;
        v = c_sign[sel] * mats[c_which[sel]][hi * 128 + ho];
    } else if (idx < OFF_ATT) {
        int r = idx - OFF_WAV, n = r >> 9, k = r & 511;
        int ho = n >> 1, po = n & 1, hi = k >> 1, pi = k & 1;
        float wl = W_low[hi * 256 + ho], wh = W_high[hi * 256 + ho];
        v = (pi == po) ? 0.5f * (wl + wh) : 0.5f * (wl - wh);
    } else {
        int r = idx - OFF_WOUT, n = r >> 9, k = r & 511;
        v = W_out[(size_t)k * 128 + n];
    }
    __half h = __float2half_rn(v);
    oh[idx] = h;
    ol[idx] = __float2half_rn(v - __half2float(h));
}

// combined attention weights (layer block = [Mqk(512) ; Mvo(512)] rows, K=512)
__global__ void combine_attn(const float* __restrict__ aWq, const float* __restrict__ aWk,
                             const float* __restrict__ aWv, const float* __restrict__ aWo,
                             __half* __restrict__ oh, __half* __restrict__ ol)
{
    __shared__ float As[16][17], Bs[16][17];
    const int z = blockIdx.z, l = z >> 1, type = z & 1;
    const int tx = threadIdx.x, ty = threadIdx.y;
    const size_t wl_off = (size_t)l * 262144;
    const float* Wq = aWq + wl_off;
    const float* Wk = aWk + wl_off;
    const float* Wv = aWv + wl_off;
    const float* Wo = aWo + wl_off;

    float acc = 0.f;
    for (int m0 = 0; m0 < 512; m0 += 16) {
        if (type == 0) {
            As[ty][tx] = Wk[(size_t)(blockIdx.y * 16 + ty) * 512 + m0 + tx];
            Bs[ty][tx] = Wq[(size_t)(blockIdx.x * 16 + ty) * 512 + m0 + tx];
        } else {
            As[ty][tx] = Wo[(size_t)(m0 + ty) * 512 + blockIdx.y * 16 + tx];
            Bs[ty][tx] = Wv[(size_t)(blockIdx.x * 16 + ty) * 512 + m0 + tx];
        }
        __syncthreads();
        if (type == 0) {
            #pragma unroll
            for (int h = 0; h < 16; ++h) acc += As[ty][h] * Bs[tx][h];
        } else {
            #pragma unroll
            for (int m = 0; m < 16; ++m) acc += Bs[tx][m] * As[m][ty];
        }
        __syncthreads();
    }
    const int n = blockIdx.y * 16 + ty;
    const int k = blockIdx.x * 16 + tx;
    const size_t o = (size_t)OFF_ATT + (size_t)z * 262144 + (size_t)n * 512 + k;
    __half h = __float2half_rn(acc);
    oh[o] = h;
    ol[o] = __float2half_rn(acc - __half2float(h));
}

__global__ void split_copy(const float4* __restrict__ in, __half* __restrict__ H,
                           __half* __restrict__ L, int n4)
{
    int i = blockIdx.x * 256 + threadIdx.x;
    if (i >= n4) return;
    float4 v = in[i];
    __half2 h, l;
    split2(v.x, v.y, h, l);
    ((__half2*)H)[2*i]   = h; ((__half2*)L)[2*i]   = l;
    split2(v.z, v.w, h, l);
    ((__half2*)H)[2*i+1] = h; ((__half2*)L)[2*i+1] = l;
}

// ============================================================================
// standalone agg (used once, after W_dr)
// ============================================================================
__global__ void agg_hl(const __half2* __restrict__ ih, const __half2* __restrict__ il,
                       __half2* __restrict__ oh, __half2* __restrict__ ol)
{
    int idx = blockIdx.x * 256 + threadIdx.x;
    const int TOT = B_SZ * NODES * 256;
    if (idx >= TOT) return;
    int h2 = idx & 255;
    int rn = (idx >> 8) % NODES;
    int b  = idx / (NODES * 256);
    size_t p = (size_t)(b * NODES + rn) * 256 + h2;
    __half2 xh = ih[p], xl = il[p];
    if (rn == 8) { oh[idx] = xh; ol[idx] = xl; return; }
    int src = (rn & 1) ? (rn >> 1) : (rn >> 1) + 4;
    size_t q = (size_t)(b * NODES + src) * 256 + h2;
    float2 fa = __half22float2(xh), fal = __half22float2(xl);
    float2 fc = __half22float2(ih[q]), fcl = __half22float2(il[q]);
    float v0 = 0.5f * ((fa.x + fal.x) + (fc.x + fcl.x));
    float v1 = 0.5f * ((fa.y + fal.y) + (fc.y + fcl.y));
    __half2 h, l;
    split2(v0, v1, h, l);
    oh[idx] = h; ol[idx] = l;
}

// ============================================================================
// fused attention + drnorm + residual + agg; QV is ROWS x 1024 (Q | V)
// ============================================================================
#define AF_SMEM (3 * NODES * H_SZ * 4 + 512)

__global__ __launch_bounds__(256)
void attn_fused(const float* __restrict__ QV,
                const __half* __restrict__ vh, const __half* __restrict__ vl,
                const float* __restrict__ gamma, const float* __restrict__ beta,
                __half* __restrict__ mh, __half* __restrict__ ml)
{
    extern __shared__ float sm[];
    float* sK = sm;                        // v (fp32)          9*512
    float* sV = sm + NODES * H_SZ;         // V                 9*512
    float* sO = sm + 2 * NODES * H_SZ;     // ctx -> nf         9*512
    float* sS = sm + 3 * NODES * H_SZ;     // scores            96

    const int b   = blockIdx.x;
    const int tid = threadIdx.x;
    const size_t base   = (size_t)b * NODES * H_SZ;          // hl-pair layout
    const size_t baseQV = (size_t)b * NODES * 1024;          // QV layout

    const __half2* K2h = (const __half2*)(vh + base);
    const __half2* K2l = (const __half2*)(vl + base);
    for (int i = tid; i < NODES * H_SZ / 2; i += 256) {
        float2 h = __half22float2(K2h[i]);
        float2 l = __half22float2(K2l[i]);
        sK[2*i]   = h.x + l.x;
        sK[2*i+1] = h.y + l.y;
    }
    for (int i = tid; i < NODES * H_SZ / 4; i += 256) {
        int rn = i >> 7, c4 = i & 127;                       // 128 float4 per row
        ((float4*)sV)[i] = *(const float4*)(QV + baseQV + (size_t)rn * 1024 + 512 + c4 * 4);
    }
    __syncthreads();

    const float scale = 0.044194173824159216f;   // 1/sqrt(512)
    const int warp = tid >> 5, lane = tid & 31;
    for (int p = warp; p < 81; p += 8) {
        int q = p / 9, kk = p % 9;
        const float* Qr = QV + baseQV + (size_t)q * 1024;
        float s = 0.f;
        #pragma unroll 4
        for (int h = lane; h < H_SZ; h += 32) s += Qr[h] * sK[kk * H_SZ + h];
        #pragma unroll
        for (int o = 16; o; o >>= 1) s += __shfl_down_sync(0xffffffffu, s, o);
        if (lane == 0) sS[q * 9 + kk] = s * scale;
    }
    __syncthreads();

    if (tid < 9) {
        float mx = -1e30f;
        #pragma unroll
        for (int k = 0; k < 9; ++k) mx = fmaxf(mx, sS[tid * 9 + k]);
        float sum = 0.f;
        #pragma unroll
        for (int k = 0; k < 9; ++k) { float e = expf(sS[tid * 9 + k] - mx); sS[tid * 9 + k] = e; sum += e; }
        float inv = 1.f / sum;
        #pragma unroll
        for (int k = 0; k < 9; ++k) sS[tid * 9 + k] *= inv;
    }
    __syncthreads();

    for (int q = 0; q < 9; ++q) {
        float a[9];
        #pragma unroll
        for (int k = 0; k < 9; ++k) a[k] = sS[q * 9 + k];
        for (int h = tid * 2; h < H_SZ; h += 512) {
            float a0 = 0.f, a1 = 0.f;
            #pragma unroll
            for (int k = 0; k < 9; ++k) {
                a0 = fmaf(a[k], sV[k * H_SZ + h],     a0);
                a1 = fmaf(a[k], sV[k * H_SZ + h + 1], a1);
            }
            sO[q * H_SZ + h]     = a0;
            sO[q * H_SZ + h + 1] = a1;
        }
    }
    __syncthreads();

    for (int r = warp; r < 9; r += 8) {
        const float* o = sO + r * H_SZ;
        float s = 0.f, sq = 0.f;
        #pragma unroll
        for (int i = 0; i < 16; ++i) {
            float v = o[lane + 32 * i];
            s += v; sq += v * v;
        }
        #pragma unroll
        for (int off = 16; off; off >>= 1) {
            s  += __shfl_down_sync(0xffffffffu, s, off);
            sq += __shfl_down_sync(0xffffffffu, sq, off);
        }
        float mu  = __shfl_sync(0xffffffffu, s,  0) * (1.f / 512.f);
        float msq = __shfl_sync(0xffffffffu, sq, 0) * (1.f / 512.f);
        float inv = rsqrtf(msq - mu * mu + 1e-5f);
        float* nf = sO + r * H_SZ;
        const float* vres = sK + r * H_SZ;
        #pragma unroll
        for (int i = 0; i < 16; ++i) {
            int h = lane + 32 * i;
            nf[h] = vres[h] + __ldg(gamma + h) * (nf[h] - mu) * inv + __ldg(beta + h);
        }
    }
    __syncthreads();

    for (int i = tid; i < NODES * H_SZ / 2; i += 256) {
        int h2 = i & 255;
        int rn = i / 256;
        float2 a = *(float2*)(sO + rn * H_SZ + 2 * h2);
        float v0, v1;
        if (rn == 8) { v0 = a.x; v1 = a.y; }
        else {
            int src = (rn & 1) ? (rn >> 1) : (rn >> 1) + 4;
            float2 c = *(float2*)(sO + src * H_SZ + 2 * h2);
            v0 = 0.5f * (a.x + c.x);
            v1 = 0.5f * (a.y + c.y);
        }
        __half2 h, l;
        split2(v0, v1, h, l);
        ((__half2*)(mh + base))[i] = h;
        ((__half2*)(ml + base))[i] = l;
    }
}

// ============================================================================
// host orchestration
// ============================================================================
template<int EPI>
static void launch_hg(const __half* Ah, const __half* Al, const __half* Bh, const __half* Bl,
                      const float* bias, float* C, __half* Ch, __half* Cl,
                      int M, int N, int lda)
{
    cudaFuncSetAttribute(hgemm3<EPI>, cudaFuncAttributeMaxDynamicSharedMemorySize, HG_SMEM);
    dim3 grid(N / 128, M / 64);
    hgemm3<EPI><<<grid, 256, HG_SMEM>>>(Ah, Al, Bh, Bl, bias, C, Ch, Cl, N, lda);
}

struct Ptrs {
    __half *mh, *ml, *ah, *al, *nh, *nl, *xh, *xl, *wh, *wl;
    float *f;
};

// attention layer: ONE N=1024 GEMM (QK|VO) + fused elementwise -> m pair
static void run_attention(const Ptrs& P, int layer, const float* gamma, const float* beta)
{
    const size_t wb = OFF_ATT + (size_t)layer * 2 * 262144;   // 1024 rows x 512
    launch_hg<0>(P.ah, P.al, P.wh + wb, P.wl + wb, nullptr, P.f, nullptr, nullptr, ROWS, 1024, 512);
    cudaFuncSetAttribute(attn_fused, cudaFuncAttributeMaxDynamicSharedMemorySize, AF_SMEM);
    attn_fused<<<B_SZ, 256, AF_SMEM>>>(P.f, P.ah, P.al, gamma, beta, P.mh, P.ml);
}

extern "C" void kernel_launch(void* const* d_in, const int* in_sizes, int n_in,
                              void* d_out, int out_size)
{
    const float* x      = (const float*)d_in[0];
    const float* W_in   = (const float*)d_in[1];
    const float* b_in   = (const float*)d_in[2];
    const float* W_dr   = (const float*)d_in[3];
    const float* b_dr   = (const float*)d_in[4];
    const float* W_hyp  = (const float*)d_in[5];
    const float* b_hyp  = (const float*)d_in[6];
    const float* Wq_r   = (const float*)d_in[7];
    const float* Wq_i   = (const float*)d_in[8];
    const float* Wq_j   = (const float*)d_in[9];
    const float* Wq_k   = (const float*)d_in[10];
    const float* b_quat = (const float*)d_in[11];
    const float* W_low  = (const float*)d_in[12];
    const float* W_high = (const float*)d_in[13];
    const float* b_wav  = (const float*)d_in[14];
    const float* aWq    = (const float*)d_in[15];
    const float* aWk    = (const float*)d_in[16];
    const float* aWv    = (const float*)d_in[17];
    const float* aWo    = (const float*)d_in[18];
    const float* gamma  = (const float*)d_in[19];
    const float* beta   = (const float*)d_in[20];
    const float* W_out  = (const float*)d_in[21];
    const float* b_out  = (const float*)d_in[22];
    float* out = (float*)d_out;

    Ptrs P;
    cudaGetSymbolAddress((void**)&P.mh, g_mh); cudaGetSymbolAddress((void**)&P.ml, g_ml);
    cudaGetSymbolAddress((void**)&P.ah, g_ah); cudaGetSymbolAddress((void**)&P.al, g_al);
    cudaGetSymbolAddress((void**)&P.nh, g_nh); cudaGetSymbolAddress((void**)&P.nl, g_nl);
    cudaGetSymbolAddress((void**)&P.xh, g_xh); cudaGetSymbolAddress((void**)&P.xl, g_xl);
    cudaGetSymbolAddress((void**)&P.wh, g_wh); cudaGetSymbolAddress((void**)&P.wl, g_wl);
    cudaGetSymbolAddress((void**)&P.f,  g_f);

    // #0 prep (non-attn weights), #1 x split
    prep_weights<<<(WTS_TOTAL + 255) / 256, 256>>>(
        W_in, W_dr, W_hyp, Wq_r, Wq_i, Wq_j, Wq_k, W_low, W_high, W_out, P.wh, P.wl);
    split_copy<<<(B_SZ * H_SZ / 4 + 255) / 256, 256>>>((const float4*)x, P.xh, P.xl, B_SZ * H_SZ / 4);

    const int AGG_BLOCKS = (B_SZ * NODES * 256 + 255) / 256;

    // #2 W_in GEMM, #3 W_dr GEMM, #4 agg, #5 W_hyp GEMM (ncu captures a GEMM)
    launch_hg<1>(P.xh, P.xl, P.wh + OFF_WIN, P.wl + OFF_WIN, b_in, nullptr, P.mh, P.ml, B_SZ, 4608, 512);
    launch_hg<2>(P.mh, P.ml, P.wh + OFF_WDR, P.wl + OFF_WDR, b_dr, nullptr, P.nh, P.nl, ROWS, 512, 512);
    agg_hl<<<AGG_BLOCKS, 256>>>((const __half2*)P.nh, (const __half2*)P.nl, (__half2*)P.mh, (__half2*)P.ml);
    launch_hg<2>(P.mh, P.ml, P.wh + OFF_WHYP, P.wl + OFF_WHYP, b_hyp, nullptr, P.ah, P.al, ROWS, 512, 512);

    // combined attention weights
    combine_attn<<<dim3(32, 32, 6), dim3(16, 16)>>>(aWq, aWk, aWv, aWo, P.wh, P.wl);

    run_attention(P, 0, gamma, beta);
    launch_hg<2>(P.mh, P.ml, P.wh + OFF_QUAT, P.wl + OFF_QUAT, b_quat, nullptr, P.ah, P.al, ROWS, 512, 512);

    run_attention(P, 1, gamma + 512, beta + 512);
    launch_hg<2>(P.mh, P.ml, P.wh + OFF_WAV, P.wl + OFF_WAV, b_wav, nullptr, P.ah, P.al, ROWS, 512, 512);

    run_attention(P, 2, gamma + 1024, beta + 1024);

    // out = nf[:,8,:] @ W_out + b_out
    launch_hg<3>(P.mh + 8 * H_SZ, P.ml + 8 * H_SZ, P.wh + OFF_WOUT, P.wl + OFF_WOUT,
                 b_out, out, nullptr, nullptr, B_SZ, 128, NODES * H_SZ);
}

// round 12
// speedup vs baseline: 1.0018x; 1.0018x over previous
#include <cuda_runtime.h>
#include <cuda_fp16.h>
#include <math.h>
#include <stdint.h>

#define B_SZ   16384
#define H_SZ   512
#define NODES  9
#define ROWS   (B_SZ * NODES)         // 147456
#define BH     (ROWS * H_SZ)          // 75497472

// ---------------- scratch (device globals; no allocation) ----------------
__device__ __half g_mh[BH], g_ml[BH];
__device__ __half g_ah[BH], g_al[BH];
__device__ __half g_nh[BH], g_nl[BH];
__device__ __half g_xh[B_SZ * H_SZ], g_xl[B_SZ * H_SZ];
__device__ float  g_f[2ull * BH];     // QV combined output: ROWS x 1024

// weights [N,K] K-major, K=512, hi/lo half pairs
#define OFF_WIN   0                    // 4608*512
#define OFF_WDR   2359296
#define OFF_WHYP  2621440
#define OFF_QUAT  2883584
#define OFF_WAV   3145728
#define OFF_ATT   3407872              // per layer: {Bt_qk, Bt_vo} contiguous (1024x512)
#define OFF_WOUT  6553600              // 128*512
#define WTS_TOTAL 6619136
__device__ __half g_wh[WTS_TOTAL], g_wl[WTS_TOTAL];

// ============================================================================
// helpers
// ============================================================================
__device__ __forceinline__ uint32_t smem_u32(const void* p) {
    uint32_t a;
    asm("{ .reg .u64 t; cvta.to.shared.u64 t, %1; cvt.u32.u64 %0, t; }" : "=r"(a) : "l"(p));
    return a;
}
__device__ __forceinline__ void cp_async16(uint32_t dst, const void* src) {
    asm volatile("cp.async.cg.shared.global [%0], [%1], 16;" :: "r"(dst), "l"(src) : "memory");
}
__device__ __forceinline__ void cp_commit() {
    asm volatile("cp.async.commit_group;" ::: "memory");
}
__device__ __forceinline__ void cp_wait1() {
    asm volatile("cp.async.wait_group 1;" ::: "memory");
}
__device__ __forceinline__ void ldm_x4(uint32_t addr, uint32_t& r0, uint32_t& r1,
                                       uint32_t& r2, uint32_t& r3) {
    asm volatile("ldmatrix.sync.aligned.m8n8.x4.shared.b16 {%0,%1,%2,%3}, [%4];"
                 : "=r"(r0), "=r"(r1), "=r"(r2), "=r"(r3) : "r"(addr));
}
__device__ __forceinline__ void mma_f16(float* c, const uint32_t* a, const uint32_t* b) {
    asm volatile(
        "mma.sync.aligned.m16n8k16.row.col.f32.f16.f16.f32 "
        "{%0,%1,%2,%3}, {%4,%5,%6,%7}, {%8,%9}, {%0,%1,%2,%3};"
        : "+f"(c[0]), "+f"(c[1]), "+f"(c[2]), "+f"(c[3])
        : "r"(a[0]), "r"(a[1]), "r"(a[2]), "r"(a[3]), "r"(b[0]), "r"(b[1]));
}
__device__ __forceinline__ void split2(float d0, float d1, __half2& h, __half2& l) {
    __half h0 = __float2half_rn(d0), h1 = __float2half_rn(d1);
    h = __halves2half2(h0, h1);
    l = __floats2half2_rn(d0 - __half2float(h0), d1 - __half2float(h1));
}

// ============================================================================
// fp16x3 GEMM: C[M,N] = A[M,512] @ Bt[N,512]^T   (term-major MMA ordering)
// EPI: 0 fp32 C; 1 bias+lrelu -> HL; 2 bias+tanh -> HL; 3 bias -> fp32
// BM=64, BN=128, 256 thr, 8 warps (2x4), warp 32x32, 2-stage, 2 CTAs/SM
// ============================================================================
#define A_ST 8192
#define B_ST 16384
#define HG_SMEM (2 * (2 * A_ST + 2 * B_ST) + 1024)

template<int EPI>
__global__ __launch_bounds__(256, 2)
void hgemm3(const __half* __restrict__ Ah, const __half* __restrict__ Al,
            const __half* __restrict__ Bh, const __half* __restrict__ Bl,
            const float* __restrict__ bias, float* __restrict__ C,
            __half* __restrict__ Ch, __half* __restrict__ Cl,
            int N, int lda)
{
    extern __shared__ char smraw[];
    const uint32_t base = (smem_u32(smraw) + 1023) & ~1023u;
    const uint32_t sAh = base;
    const uint32_t sAl = base + 2 * A_ST;
    const uint32_t sBh = base + 4 * A_ST;
    const uint32_t sBl = base + 4 * A_ST + 2 * B_ST;

    const int col0 = blockIdx.x * 128;
    const int row0 = blockIdx.y * 64;

    const int tid    = threadIdx.x;
    const int lane   = tid & 31;
    const int wid    = tid >> 5;
    const int warp_m = wid >> 2;
    const int warp_n = wid & 3;

    const int lm = tid >> 3;
    const int lq = tid & 7;

    const int mat = lane >> 3;
    const int mr  = lane & 7;
    int rbA[2], s7A[2];
    #pragma unroll
    for (int mf = 0; mf < 2; ++mf) {
        int m = warp_m * 32 + mf * 16 + (mat & 1) * 8 + mr;
        rbA[mf] = m * 128; s7A[mf] = m & 7;
    }
    const int qaA = mat >> 1;
    int rbB[2], s7B[2];
    #pragma unroll
    for (int p = 0; p < 2; ++p) {
        int n = warp_n * 32 + (2 * p + (mat >> 1)) * 8 + mr;
        rbB[p] = n * 128; s7B[p] = n & 7;
    }
    const int qaB = mat & 1;

    float acc[2][4][4];
    #pragma unroll
    for (int i = 0; i < 2; ++i)
        #pragma unroll
        for (int j = 0; j < 4; ++j)
            #pragma unroll
            for (int k = 0; k < 4; ++k) acc[i][j][k] = 0.f;

    #pragma unroll
    for (int st = 0; st < 2; ++st) {
        #pragma unroll
        for (int i = 0; i < 2; ++i) {
            const int row = lm + i * 32;
            const uint32_t d = st * A_ST + row * 128 + (((lq ^ (row & 7)) << 4));
            const size_t oa = (size_t)(row0 + row) * lda + st * 64 + lq * 8;
            cp_async16(sAh + d, Ah + oa);
            cp_async16(sAl + d, Al + oa);
        }
        #pragma unroll
        for (int i = 0; i < 4; ++i) {
            const int row = lm + i * 32;
            const uint32_t d = st * B_ST + row * 128 + (((lq ^ (row & 7)) << 4));
            const size_t ob = (size_t)(col0 + row) * 512 + st * 64 + lq * 8;
            cp_async16(sBh + d, Bh + ob);
            cp_async16(sBl + d, Bl + ob);
        }
        cp_commit();
    }

    #pragma unroll 1
    for (int t = 0; t < 8; ++t) {
        cp_wait1();
        __syncthreads();

        const uint32_t pAh = sAh + (t & 1) * A_ST;
        const uint32_t pAl = sAl + (t & 1) * A_ST;
        const uint32_t pBh = sBh + (t & 1) * B_ST;
        const uint32_t pBl = sBl + (t & 1) * B_ST;

        #pragma unroll
        for (int ks = 0; ks < 4; ++ks) {
            uint32_t ah[2][4], al[2][4];
            #pragma unroll
            for (int mf = 0; mf < 2; ++mf) {
                const uint32_t off = rbA[mf] + (((2 * ks + qaA) ^ s7A[mf]) << 4);
                ldm_x4(pAh + off, ah[mf][0], ah[mf][1], ah[mf][2], ah[mf][3]);
                ldm_x4(pAl + off, al[mf][0], al[mf][1], al[mf][2], al[mf][3]);
            }
            #pragma unroll
            for (int p = 0; p < 2; ++p) {
                uint32_t bh[2][2], bl[2][2];
                const uint32_t off = rbB[p] + (((2 * ks + qaB) ^ s7B[p]) << 4);
                ldm_x4(pBh + off, bh[0][0], bh[0][1], bh[1][0], bh[1][1]);
                ldm_x4(pBl + off, bl[0][0], bl[0][1], bl[1][0], bl[1][1]);
                // term-major: 4 independent accs between same-acc reuse
                #pragma unroll
                for (int mf = 0; mf < 2; ++mf)
                    #pragma unroll
                    for (int q = 0; q < 2; ++q)
                        mma_f16(acc[mf][2 * p + q], ah[mf], bh[q]);
                #pragma unroll
                for (int mf = 0; mf < 2; ++mf)
                    #pragma unroll
                    for (int q = 0; q < 2; ++q)
                        mma_f16(acc[mf][2 * p + q], ah[mf], bl[q]);
                #pragma unroll
                for (int mf = 0; mf < 2; ++mf)
                    #pragma unroll
                    for (int q = 0; q < 2; ++q)
                        mma_f16(acc[mf][2 * p + q], al[mf], bh[q]);
            }
        }
        __syncthreads();
        if (t + 2 < 8) {
            const int st = t & 1;
            #pragma unroll
            for (int i = 0; i < 2; ++i) {
                const int row = lm + i * 32;
                const uint32_t d = st * A_ST + row * 128 + (((lq ^ (row & 7)) << 4));
                const size_t oa = (size_t)(row0 + row) * lda + (t + 2) * 64 + lq * 8;
                cp_async16(sAh + d, Ah + oa);
                cp_async16(sAl + d, Al + oa);
            }
            #pragma unroll
            for (int i = 0; i < 4; ++i) {
                const int row = lm + i * 32;
                const uint32_t d = st * B_ST + row * 128 + (((lq ^ (row & 7)) << 4));
                const size_t ob = (size_t)(col0 + row) * 512 + (t + 2) * 64 + lq * 8;
                cp_async16(sBh + d, Bh + ob);
                cp_async16(sBl + d, Bl + ob);
            }
        }
        cp_commit();
    }

    const int g  = lane >> 2;
    const int t4 = lane & 3;
    #pragma unroll
    for (int mf = 0; mf < 2; ++mf) {
        #pragma unroll
        for (int nf = 0; nf < 4; ++nf) {
            const int r1 = row0 + warp_m * 32 + mf * 16 + g;
            const int cc = col0 + warp_n * 32 + nf * 8 + t4 * 2;
            float d[4] = {acc[mf][nf][0], acc[mf][nf][1], acc[mf][nf][2], acc[mf][nf][3]};
            if (EPI != 0) {
                float b0 = __ldg(bias + cc), b1 = __ldg(bias + cc + 1);
                d[0] += b0; d[1] += b1; d[2] += b0; d[3] += b1;
                #pragma unroll
                for (int i = 0; i < 4; ++i) {
                    if (EPI == 1)      d[i] = d[i] > 0.f ? d[i] : 0.01f * d[i];
                    else if (EPI == 2) d[i] = tanhf(d[i]);
                }
            }
            if (EPI == 0 || EPI == 3) {
                *(float2*)(C + (size_t)r1 * N + cc)       = make_float2(d[0], d[1]);
                *(float2*)(C + (size_t)(r1 + 8) * N + cc) = make_float2(d[2], d[3]);
            } else {
                __half2 h, l;
                split2(d[0], d[1], h, l);
                *(__half2*)(Ch + (size_t)r1 * N + cc) = h;
                *(__half2*)(Cl + (size_t)r1 * N + cc) = l;
                split2(d[2], d[3], h, l);
                *(__half2*)(Ch + (size_t)(r1 + 8) * N + cc) = h;
                *(__half2*)(Cl + (size_t)(r1 + 8) * N + cc) = l;
            }
        }
    }
}

// ============================================================================
// weight prep (non-attention weights)
// ============================================================================
__constant__ int   c_which[16] = {0,1,2,3, 1,0,3,2, 2,3,0,1, 3,2,1,0};
__constant__ float c_sign [16] = {1.f,-1.f,-1.f,-1.f,
                                  1.f, 1.f, 1.f,-1.f,
                                  1.f,-1.f, 1.f, 1.f,
                                  1.f, 1.f,-1.f, 1.f};

__global__ void prep_weights(
    const float* __restrict__ W_in,  const float* __restrict__ W_dr,
    const float* __restrict__ W_hyp, const float* __restrict__ Wq_r,
    const float* __restrict__ Wq_i,  const float* __restrict__ Wq_j,
    const float* __restrict__ Wq_k,  const float* __restrict__ W_low,
    const float* __restrict__ W_high,const float* __restrict__ W_out,
    __half* __restrict__ oh, __half* __restrict__ ol)
{
    int idx = blockIdx.x * 256 + threadIdx.x;
    if (idx >= WTS_TOTAL) return;
    if (idx >= OFF_ATT && idx < OFF_WOUT) return;   // filled by combine_attn
    float v;
    if (idx < OFF_WDR) {
        int n = idx >> 9, k = idx & 511;
        v = W_in[(size_t)k * 4608 + n];
    } else if (idx < OFF_WHYP) {
        int r = idx - OFF_WDR, n = r >> 9, k = r & 511;
        v = W_dr[(size_t)k * 512 + n];
    } else if (idx < OFF_QUAT) {
        int r = idx - OFF_WHYP, n = r >> 9, k = r & 511;
        v = W_hyp[(size_t)k * 512 + n];
    } else if (idx < OFF_WAV) {
        int r = idx - OFF_QUAT, n = r >> 9, k = r & 511;
        int co = n >> 7, ho = n & 127, ci = k >> 7, hi = k & 127;
        const float* mats[4] = {Wq_r, Wq_i, Wq_j, Wq_k};
        int sel = co * 4 + ci;
        v = c_sign[sel] * mats[c_which[sel]][hi * 128 + ho];
    } else if (idx < OFF_ATT) {
        int r = idx - OFF_WAV, n = r >> 9, k = r & 511;
        int ho = n >> 1, po = n & 1, hi = k >> 1, pi = k & 1;
        float wl = W_low[hi * 256 + ho], wh = W_high[hi * 256 + ho];
        v = (pi == po) ? 0.5f * (wl + wh) : 0.5f * (wl - wh);
    } else {
        int r = idx - OFF_WOUT, n = r >> 9, k = r & 511;
        v = W_out[(size_t)k * 128 + n];
    }
    __half h = __float2half_rn(v);
    oh[idx] = h;
    ol[idx] = __float2half_rn(v - __half2float(h));
}

// combined attention weights (layer block = [Mqk(512) ; Mvo(512)] rows, K=512)
__global__ void combine_attn(const float* __restrict__ aWq, const float* __restrict__ aWk,
                             const float* __restrict__ aWv, const float* __restrict__ aWo,
                             __half* __restrict__ oh, __half* __restrict__ ol)
{
    __shared__ float As[16][17], Bs[16][17];
    const int z = blockIdx.z, l = z >> 1, type = z & 1;
    const int tx = threadIdx.x, ty = threadIdx.y;
    const size_t wl_off = (size_t)l * 262144;
    const float* Wq = aWq + wl_off;
    const float* Wk = aWk + wl_off;
    const float* Wv = aWv + wl_off;
    const float* Wo = aWo + wl_off;

    float acc = 0.f;
    for (int m0 = 0; m0 < 512; m0 += 16) {
        if (type == 0) {
            As[ty][tx] = Wk[(size_t)(blockIdx.y * 16 + ty) * 512 + m0 + tx];
            Bs[ty][tx] = Wq[(size_t)(blockIdx.x * 16 + ty) * 512 + m0 + tx];
        } else {
            As[ty][tx] = Wo[(size_t)(m0 + ty) * 512 + blockIdx.y * 16 + tx];
            Bs[ty][tx] = Wv[(size_t)(blockIdx.x * 16 + ty) * 512 + m0 + tx];
        }
        __syncthreads();
        if (type == 0) {
            #pragma unroll
            for (int h = 0; h < 16; ++h) acc += As[ty][h] * Bs[tx][h];
        } else {
            #pragma unroll
            for (int m = 0; m < 16; ++m) acc += Bs[tx][m] * As[m][ty];
        }
        __syncthreads();
    }
    const int n = blockIdx.y * 16 + ty;
    const int k = blockIdx.x * 16 + tx;
    const size_t o = (size_t)OFF_ATT + (size_t)z * 262144 + (size_t)n * 512 + k;
    __half h = __float2half_rn(acc);
    oh[o] = h;
    ol[o] = __float2half_rn(acc - __half2float(h));
}

__global__ void split_copy(const float4* __restrict__ in, __half* __restrict__ H,
                           __half* __restrict__ L, int n4)
{
    int i = blockIdx.x * 256 + threadIdx.x;
    if (i >= n4) return;
    float4 v = in[i];
    __half2 h, l;
    split2(v.x, v.y, h, l);
    ((__half2*)H)[2*i]   = h; ((__half2*)L)[2*i]   = l;
    split2(v.z, v.w, h, l);
    ((__half2*)H)[2*i+1] = h; ((__half2*)L)[2*i+1] = l;
}

// ============================================================================
// standalone agg (used once, after W_dr)
// ============================================================================
__global__ void agg_hl(const __half2* __restrict__ ih, const __half2* __restrict__ il,
                       __half2* __restrict__ oh, __half2* __restrict__ ol)
{
    int idx = blockIdx.x * 256 + threadIdx.x;
    const int TOT = B_SZ * NODES * 256;
    if (idx >= TOT) return;
    int h2 = idx & 255;
    int rn = (idx >> 8) % NODES;
    int b  = idx / (NODES * 256);
    size_t p = (size_t)(b * NODES + rn) * 256 + h2;
    __half2 xh = ih[p], xl = il[p];
    if (rn == 8) { oh[idx] = xh; ol[idx] = xl; return; }
    int src = (rn & 1) ? (rn >> 1) : (rn >> 1) + 4;
    size_t q = (size_t)(b * NODES + src) * 256 + h2;
    float2 fa = __half22float2(xh), fal = __half22float2(xl);
    float2 fc = __half22float2(ih[q]), fcl = __half22float2(il[q]);
    float v0 = 0.5f * ((fa.x + fal.x) + (fc.x + fcl.x));
    float v1 = 0.5f * ((fa.y + fal.y) + (fc.y + fcl.y));
    __half2 h, l;
    split2(v0, v1, h, l);
    oh[idx] = h; ol[idx] = l;
}

// ============================================================================
// fused attention + drnorm + residual + agg; QV is ROWS x 1024 (Q | V)
// ============================================================================
#define AF_SMEM (3 * NODES * H_SZ * 4 + 512)

__global__ __launch_bounds__(256)
void attn_fused(const float* __restrict__ QV,
                const __half* __restrict__ vh, const __half* __restrict__ vl,
                const float* __restrict__ gamma, const float* __restrict__ beta,
                __half* __restrict__ mh, __half* __restrict__ ml)
{
    extern __shared__ float sm[];
    float* sK = sm;                        // v (fp32)          9*512
    float* sV = sm + NODES * H_SZ;         // V                 9*512
    float* sO = sm + 2 * NODES * H_SZ;     // ctx -> nf         9*512
    float* sS = sm + 3 * NODES * H_SZ;     // scores            96

    const int b   = blockIdx.x;
    const int tid = threadIdx.x;
    const size_t base   = (size_t)b * NODES * H_SZ;          // hl-pair layout
    const size_t baseQV = (size_t)b * NODES * 1024;          // QV layout

    const __half2* K2h = (const __half2*)(vh + base);
    const __half2* K2l = (const __half2*)(vl + base);
    for (int i = tid; i < NODES * H_SZ / 2; i += 256) {
        float2 h = __half22float2(K2h[i]);
        float2 l = __half22float2(K2l[i]);
        sK[2*i]   = h.x + l.x;
        sK[2*i+1] = h.y + l.y;
    }
    for (int i = tid; i < NODES * H_SZ / 4; i += 256) {
        int rn = i >> 7, c4 = i & 127;                       // 128 float4 per row
        ((float4*)sV)[i] = *(const float4*)(QV + baseQV + (size_t)rn * 1024 + 512 + c4 * 4);
    }
    __syncthreads();

    const float scale = 0.044194173824159216f;   // 1/sqrt(512)
    const int warp = tid >> 5, lane = tid & 31;
    for (int p = warp; p < 81; p += 8) {
        int q = p / 9, kk = p % 9;
        const float* Qr = QV + baseQV + (size_t)q * 1024;
        float s = 0.f;
        #pragma unroll 4
        for (int h = lane; h < H_SZ; h += 32) s += Qr[h] * sK[kk * H_SZ + h];
        #pragma unroll
        for (int o = 16; o; o >>= 1) s += __shfl_down_sync(0xffffffffu, s, o);
        if (lane == 0) sS[q * 9 + kk] = s * scale;
    }
    __syncthreads();

    if (tid < 9) {
        float mx = -1e30f;
        #pragma unroll
        for (int k = 0; k < 9; ++k) mx = fmaxf(mx, sS[tid * 9 + k]);
        float sum = 0.f;
        #pragma unroll
        for (int k = 0; k < 9; ++k) { float e = expf(sS[tid * 9 + k] - mx); sS[tid * 9 + k] = e; sum += e; }
        float inv = 1.f / sum;
        #pragma unroll
        for (int k = 0; k < 9; ++k) sS[tid * 9 + k] *= inv;
    }
    __syncthreads();

    for (int q = 0; q < 9; ++q) {
        float a[9];
        #pragma unroll
        for (int k = 0; k < 9; ++k) a[k] = sS[q * 9 + k];
        for (int h = tid * 2; h < H_SZ; h += 512) {
            float a0 = 0.f, a1 = 0.f;
            #pragma unroll
            for (int k = 0; k < 9; ++k) {
                a0 = fmaf(a[k], sV[k * H_SZ + h],     a0);
                a1 = fmaf(a[k], sV[k * H_SZ + h + 1], a1);
            }
            sO[q * H_SZ + h]     = a0;
            sO[q * H_SZ + h + 1] = a1;
        }
    }
    __syncthreads();

    for (int r = warp; r < 9; r += 8) {
        const float* o = sO + r * H_SZ;
        float s = 0.f, sq = 0.f;
        #pragma unroll
        for (int i = 0; i < 16; ++i) {
            float v = o[lane + 32 * i];
            s += v; sq += v * v;
        }
        #pragma unroll
        for (int off = 16; off; off >>= 1) {
            s  += __shfl_down_sync(0xffffffffu, s, off);
            sq += __shfl_down_sync(0xffffffffu, sq, off);
        }
        float mu  = __shfl_sync(0xffffffffu, s,  0) * (1.f / 512.f);
        float msq = __shfl_sync(0xffffffffu, sq, 0) * (1.f / 512.f);
        float inv = rsqrtf(msq - mu * mu + 1e-5f);
        float* nf = sO + r * H_SZ;
        const float* vres = sK + r * H_SZ;
        #pragma unroll
        for (int i = 0; i < 16; ++i) {
            int h = lane + 32 * i;
            nf[h] = vres[h] + __ldg(gamma + h) * (nf[h] - mu) * inv + __ldg(beta + h);
        }
    }
    __syncthreads();

    for (int i = tid; i < NODES * H_SZ / 2; i += 256) {
        int h2 = i & 255;
        int rn = i / 256;
        float2 a = *(float2*)(sO + rn * H_SZ + 2 * h2);
        float v0, v1;
        if (rn == 8) { v0 = a.x; v1 = a.y; }
        else {
            int src = (rn & 1) ? (rn >> 1) : (rn >> 1) + 4;
            float2 c = *(float2*)(sO + src * H_SZ + 2 * h2);
            v0 = 0.5f * (a.x + c.x);
            v1 = 0.5f * (a.y + c.y);
        }
        __half2 h, l;
        split2(v0, v1, h, l);
        ((__half2*)(mh + base))[i] = h;
        ((__half2*)(ml + base))[i] = l;
    }
}

// ============================================================================
// host orchestration
// ============================================================================
template<int EPI>
static void launch_hg(const __half* Ah, const __half* Al, const __half* Bh, const __half* Bl,
                      const float* bias, float* C, __half* Ch, __half* Cl,
                      int M, int N, int lda)
{
    cudaFuncSetAttribute(hgemm3<EPI>, cudaFuncAttributeMaxDynamicSharedMemorySize, HG_SMEM);
    dim3 grid(N / 128, M / 64);
    hgemm3<EPI><<<grid, 256, HG_SMEM>>>(Ah, Al, Bh, Bl, bias, C, Ch, Cl, N, lda);
}

struct Ptrs {
    __half *mh, *ml, *ah, *al, *nh, *nl, *xh, *xl, *wh, *wl;
    float *f;
};

// attention layer: ONE N=1024 GEMM (QK|VO) + fused elementwise -> m pair
static void run_attention(const Ptrs& P, int layer, const float* gamma, const float* beta)
{
    const size_t wb = OFF_ATT + (size_t)layer * 2 * 262144;   // 1024 rows x 512
    launch_hg<0>(P.ah, P.al, P.wh + wb, P.wl + wb, nullptr, P.f, nullptr, nullptr, ROWS, 1024, 512);
    cudaFuncSetAttribute(attn_fused, cudaFuncAttributeMaxDynamicSharedMemorySize, AF_SMEM);
    attn_fused<<<B_SZ, 256, AF_SMEM>>>(P.f, P.ah, P.al, gamma, beta, P.mh, P.ml);
}

extern "C" void kernel_launch(void* const* d_in, const int* in_sizes, int n_in,
                              void* d_out, int out_size)
{
    const float* x      = (const float*)d_in[0];
    const float* W_in   = (const float*)d_in[1];
    const float* b_in   = (const float*)d_in[2];
    const float* W_dr   = (const float*)d_in[3];
    const float* b_dr   = (const float*)d_in[4];
    const float* W_hyp  = (const float*)d_in[5];
    const float* b_hyp  = (const float*)d_in[6];
    const float* Wq_r   = (const float*)d_in[7];
    const float* Wq_i   = (const float*)d_in[8];
    const float* Wq_j   = (const float*)d_in[9];
    const float* Wq_k   = (const float*)d_in[10];
    const float* b_quat = (const float*)d_in[11];
    const float* W_low  = (const float*)d_in[12];
    const float* W_high = (const float*)d_in[13];
    const float* b_wav  = (const float*)d_in[14];
    const float* aWq    = (const float*)d_in[15];
    const float* aWk    = (const float*)d_in[16];
    const float* aWv    = (const float*)d_in[17];
    const float* aWo    = (const float*)d_in[18];
    const float* gamma  = (const float*)d_in[19];
    const float* beta   = (const float*)d_in[20];
    const float* W_out  = (const float*)d_in[21];
    const float* b_out  = (const float*)d_in[22];
    float* out = (float*)d_out;

    Ptrs P;
    cudaGetSymbolAddress((void**)&P.mh, g_mh); cudaGetSymbolAddress((void**)&P.ml, g_ml);
    cudaGetSymbolAddress((void**)&P.ah, g_ah); cudaGetSymbolAddress((void**)&P.al, g_al);
    cudaGetSymbolAddress((void**)&P.nh, g_nh); cudaGetSymbolAddress((void**)&P.nl, g_nl);
    cudaGetSymbolAddress((void**)&P.xh, g_xh); cudaGetSymbolAddress((void**)&P.xl, g_xl);
    cudaGetSymbolAddress((void**)&P.wh, g_wh); cudaGetSymbolAddress((void**)&P.wl, g_wl);
    cudaGetSymbolAddress((void**)&P.f,  g_f);

    // #0 prep (non-attn weights), #1 x split
    prep_weights<<<(WTS_TOTAL + 255) / 256, 256>>>(
        W_in, W_dr, W_hyp, Wq_r, Wq_i, Wq_j, Wq_k, W_low, W_high, W_out, P.wh, P.wl);
    split_copy<<<(B_SZ * H_SZ / 4 + 255) / 256, 256>>>((const float4*)x, P.xh, P.xl, B_SZ * H_SZ / 4);

    const int AGG_BLOCKS = (B_SZ * NODES * 256 + 255) / 256;

    // #2 W_in GEMM, #3 W_dr GEMM, #4 agg, #5 W_hyp GEMM (ncu captures a GEMM)
    launch_hg<1>(P.xh, P.xl, P.wh + OFF_WIN, P.wl + OFF_WIN, b_in, nullptr, P.mh, P.ml, B_SZ, 4608, 512);
    launch_hg<2>(P.mh, P.ml, P.wh + OFF_WDR, P.wl + OFF_WDR, b_dr, nullptr, P.nh, P.nl, ROWS, 512, 512);
    agg_hl<<<AGG_BLOCKS, 256>>>((const __half2*)P.nh, (const __half2*)P.nl, (__half2*)P.mh, (__half2*)P.ml);
    launch_hg<2>(P.mh, P.ml, P.wh + OFF_WHYP, P.wl + OFF_WHYP, b_hyp, nullptr, P.ah, P.al, ROWS, 512, 512);

    // combined attention weights
    combine_attn<<<dim3(32, 32, 6), dim3(16, 16)>>>(aWq, aWk, aWv, aWo, P.wh, P.wl);

    run_attention(P, 0, gamma, beta);
    launch_hg<2>(P.mh, P.ml, P.wh + OFF_QUAT, P.wl + OFF_QUAT, b_quat, nullptr, P.ah, P.al, ROWS, 512, 512);

    run_attention(P, 1, gamma + 512, beta + 512);
    launch_hg<2>(P.mh, P.ml, P.wh + OFF_WAV, P.wl + OFF_WAV, b_wav, nullptr, P.ah, P.al, ROWS, 512, 512);

    run_attention(P, 2, gamma + 1024, beta + 1024);

    // out = nf[:,8,:] @ W_out + b_out
    launch_hg<3>(P.mh + 8 * H_SZ, P.ml + 8 * H_SZ, P.wh + OFF_WOUT, P.wl + OFF_WOUT,
                 b_out, out, nullptr, nullptr, B_SZ, 128, NODES * H_SZ);
}

// round 13
// speedup vs baseline: 1.1499x; 1.1478x over previous
#include <cuda_runtime.h>
#include <cuda_fp16.h>
#include <math.h>
#include <stdint.h>

#define B_SZ   16384
#define H_SZ   512
#define NODES  9
#define ROWS   (B_SZ * NODES)         // 147456
#define BH     (ROWS * H_SZ)          // 75497472

// ---------------- scratch (device globals; no allocation) ----------------
__device__ __half g_mh[BH], g_ml[BH];
__device__ __half g_ah[BH], g_al[BH];
__device__ __half g_nh[BH], g_nl[BH];
__device__ __half g_xh[B_SZ * H_SZ], g_xl[B_SZ * H_SZ];
__device__ float  g_f[2ull * BH];     // QV combined output: ROWS x 1024

// weights [N,K] K-major, K=512, hi/lo half pairs
#define OFF_WIN   0                    // 4608*512
#define OFF_WDR   2359296
#define OFF_WHYP  2621440
#define OFF_QUAT  2883584
#define OFF_WAV   3145728
#define OFF_ATT   3407872              // per layer: {Bt_qk, Bt_vo} contiguous (1024x512)
#define OFF_WOUT  6553600              // 128*512
#define WTS_TOTAL 6619136
__device__ __half g_wh[WTS_TOTAL], g_wl[WTS_TOTAL];

// ============================================================================
// helpers
// ============================================================================
__device__ __forceinline__ uint32_t smem_u32(const void* p) {
    uint32_t a;
    asm("{ .reg .u64 t; cvta.to.shared.u64 t, %1; cvt.u32.u64 %0, t; }" : "=r"(a) : "l"(p));
    return a;
}
__device__ __forceinline__ void cp_async16(uint32_t dst, const void* src) {
    asm volatile("cp.async.cg.shared.global [%0], [%1], 16;" :: "r"(dst), "l"(src) : "memory");
}
__device__ __forceinline__ void cp_commit() {
    asm volatile("cp.async.commit_group;" ::: "memory");
}
__device__ __forceinline__ void cp_wait1() {
    asm volatile("cp.async.wait_group 1;" ::: "memory");
}
__device__ __forceinline__ void ldm_x4(uint32_t addr, uint32_t& r0, uint32_t& r1,
                                       uint32_t& r2, uint32_t& r3) {
    asm volatile("ldmatrix.sync.aligned.m8n8.x4.shared.b16 {%0,%1,%2,%3}, [%4];"
                 : "=r"(r0), "=r"(r1), "=r"(r2), "=r"(r3) : "r"(addr));
}
__device__ __forceinline__ void mma_f16(float* c, const uint32_t* a, const uint32_t* b) {
    asm volatile(
        "mma.sync.aligned.m16n8k16.row.col.f32.f16.f16.f32 "
        "{%0,%1,%2,%3}, {%4,%5,%6,%7}, {%8,%9}, {%0,%1,%2,%3};"
        : "+f"(c[0]), "+f"(c[1]), "+f"(c[2]), "+f"(c[3])
        : "r"(a[0]), "r"(a[1]), "r"(a[2]), "r"(a[3]), "r"(b[0]), "r"(b[1]));
}
__device__ __forceinline__ void split2(float d0, float d1, __half2& h, __half2& l) {
    __half h0 = __float2half_rn(d0), h1 = __float2half_rn(d1);
    h = __halves2half2(h0, h1);
    l = __floats2half2_rn(d0 - __half2float(h0), d1 - __half2float(h1));
}

// ============================================================================
// fp16x3 GEMM: C[M,N] = A[M,512] @ Bt[N,512]^T
// EPI: 0 fp32 C; 1 bias+lrelu -> HL; 2 bias+tanh -> HL; 3 bias -> fp32
// BM=64, BN=128, 256 thr, 8 warps (2x4), warp 32x32, 2-stage, 2 CTAs/SM
// ============================================================================
#define A_ST 8192
#define B_ST 16384
#define HG_SMEM (2 * (2 * A_ST + 2 * B_ST) + 1024)

template<int EPI>
__global__ __launch_bounds__(256, 2)
void hgemm3(const __half* __restrict__ Ah, const __half* __restrict__ Al,
            const __half* __restrict__ Bh, const __half* __restrict__ Bl,
            const float* __restrict__ bias, float* __restrict__ C,
            __half* __restrict__ Ch, __half* __restrict__ Cl,
            int N, int lda)
{
    extern __shared__ char smraw[];
    const uint32_t base = (smem_u32(smraw) + 1023) & ~1023u;
    const uint32_t sAh = base;
    const uint32_t sAl = base + 2 * A_ST;
    const uint32_t sBh = base + 4 * A_ST;
    const uint32_t sBl = base + 4 * A_ST + 2 * B_ST;

    const int col0 = blockIdx.x * 128;
    const int row0 = blockIdx.y * 64;

    const int tid    = threadIdx.x;
    const int lane   = tid & 31;
    const int wid    = tid >> 5;
    const int warp_m = wid >> 2;
    const int warp_n = wid & 3;

    const int lm = tid >> 3;
    const int lq = tid & 7;

    const int mat = lane >> 3;
    const int mr  = lane & 7;
    int rbA[2], s7A[2];
    #pragma unroll
    for (int mf = 0; mf < 2; ++mf) {
        int m = warp_m * 32 + mf * 16 + (mat & 1) * 8 + mr;
        rbA[mf] = m * 128; s7A[mf] = m & 7;
    }
    const int qaA = mat >> 1;
    int rbB[2], s7B[2];
    #pragma unroll
    for (int p = 0; p < 2; ++p) {
        int n = warp_n * 32 + (2 * p + (mat >> 1)) * 8 + mr;
        rbB[p] = n * 128; s7B[p] = n & 7;
    }
    const int qaB = mat & 1;

    float acc[2][4][4];
    #pragma unroll
    for (int i = 0; i < 2; ++i)
        #pragma unroll
        for (int j = 0; j < 4; ++j)
            #pragma unroll
            for (int k = 0; k < 4; ++k) acc[i][j][k] = 0.f;

    #pragma unroll
    for (int st = 0; st < 2; ++st) {
        #pragma unroll
        for (int i = 0; i < 2; ++i) {
            const int row = lm + i * 32;
            const uint32_t d = st * A_ST + row * 128 + (((lq ^ (row & 7)) << 4));
            const size_t oa = (size_t)(row0 + row) * lda + st * 64 + lq * 8;
            cp_async16(sAh + d, Ah + oa);
            cp_async16(sAl + d, Al + oa);
        }
        #pragma unroll
        for (int i = 0; i < 4; ++i) {
            const int row = lm + i * 32;
            const uint32_t d = st * B_ST + row * 128 + (((lq ^ (row & 7)) << 4));
            const size_t ob = (size_t)(col0 + row) * 512 + st * 64 + lq * 8;
            cp_async16(sBh + d, Bh + ob);
            cp_async16(sBl + d, Bl + ob);
        }
        cp_commit();
    }

    #pragma unroll 1
    for (int t = 0; t < 8; ++t) {
        cp_wait1();
        __syncthreads();

        const uint32_t pAh = sAh + (t & 1) * A_ST;
        const uint32_t pAl = sAl + (t & 1) * A_ST;
        const uint32_t pBh = sBh + (t & 1) * B_ST;
        const uint32_t pBl = sBl + (t & 1) * B_ST;

        #pragma unroll
        for (int ks = 0; ks < 4; ++ks) {
            uint32_t ah[2][4], al[2][4];
            #pragma unroll
            for (int mf = 0; mf < 2; ++mf) {
                const uint32_t off = rbA[mf] + (((2 * ks + qaA) ^ s7A[mf]) << 4);
                ldm_x4(pAh + off, ah[mf][0], ah[mf][1], ah[mf][2], ah[mf][3]);
                ldm_x4(pAl + off, al[mf][0], al[mf][1], al[mf][2], al[mf][3]);
            }
            #pragma unroll
            for (int p = 0; p < 2; ++p) {
                uint32_t bh[2][2], bl[2][2];
                const uint32_t off = rbB[p] + (((2 * ks + qaB) ^ s7B[p]) << 4);
                ldm_x4(pBh + off, bh[0][0], bh[0][1], bh[1][0], bh[1][1]);
                ldm_x4(pBl + off, bl[0][0], bl[0][1], bl[1][0], bl[1][1]);
                #pragma unroll
                for (int mf = 0; mf < 2; ++mf)
                    #pragma unroll
                    for (int q = 0; q < 2; ++q) {
                        float* a_ = acc[mf][2 * p + q];
                        mma_f16(a_, ah[mf], bh[q]);
                        mma_f16(a_, ah[mf], bl[q]);
                        mma_f16(a_, al[mf], bh[q]);
                    }
            }
        }
        __syncthreads();
        if (t + 2 < 8) {
            const int st = t & 1;
            #pragma unroll
            for (int i = 0; i < 2; ++i) {
                const int row = lm + i * 32;
                const uint32_t d = st * A_ST + row * 128 + (((lq ^ (row & 7)) << 4));
                const size_t oa = (size_t)(row0 + row) * lda + (t + 2) * 64 + lq * 8;
                cp_async16(sAh + d, Ah + oa);
                cp_async16(sAl + d, Al + oa);
            }
            #pragma unroll
            for (int i = 0; i < 4; ++i) {
                const int row = lm + i * 32;
                const uint32_t d = st * B_ST + row * 128 + (((lq ^ (row & 7)) << 4));
                const size_t ob = (size_t)(col0 + row) * 512 + (t + 2) * 64 + lq * 8;
                cp_async16(sBh + d, Bh + ob);
                cp_async16(sBl + d, Bl + ob);
            }
        }
        cp_commit();
    }

    const int g  = lane >> 2;
    const int t4 = lane & 3;
    #pragma unroll
    for (int mf = 0; mf < 2; ++mf) {
        #pragma unroll
        for (int nf = 0; nf < 4; ++nf) {
            const int r1 = row0 + warp_m * 32 + mf * 16 + g;
            const int cc = col0 + warp_n * 32 + nf * 8 + t4 * 2;
            float d[4] = {acc[mf][nf][0], acc[mf][nf][1], acc[mf][nf][2], acc[mf][nf][3]};
            if (EPI != 0) {
                float b0 = __ldg(bias + cc), b1 = __ldg(bias + cc + 1);
                d[0] += b0; d[1] += b1; d[2] += b0; d[3] += b1;
                #pragma unroll
                for (int i = 0; i < 4; ++i) {
                    if (EPI == 1)      d[i] = d[i] > 0.f ? d[i] : 0.01f * d[i];
                    else if (EPI == 2) d[i] = tanhf(d[i]);
                }
            }
            if (EPI == 0 || EPI == 3) {
                *(float2*)(C + (size_t)r1 * N + cc)       = make_float2(d[0], d[1]);
                *(float2*)(C + (size_t)(r1 + 8) * N + cc) = make_float2(d[2], d[3]);
            } else {
                __half2 h, l;
                split2(d[0], d[1], h, l);
                *(__half2*)(Ch + (size_t)r1 * N + cc) = h;
                *(__half2*)(Cl + (size_t)r1 * N + cc) = l;
                split2(d[2], d[3], h, l);
                *(__half2*)(Ch + (size_t)(r1 + 8) * N + cc) = h;
                *(__half2*)(Cl + (size_t)(r1 + 8) * N + cc) = l;
            }
        }
    }
}

// ============================================================================
// weight prep (non-attention weights)
// ============================================================================
__constant__ int   c_which[16] = {0,1,2,3, 1,0,3,2, 2,3,0,1, 3,2,1,0};
__constant__ float c_sign [16] = {1.f,-1.f,-1.f,-1.f,
                                  1.f, 1.f, 1.f,-1.f,
                                  1.f,-1.f, 1.f, 1.f,
                                  1.f, 1.f,-1.f, 1.f};

__global__ void prep_weights(
    const float* __restrict__ W_in,  const float* __restrict__ W_dr,
    const float* __restrict__ W_hyp, const float* __restrict__ Wq_r,
    const float* __restrict__ Wq_i,  const float* __restrict__ Wq_j,
    const float* __restrict__ Wq_k,  const float* __restrict__ W_low,
    const float* __restrict__ W_high,const float* __restrict__ W_out,
    __half* __restrict__ oh, __half* __restrict__ ol)
{
    int idx = blockIdx.x * 256 + threadIdx.x;
    if (idx >= WTS_TOTAL) return;
    if (idx >= OFF_ATT && idx < OFF_WOUT) return;   // filled by combine_attn
    float v;
    if (idx < OFF_WDR) {
        int n = idx >> 9, k = idx & 511;
        v = W_in[(size_t)k * 4608 + n];
    } else if (idx < OFF_WHYP) {
        int r = idx - OFF_WDR, n = r >> 9, k = r & 511;
        v = W_dr[(size_t)k * 512 + n];
    } else if (idx < OFF_QUAT) {
        int r = idx - OFF_WHYP, n = r >> 9, k = r & 511;
        v = W_hyp[(size_t)k * 512 + n];
    } else if (idx < OFF_WAV) {
        int r = idx - OFF_QUAT, n = r >> 9, k = r & 511;
        int co = n >> 7, ho = n & 127, ci = k >> 7, hi = k & 127;
        const float* mats[4] = {Wq_r, Wq_i, Wq_j, Wq_k};
        int sel = co * 4 + ci;
        v = c_sign[sel] * mats[c_which[sel]][hi * 128 + ho];
    } else if (idx < OFF_ATT) {
        int r = idx - OFF_WAV, n = r >> 9, k = r & 511;
        int ho = n >> 1, po = n & 1, hi = k >> 1, pi = k & 1;
        float wl = W_low[hi * 256 + ho], wh = W_high[hi * 256 + ho];
        v = (pi == po) ? 0.5f * (wl + wh) : 0.5f * (wl - wh);
    } else {
        int r = idx - OFF_WOUT, n = r >> 9, k = r & 511;
        v = W_out[(size_t)k * 128 + n];
    }
    __half h = __float2half_rn(v);
    oh[idx] = h;
    ol[idx] = __float2half_rn(v - __half2float(h));
}

// combined attention weights (layer block = [Mqk(512) ; Mvo(512)] rows, K=512)
__global__ void combine_attn(const float* __restrict__ aWq, const float* __restrict__ aWk,
                             const float* __restrict__ aWv, const float* __restrict__ aWo,
                             __half* __restrict__ oh, __half* __restrict__ ol)
{
    __shared__ float As[16][17], Bs[16][17];
    const int z = blockIdx.z, l = z >> 1, type = z & 1;
    const int tx = threadIdx.x, ty = threadIdx.y;
    const size_t wl_off = (size_t)l * 262144;
    const float* Wq = aWq + wl_off;
    const float* Wk = aWk + wl_off;
    const float* Wv = aWv + wl_off;
    const float* Wo = aWo + wl_off;

    float acc = 0.f;
    for (int m0 = 0; m0 < 512; m0 += 16) {
        if (type == 0) {
            As[ty][tx] = Wk[(size_t)(blockIdx.y * 16 + ty) * 512 + m0 + tx];
            Bs[ty][tx] = Wq[(size_t)(blockIdx.x * 16 + ty) * 512 + m0 + tx];
        } else {
            As[ty][tx] = Wo[(size_t)(m0 + ty) * 512 + blockIdx.y * 16 + tx];
            Bs[ty][tx] = Wv[(size_t)(blockIdx.x * 16 + ty) * 512 + m0 + tx];
        }
        __syncthreads();
        if (type == 0) {
            #pragma unroll
            for (int h = 0; h < 16; ++h) acc += As[ty][h] * Bs[tx][h];
        } else {
            #pragma unroll
            for (int m = 0; m < 16; ++m) acc += Bs[tx][m] * As[m][ty];
        }
        __syncthreads();
    }
    const int n = blockIdx.y * 16 + ty;
    const int k = blockIdx.x * 16 + tx;
    const size_t o = (size_t)OFF_ATT + (size_t)z * 262144 + (size_t)n * 512 + k;
    __half h = __float2half_rn(acc);
    oh[o] = h;
    ol[o] = __float2half_rn(acc - __half2float(h));
}

__global__ void split_copy(const float4* __restrict__ in, __half* __restrict__ H,
                           __half* __restrict__ L, int n4)
{
    int i = blockIdx.x * 256 + threadIdx.x;
    if (i >= n4) return;
    float4 v = in[i];
    __half2 h, l;
    split2(v.x, v.y, h, l);
    ((__half2*)H)[2*i]   = h; ((__half2*)L)[2*i]   = l;
    split2(v.z, v.w, h, l);
    ((__half2*)H)[2*i+1] = h; ((__half2*)L)[2*i+1] = l;
}

// ============================================================================
// standalone agg (used once, after W_dr)
// ============================================================================
__global__ void agg_hl(const __half2* __restrict__ ih, const __half2* __restrict__ il,
                       __half2* __restrict__ oh, __half2* __restrict__ ol)
{
    int idx = blockIdx.x * 256 + threadIdx.x;
    const int TOT = B_SZ * NODES * 256;
    if (idx >= TOT) return;
    int h2 = idx & 255;
    int rn = (idx >> 8) % NODES;
    int b  = idx / (NODES * 256);
    size_t p = (size_t)(b * NODES + rn) * 256 + h2;
    __half2 xh = ih[p], xl = il[p];
    if (rn == 8) { oh[idx] = xh; ol[idx] = xl; return; }
    int src = (rn & 1) ? (rn >> 1) : (rn >> 1) + 4;
    size_t q = (size_t)(b * NODES + src) * 256 + h2;
    float2 fa = __half22float2(xh), fal = __half22float2(xl);
    float2 fc = __half22float2(ih[q]), fcl = __half22float2(il[q]);
    float v0 = 0.5f * ((fa.x + fal.x) + (fc.x + fcl.x));
    float v1 = 0.5f * ((fa.y + fal.y) + (fc.y + fcl.y));
    __half2 h, l;
    split2(v0, v1, h, l);
    oh[idx] = h; ol[idx] = l;
}

// ============================================================================
// fused attention + drnorm + residual + agg; QV is ROWS x 1024 (Q | V)
// Q staged in smem (sQ); sQ reused for ctx/nf after score phase.
// smem: sK(18K) + sV(18K) + sQ(18K) + scores = 55.4KB -> 4 CTAs/SM
// ============================================================================
#define AF_SMEM (3 * NODES * H_SZ * 4 + 512)

__global__ __launch_bounds__(256)
void attn_fused(const float* __restrict__ QV,
                const __half* __restrict__ vh, const __half* __restrict__ vl,
                const float* __restrict__ gamma, const float* __restrict__ beta,
                __half* __restrict__ mh, __half* __restrict__ ml)
{
    extern __shared__ float sm[];
    float* sK = sm;                        // v (fp32)              9*512
    float* sV = sm + NODES * H_SZ;         // V                     9*512
    float* sQ = sm + 2 * NODES * H_SZ;     // Q, then ctx -> nf     9*512
    float* sS = sm + 3 * NODES * H_SZ;     // scores                96

    const int b   = blockIdx.x;
    const int tid = threadIdx.x;
    const size_t base   = (size_t)b * NODES * H_SZ;
    const size_t baseQV = (size_t)b * NODES * 1024;

    const __half2* K2h = (const __half2*)(vh + base);
    const __half2* K2l = (const __half2*)(vl + base);
    for (int i = tid; i < NODES * H_SZ / 2; i += 256) {
        float2 h = __half22float2(K2h[i]);
        float2 l = __half22float2(K2l[i]);
        sK[2*i]   = h.x + l.x;
        sK[2*i+1] = h.y + l.y;
    }
    for (int i = tid; i < NODES * H_SZ / 4; i += 256) {
        int rn = i >> 7, c4 = i & 127;
        const float* row = QV + baseQV + (size_t)rn * 1024 + c4 * 4;
        ((float4*)sQ)[i] = *(const float4*)(row);          // Q cols 0..511
        ((float4*)sV)[i] = *(const float4*)(row + 512);    // V cols 512..1023
    }
    __syncthreads();

    const float scale = 0.044194173824159216f;   // 1/sqrt(512)
    const int warp = tid >> 5, lane = tid & 31;
    for (int p = warp; p < 81; p += 8) {
        int q = p / 9, kk = p % 9;
        const float* Qr = sQ + q * H_SZ;
        const float* Kr = sK + kk * H_SZ;
        float s = 0.f;
        #pragma unroll 4
        for (int h = lane; h < H_SZ; h += 32) s += Qr[h] * Kr[h];
        #pragma unroll
        for (int o = 16; o; o >>= 1) s += __shfl_down_sync(0xffffffffu, s, o);
        if (lane == 0) sS[q * 9 + kk] = s * scale;
    }
    __syncthreads();

    if (tid < 9) {
        float mx = -1e30f;
        #pragma unroll
        for (int k = 0; k < 9; ++k) mx = fmaxf(mx, sS[tid * 9 + k]);
        float sum = 0.f;
        #pragma unroll
        for (int k = 0; k < 9; ++k) { float e = expf(sS[tid * 9 + k] - mx); sS[tid * 9 + k] = e; sum += e; }
        float inv = 1.f / sum;
        #pragma unroll
        for (int k = 0; k < 9; ++k) sS[tid * 9 + k] *= inv;
    }
    __syncthreads();

    // ctx -> sQ (Q is dead after scores)
    for (int q = 0; q < 9; ++q) {
        float a[9];
        #pragma unroll
        for (int k = 0; k < 9; ++k) a[k] = sS[q * 9 + k];
        for (int h = tid * 2; h < H_SZ; h += 512) {
            float a0 = 0.f, a1 = 0.f;
            #pragma unroll
            for (int k = 0; k < 9; ++k) {
                a0 = fmaf(a[k], sV[k * H_SZ + h],     a0);
                a1 = fmaf(a[k], sV[k * H_SZ + h + 1], a1);
            }
            sQ[q * H_SZ + h]     = a0;
            sQ[q * H_SZ + h + 1] = a1;
        }
    }
    __syncthreads();

    // drnorm + residual per row (warp r handles rows r, r+8)
    for (int r = warp; r < 9; r += 8) {
        const float* o = sQ + r * H_SZ;
        float s = 0.f, sq = 0.f;
        #pragma unroll
        for (int i = 0; i < 16; ++i) {
            float v = o[lane + 32 * i];
            s += v; sq += v * v;
        }
        #pragma unroll
        for (int off = 16; off; off >>= 1) {
            s  += __shfl_down_sync(0xffffffffu, s, off);
            sq += __shfl_down_sync(0xffffffffu, sq, off);
        }
        float mu  = __shfl_sync(0xffffffffu, s,  0) * (1.f / 512.f);
        float msq = __shfl_sync(0xffffffffu, sq, 0) * (1.f / 512.f);
        float inv = rsqrtf(msq - mu * mu + 1e-5f);
        float* nf = sQ + r * H_SZ;
        const float* vres = sK + r * H_SZ;
        #pragma unroll
        for (int i = 0; i < 16; ++i) {
            int h = lane + 32 * i;
            nf[h] = vres[h] + __ldg(gamma + h) * (nf[h] - mu) * inv + __ldg(beta + h);
        }
    }
    __syncthreads();

    // agg + split -> (mh, ml)
    for (int i = tid; i < NODES * H_SZ / 2; i += 256) {
        int h2 = i & 255;
        int rn = i / 256;
        float2 a = *(float2*)(sQ + rn * H_SZ + 2 * h2);
        float v0, v1;
        if (rn == 8) { v0 = a.x; v1 = a.y; }
        else {
            int src = (rn & 1) ? (rn >> 1) : (rn >> 1) + 4;
            float2 c = *(float2*)(sQ + src * H_SZ + 2 * h2);
            v0 = 0.5f * (a.x + c.x);
            v1 = 0.5f * (a.y + c.y);
        }
        __half2 h, l;
        split2(v0, v1, h, l);
        ((__half2*)(mh + base))[i] = h;
        ((__half2*)(ml + base))[i] = l;
    }
}

// ============================================================================
// host orchestration
// ============================================================================
template<int EPI>
static void launch_hg(const __half* Ah, const __half* Al, const __half* Bh, const __half* Bl,
                      const float* bias, float* C, __half* Ch, __half* Cl,
                      int M, int N, int lda)
{
    cudaFuncSetAttribute(hgemm3<EPI>, cudaFuncAttributeMaxDynamicSharedMemorySize, HG_SMEM);
    dim3 grid(N / 128, M / 64);
    hgemm3<EPI><<<grid, 256, HG_SMEM>>>(Ah, Al, Bh, Bl, bias, C, Ch, Cl, N, lda);
}

struct Ptrs {
    __half *mh, *ml, *ah, *al, *nh, *nl, *xh, *xl, *wh, *wl;
    float *f;
};

// attention layer: ONE N=1024 GEMM (QK|VO) + fused elementwise -> m pair
static void run_attention(const Ptrs& P, int layer, const float* gamma, const float* beta)
{
    const size_t wb = OFF_ATT + (size_t)layer * 2 * 262144;
    launch_hg<0>(P.ah, P.al, P.wh + wb, P.wl + wb, nullptr, P.f, nullptr, nullptr, ROWS, 1024, 512);
    cudaFuncSetAttribute(attn_fused, cudaFuncAttributeMaxDynamicSharedMemorySize, AF_SMEM);
    attn_fused<<<B_SZ, 256, AF_SMEM>>>(P.f, P.ah, P.al, gamma, beta, P.mh, P.ml);
}

extern "C" void kernel_launch(void* const* d_in, const int* in_sizes, int n_in,
                              void* d_out, int out_size)
{
    const float* x      = (const float*)d_in[0];
    const float* W_in   = (const float*)d_in[1];
    const float* b_in   = (const float*)d_in[2];
    const float* W_dr   = (const float*)d_in[3];
    const float* b_dr   = (const float*)d_in[4];
    const float* W_hyp  = (const float*)d_in[5];
    const float* b_hyp  = (const float*)d_in[6];
    const float* Wq_r   = (const float*)d_in[7];
    const float* Wq_i   = (const float*)d_in[8];
    const float* Wq_j   = (const float*)d_in[9];
    const float* Wq_k   = (const float*)d_in[10];
    const float* b_quat = (const float*)d_in[11];
    const float* W_low  = (const float*)d_in[12];
    const float* W_high = (const float*)d_in[13];
    const float* b_wav  = (const float*)d_in[14];
    const float* aWq    = (const float*)d_in[15];
    const float* aWk    = (const float*)d_in[16];
    const float* aWv    = (const float*)d_in[17];
    const float* aWo    = (const float*)d_in[18];
    const float* gamma  = (const float*)d_in[19];
    const float* beta   = (const float*)d_in[20];
    const float* W_out  = (const float*)d_in[21];
    const float* b_out  = (const float*)d_in[22];
    float* out = (float*)d_out;

    Ptrs P;
    cudaGetSymbolAddress((void**)&P.mh, g_mh); cudaGetSymbolAddress((void**)&P.ml, g_ml);
    cudaGetSymbolAddress((void**)&P.ah, g_ah); cudaGetSymbolAddress((void**)&P.al, g_al);
    cudaGetSymbolAddress((void**)&P.nh, g_nh); cudaGetSymbolAddress((void**)&P.nl, g_nl);
    cudaGetSymbolAddress((void**)&P.xh, g_xh); cudaGetSymbolAddress((void**)&P.xl, g_xl);
    cudaGetSymbolAddress((void**)&P.wh, g_wh); cudaGetSymbolAddress((void**)&P.wl, g_wl);
    cudaGetSymbolAddress((void**)&P.f,  g_f);

    // #0 prep (non-attn weights), #1 x split
    prep_weights<<<(WTS_TOTAL + 255) / 256, 256>>>(
        W_in, W_dr, W_hyp, Wq_r, Wq_i, Wq_j, Wq_k, W_low, W_high, W_out, P.wh, P.wl);
    split_copy<<<(B_SZ * H_SZ / 4 + 255) / 256, 256>>>((const float4*)x, P.xh, P.xl, B_SZ * H_SZ / 4);

    const int AGG_BLOCKS = (B_SZ * NODES * 256 + 255) / 256;

    // #2 W_in GEMM, #3 W_dr GEMM, #4 agg, #5 W_hyp GEMM (ncu captures a GEMM)
    launch_hg<1>(P.xh, P.xl, P.wh + OFF_WIN, P.wl + OFF_WIN, b_in, nullptr, P.mh, P.ml, B_SZ, 4608, 512);
    launch_hg<2>(P.mh, P.ml, P.wh + OFF_WDR, P.wl + OFF_WDR, b_dr, nullptr, P.nh, P.nl, ROWS, 512, 512);
    agg_hl<<<AGG_BLOCKS, 256>>>((const __half2*)P.nh, (const __half2*)P.nl, (__half2*)P.mh, (__half2*)P.ml);
    launch_hg<2>(P.mh, P.ml, P.wh + OFF_WHYP, P.wl + OFF_WHYP, b_hyp, nullptr, P.ah, P.al, ROWS, 512, 512);

    // combined attention weights
    combine_attn<<<dim3(32, 32, 6), dim3(16, 16)>>>(aWq, aWk, aWv, aWo, P.wh, P.wl);

    run_attention(P, 0, gamma, beta);
    launch_hg<2>(P.mh, P.ml, P.wh + OFF_QUAT, P.wl + OFF_QUAT, b_quat, nullptr, P.ah, P.al, ROWS, 512, 512);

    run_attention(P, 1, gamma + 512, beta + 512);
    launch_hg<2>(P.mh, P.ml, P.wh + OFF_WAV, P.wl + OFF_WAV, b_wav, nullptr, P.ah, P.al, ROWS, 512, 512);

    run_attention(P, 2, gamma + 1024, beta + 1024);

    // out = nf[:,8,:] @ W_out + b_out
    launch_hg<3>(P.mh + 8 * H_SZ, P.ml + 8 * H_SZ, P.wh + OFF_WOUT, P.wl + OFF_WOUT,
                 b_out, out, nullptr, nullptr, B_SZ, 128, NODES * H_SZ);
}

// round 14
// speedup vs baseline: 1.2303x; 1.0699x over previous
#include <cuda_runtime.h>
#include <cuda_fp16.h>
#include <math.h>
#include <stdint.h>

#define B_SZ   16384
#define H_SZ   512
#define NODES  9
#define ROWS   (B_SZ * NODES)         // 147456
#define BH     (ROWS * H_SZ)          // 75497472

// ---------------- scratch (device globals; no allocation) ----------------
__device__ __half g_mh[BH], g_ml[BH];
__device__ __half g_ah[BH], g_al[BH];
__device__ __half g_nh[BH], g_nl[BH];
__device__ __half g_xh[B_SZ * H_SZ], g_xl[B_SZ * H_SZ];
__device__ float  g_f[2ull * BH];

// weights [N,K] K-major, K=512, hi/lo half pairs
#define OFF_WIN   0                    // 4608*512
#define OFF_WDR   2359296
#define OFF_WHYP  2621440
#define OFF_QUAT  2883584
#define OFF_WAV   3145728
#define OFF_ATT   3407872              // per layer: {Bt_qk, Bt_vo} contiguous (1024x512)
#define OFF_WOUT  6553600              // 128*512
#define WTS_TOTAL 6619136
__device__ __half g_wh[WTS_TOTAL], g_wl[WTS_TOTAL];

// ============================================================================
// helpers
// ============================================================================
__device__ __forceinline__ uint32_t smem_u32(const void* p) {
    uint32_t a;
    asm("{ .reg .u64 t; cvta.to.shared.u64 t, %1; cvt.u32.u64 %0, t; }" : "=r"(a) : "l"(p));
    return a;
}
__device__ __forceinline__ void cp_async16(uint32_t dst, const void* src) {
    asm volatile("cp.async.cg.shared.global [%0], [%1], 16;" :: "r"(dst), "l"(src) : "memory");
}
__device__ __forceinline__ void cp_commit() {
    asm volatile("cp.async.commit_group;" ::: "memory");
}
__device__ __forceinline__ void cp_wait1() {
    asm volatile("cp.async.wait_group 1;" ::: "memory");
}
__device__ __forceinline__ void ldm_x4(uint32_t addr, uint32_t& r0, uint32_t& r1,
                                       uint32_t& r2, uint32_t& r3) {
    asm volatile("ldmatrix.sync.aligned.m8n8.x4.shared.b16 {%0,%1,%2,%3}, [%4];"
                 : "=r"(r0), "=r"(r1), "=r"(r2), "=r"(r3) : "r"(addr));
}
__device__ __forceinline__ void mma_f16(float* c, const uint32_t* a, const uint32_t* b) {
    asm volatile(
        "mma.sync.aligned.m16n8k16.row.col.f32.f16.f16.f32 "
        "{%0,%1,%2,%3}, {%4,%5,%6,%7}, {%8,%9}, {%0,%1,%2,%3};"
        : "+f"(c[0]), "+f"(c[1]), "+f"(c[2]), "+f"(c[3])
        : "r"(a[0]), "r"(a[1]), "r"(a[2]), "r"(a[3]), "r"(b[0]), "r"(b[1]));
}
__device__ __forceinline__ void split2(float d0, float d1, __half2& h, __half2& l) {
    __half h0 = __float2half_rn(d0), h1 = __float2half_rn(d1);
    h = __halves2half2(h0, h1);
    l = __floats2half2_rn(d0 - __half2float(h0), d1 - __half2float(h1));
}

// ============================================================================
// fp16x3 GEMM: C[M,N] = A[M,512] @ Bt[N,512]^T
// EPI: 0 fp32 C; 1 bias+lrelu -> HL; 2 bias+tanh -> HL; 3 bias -> fp32
// BM=64, BN=128, 256 thr, 8 warps (2x4), warp 32x32, 2-stage, 2 CTAs/SM
// ============================================================================
#define A_ST 8192
#define B_ST 16384
#define HG_SMEM (2 * (2 * A_ST + 2 * B_ST) + 1024)

template<int EPI>
__global__ __launch_bounds__(256, 2)
void hgemm3(const __half* __restrict__ Ah, const __half* __restrict__ Al,
            const __half* __restrict__ Bh, const __half* __restrict__ Bl,
            const float* __restrict__ bias, float* __restrict__ C,
            __half* __restrict__ Ch, __half* __restrict__ Cl,
            int N, int lda)
{
    extern __shared__ char smraw[];
    const uint32_t base = (smem_u32(smraw) + 1023) & ~1023u;
    const uint32_t sAh = base;
    const uint32_t sAl = base + 2 * A_ST;
    const uint32_t sBh = base + 4 * A_ST;
    const uint32_t sBl = base + 4 * A_ST + 2 * B_ST;

    const int col0 = blockIdx.x * 128;
    const int row0 = blockIdx.y * 64;

    const int tid    = threadIdx.x;
    const int lane   = tid & 31;
    const int wid    = tid >> 5;
    const int warp_m = wid >> 2;
    const int warp_n = wid & 3;

    const int lm = tid >> 3;
    const int lq = tid & 7;

    const int mat = lane >> 3;
    const int mr  = lane & 7;
    int rbA[2], s7A[2];
    #pragma unroll
    for (int mf = 0; mf < 2; ++mf) {
        int m = warp_m * 32 + mf * 16 + (mat & 1) * 8 + mr;
        rbA[mf] = m * 128; s7A[mf] = m & 7;
    }
    const int qaA = mat >> 1;
    int rbB[2], s7B[2];
    #pragma unroll
    for (int p = 0; p < 2; ++p) {
        int n = warp_n * 32 + (2 * p + (mat >> 1)) * 8 + mr;
        rbB[p] = n * 128; s7B[p] = n & 7;
    }
    const int qaB = mat & 1;

    float acc[2][4][4];
    #pragma unroll
    for (int i = 0; i < 2; ++i)
        #pragma unroll
        for (int j = 0; j < 4; ++j)
            #pragma unroll
            for (int k = 0; k < 4; ++k) acc[i][j][k] = 0.f;

    #pragma unroll
    for (int st = 0; st < 2; ++st) {
        #pragma unroll
        for (int i = 0; i < 2; ++i) {
            const int row = lm + i * 32;
            const uint32_t d = st * A_ST + row * 128 + (((lq ^ (row & 7)) << 4));
            const size_t oa = (size_t)(row0 + row) * lda + st * 64 + lq * 8;
            cp_async16(sAh + d, Ah + oa);
            cp_async16(sAl + d, Al + oa);
        }
        #pragma unroll
        for (int i = 0; i < 4; ++i) {
            const int row = lm + i * 32;
            const uint32_t d = st * B_ST + row * 128 + (((lq ^ (row & 7)) << 4));
            const size_t ob = (size_t)(col0 + row) * 512 + st * 64 + lq * 8;
            cp_async16(sBh + d, Bh + ob);
            cp_async16(sBl + d, Bl + ob);
        }
        cp_commit();
    }

    #pragma unroll 1
    for (int t = 0; t < 8; ++t) {
        cp_wait1();
        __syncthreads();

        const uint32_t pAh = sAh + (t & 1) * A_ST;
        const uint32_t pAl = sAl + (t & 1) * A_ST;
        const uint32_t pBh = sBh + (t & 1) * B_ST;
        const uint32_t pBl = sBl + (t & 1) * B_ST;

        #pragma unroll
        for (int ks = 0; ks < 4; ++ks) {
            uint32_t ah[2][4], al[2][4];
            #pragma unroll
            for (int mf = 0; mf < 2; ++mf) {
                const uint32_t off = rbA[mf] + (((2 * ks + qaA) ^ s7A[mf]) << 4);
                ldm_x4(pAh + off, ah[mf][0], ah[mf][1], ah[mf][2], ah[mf][3]);
                ldm_x4(pAl + off, al[mf][0], al[mf][1], al[mf][2], al[mf][3]);
            }
            #pragma unroll
            for (int p = 0; p < 2; ++p) {
                uint32_t bh[2][2], bl[2][2];
                const uint32_t off = rbB[p] + (((2 * ks + qaB) ^ s7B[p]) << 4);
                ldm_x4(pBh + off, bh[0][0], bh[0][1], bh[1][0], bh[1][1]);
                ldm_x4(pBl + off, bl[0][0], bl[0][1], bl[1][0], bl[1][1]);
                #pragma unroll
                for (int mf = 0; mf < 2; ++mf)
                    #pragma unroll
                    for (int q = 0; q < 2; ++q) {
                        float* a_ = acc[mf][2 * p + q];
                        mma_f16(a_, ah[mf], bh[q]);
                        mma_f16(a_, ah[mf], bl[q]);
                        mma_f16(a_, al[mf], bh[q]);
                    }
            }
        }
        __syncthreads();
        if (t + 2 < 8) {
            const int st = t & 1;
            #pragma unroll
            for (int i = 0; i < 2; ++i) {
                const int row = lm + i * 32;
                const uint32_t d = st * A_ST + row * 128 + (((lq ^ (row & 7)) << 4));
                const size_t oa = (size_t)(row0 + row) * lda + (t + 2) * 64 + lq * 8;
                cp_async16(sAh + d, Ah + oa);
                cp_async16(sAl + d, Al + oa);
            }
            #pragma unroll
            for (int i = 0; i < 4; ++i) {
                const int row = lm + i * 32;
                const uint32_t d = st * B_ST + row * 128 + (((lq ^ (row & 7)) << 4));
                const size_t ob = (size_t)(col0 + row) * 512 + (t + 2) * 64 + lq * 8;
                cp_async16(sBh + d, Bh + ob);
                cp_async16(sBl + d, Bl + ob);
            }
        }
        cp_commit();
    }

    const int g  = lane >> 2;
    const int t4 = lane & 3;
    #pragma unroll
    for (int mf = 0; mf < 2; ++mf) {
        #pragma unroll
        for (int nf = 0; nf < 4; ++nf) {
            const int r1 = row0 + warp_m * 32 + mf * 16 + g;
            const int cc = col0 + warp_n * 32 + nf * 8 + t4 * 2;
            float d[4] = {acc[mf][nf][0], acc[mf][nf][1], acc[mf][nf][2], acc[mf][nf][3]};
            if (EPI != 0) {
                float b0 = __ldg(bias + cc), b1 = __ldg(bias + cc + 1);
                d[0] += b0; d[1] += b1; d[2] += b0; d[3] += b1;
                #pragma unroll
                for (int i = 0; i < 4; ++i) {
                    if (EPI == 1)      d[i] = d[i] > 0.f ? d[i] : 0.01f * d[i];
                    else if (EPI == 2) d[i] = tanhf(d[i]);
                }
            }
            if (EPI == 0 || EPI == 3) {
                *(float2*)(C + (size_t)r1 * N + cc)       = make_float2(d[0], d[1]);
                *(float2*)(C + (size_t)(r1 + 8) * N + cc) = make_float2(d[2], d[3]);
            } else {
                __half2 h, l;
                split2(d[0], d[1], h, l);
                *(__half2*)(Ch + (size_t)r1 * N + cc) = h;
                *(__half2*)(Cl + (size_t)r1 * N + cc) = l;
                split2(d[2], d[3], h, l);
                *(__half2*)(Ch + (size_t)(r1 + 8) * N + cc) = h;
                *(__half2*)(Cl + (size_t)(r1 + 8) * N + cc) = l;
            }
        }
    }
}

// ============================================================================
// weight prep (non-attention weights)
// ============================================================================
__constant__ int   c_which[16] = {0,1,2,3, 1,0,3,2, 2,3,0,1, 3,2,1,0};
__constant__ float c_sign [16] = {1.f,-1.f,-1.f,-1.f,
                                  1.f, 1.f, 1.f,-1.f,
                                  1.f,-1.f, 1.f, 1.f,
                                  1.f, 1.f,-1.f, 1.f};

__global__ void prep_weights(
    const float* __restrict__ W_in,  const float* __restrict__ W_dr,
    const float* __restrict__ W_hyp, const float* __restrict__ Wq_r,
    const float* __restrict__ Wq_i,  const float* __restrict__ Wq_j,
    const float* __restrict__ Wq_k,  const float* __restrict__ W_low,
    const float* __restrict__ W_high,const float* __restrict__ W_out,
    __half* __restrict__ oh, __half* __restrict__ ol)
{
    int idx = blockIdx.x * 256 + threadIdx.x;
    if (idx >= WTS_TOTAL) return;
    if (idx >= OFF_ATT && idx < OFF_WOUT) return;
    float v;
    if (idx < OFF_WDR) {
        int n = idx >> 9, k = idx & 511;
        v = W_in[(size_t)k * 4608 + n];
    } else if (idx < OFF_WHYP) {
        int r = idx - OFF_WDR, n = r >> 9, k = r & 511;
        v = W_dr[(size_t)k * 512 + n];
    } else if (idx < OFF_QUAT) {
        int r = idx - OFF_WHYP, n = r >> 9, k = r & 511;
        v = W_hyp[(size_t)k * 512 + n];
    } else if (idx < OFF_WAV) {
        int r = idx - OFF_QUAT, n = r >> 9, k = r & 511;
        int co = n >> 7, ho = n & 127, ci = k >> 7, hi = k & 127;
        const float* mats[4] = {Wq_r, Wq_i, Wq_j, Wq_k};
        int sel = co * 4 + ci;
        v = c_sign[sel] * mats[c_which[sel]][hi * 128 + ho];
    } else if (idx < OFF_ATT) {
        int r = idx - OFF_WAV, n = r >> 9, k = r & 511;
        int ho = n >> 1, po = n & 1, hi = k >> 1, pi = k & 1;
        float wl = W_low[hi * 256 + ho], wh = W_high[hi * 256 + ho];
        v = (pi == po) ? 0.5f * (wl + wh) : 0.5f * (wl - wh);
    } else {
        int r = idx - OFF_WOUT, n = r >> 9, k = r & 511;
        v = W_out[(size_t)k * 128 + n];
    }
    __half h = __float2half_rn(v);
    oh[idx] = h;
    ol[idx] = __float2half_rn(v - __half2float(h));
}

// combined attention weights (layer block = [Mqk(512) ; Mvo(512)] rows, K=512)
__global__ void combine_attn(const float* __restrict__ aWq, const float* __restrict__ aWk,
                             const float* __restrict__ aWv, const float* __restrict__ aWo,
                             __half* __restrict__ oh, __half* __restrict__ ol)
{
    __shared__ float As[16][17], Bs[16][17];
    const int z = blockIdx.z, l = z >> 1, type = z & 1;
    const int tx = threadIdx.x, ty = threadIdx.y;
    const size_t wl_off = (size_t)l * 262144;
    const float* Wq = aWq + wl_off;
    const float* Wk = aWk + wl_off;
    const float* Wv = aWv + wl_off;
    const float* Wo = aWo + wl_off;

    float acc = 0.f;
    for (int m0 = 0; m0 < 512; m0 += 16) {
        if (type == 0) {
            As[ty][tx] = Wk[(size_t)(blockIdx.y * 16 + ty) * 512 + m0 + tx];
            Bs[ty][tx] = Wq[(size_t)(blockIdx.x * 16 + ty) * 512 + m0 + tx];
        } else {
            As[ty][tx] = Wo[(size_t)(m0 + ty) * 512 + blockIdx.y * 16 + tx];
            Bs[ty][tx] = Wv[(size_t)(blockIdx.x * 16 + ty) * 512 + m0 + tx];
        }
        __syncthreads();
        if (type == 0) {
            #pragma unroll
            for (int h = 0; h < 16; ++h) acc += As[ty][h] * Bs[tx][h];
        } else {
            #pragma unroll
            for (int m = 0; m < 16; ++m) acc += Bs[tx][m] * As[m][ty];
        }
        __syncthreads();
    }
    const int n = blockIdx.y * 16 + ty;
    const int k = blockIdx.x * 16 + tx;
    const size_t o = (size_t)OFF_ATT + (size_t)z * 262144 + (size_t)n * 512 + k;
    __half h = __float2half_rn(acc);
    oh[o] = h;
    ol[o] = __float2half_rn(acc - __half2float(h));
}

__global__ void split_copy(const float4* __restrict__ in, __half* __restrict__ H,
                           __half* __restrict__ L, int n4)
{
    int i = blockIdx.x * 256 + threadIdx.x;
    if (i >= n4) return;
    float4 v = in[i];
    __half2 h, l;
    split2(v.x, v.y, h, l);
    ((__half2*)H)[2*i]   = h; ((__half2*)L)[2*i]   = l;
    split2(v.z, v.w, h, l);
    ((__half2*)H)[2*i+1] = h; ((__half2*)L)[2*i+1] = l;
}

// ============================================================================
// standalone agg (used once, after W_dr)
// ============================================================================
__global__ void agg_hl(const __half2* __restrict__ ih, const __half2* __restrict__ il,
                       __half2* __restrict__ oh, __half2* __restrict__ ol)
{
    int idx = blockIdx.x * 256 + threadIdx.x;
    const int TOT = B_SZ * NODES * 256;
    if (idx >= TOT) return;
    int h2 = idx & 255;
    int rn = (idx >> 8) % NODES;
    int b  = idx / (NODES * 256);
    size_t p = (size_t)(b * NODES + rn) * 256 + h2;
    __half2 xh = ih[p], xl = il[p];
    if (rn == 8) { oh[idx] = xh; ol[idx] = xl; return; }
    int src = (rn & 1) ? (rn >> 1) : (rn >> 1) + 4;
    size_t q = (size_t)(b * NODES + src) * 256 + h2;
    float2 fa = __half22float2(xh), fal = __half22float2(xl);
    float2 fc = __half22float2(ih[q]), fcl = __half22float2(il[q]);
    float v0 = 0.5f * ((fa.x + fal.x) + (fc.x + fcl.x));
    float v1 = 0.5f * ((fa.y + fal.y) + (fc.y + fcl.y));
    __half2 h, l;
    split2(v0, v1, h, l);
    oh[idx] = h; ol[idx] = l;
}

// ============================================================================
// fused attention + drnorm + residual + agg (layers 0,1); QV = ROWS x 1024
// float4-vectorized score/ctx phases.
// ============================================================================
#define AF_SMEM (3 * NODES * H_SZ * 4 + 512)

__global__ __launch_bounds__(256)
void attn_fused(const float* __restrict__ QV,
                const __half* __restrict__ vh, const __half* __restrict__ vl,
                const float* __restrict__ gamma, const float* __restrict__ beta,
                __half* __restrict__ mh, __half* __restrict__ ml)
{
    extern __shared__ float sm[];
    float* sK = sm;                        // v (fp32)              9*512
    float* sV = sm + NODES * H_SZ;         // V                     9*512
    float* sQ = sm + 2 * NODES * H_SZ;     // Q, then ctx -> nf     9*512
    float* sS = sm + 3 * NODES * H_SZ;     // scores                96

    const int b   = blockIdx.x;
    const int tid = threadIdx.x;
    const size_t base   = (size_t)b * NODES * H_SZ;
    const size_t baseQV = (size_t)b * NODES * 1024;

    const __half2* K2h = (const __half2*)(vh + base);
    const __half2* K2l = (const __half2*)(vl + base);
    for (int i = tid; i < NODES * H_SZ / 2; i += 256) {
        float2 h = __half22float2(K2h[i]);
        float2 l = __half22float2(K2l[i]);
        sK[2*i]   = h.x + l.x;
        sK[2*i+1] = h.y + l.y;
    }
    for (int i = tid; i < NODES * H_SZ / 4; i += 256) {
        int rn = i >> 7, c4 = i & 127;
        const float* row = QV + baseQV + (size_t)rn * 1024 + c4 * 4;
        ((float4*)sQ)[i] = *(const float4*)(row);
        ((float4*)sV)[i] = *(const float4*)(row + 512);
    }
    __syncthreads();

    const float scale = 0.044194173824159216f;   // 1/sqrt(512)
    const int warp = tid >> 5, lane = tid & 31;
    for (int p = warp; p < 81; p += 8) {
        int q = p / 9, kk = p % 9;
        const float4* Q4 = (const float4*)(sQ + q * H_SZ);
        const float4* K4 = (const float4*)(sK + kk * H_SZ);
        float s = 0.f;
        #pragma unroll
        for (int h4 = 0; h4 < 4; ++h4) {
            float4 qv = Q4[lane + 32 * h4];
            float4 kv = K4[lane + 32 * h4];
            s += qv.x * kv.x + qv.y * kv.y + qv.z * kv.z + qv.w * kv.w;
        }
        #pragma unroll
        for (int o = 16; o; o >>= 1) s += __shfl_down_sync(0xffffffffu, s, o);
        if (lane == 0) sS[q * 9 + kk] = s * scale;
    }
    __syncthreads();

    if (tid < 9) {
        float mx = -1e30f;
        #pragma unroll
        for (int k = 0; k < 9; ++k) mx = fmaxf(mx, sS[tid * 9 + k]);
        float sum = 0.f;
        #pragma unroll
        for (int k = 0; k < 9; ++k) { float e = expf(sS[tid * 9 + k] - mx); sS[tid * 9 + k] = e; sum += e; }
        float inv = 1.f / sum;
        #pragma unroll
        for (int k = 0; k < 9; ++k) sS[tid * 9 + k] *= inv;
    }
    __syncthreads();

    // ctx -> sQ (task-parallel over (q, c4))
    for (int i = tid; i < NODES * 128; i += 256) {
        int q = i >> 7, c4 = i & 127;
        const float* a = sS + q * 9;
        float4 acc = make_float4(0.f, 0.f, 0.f, 0.f);
        #pragma unroll
        for (int k = 0; k < 9; ++k) {
            float4 v = ((const float4*)(sV + k * H_SZ))[c4];
            float ak = a[k];
            acc.x = fmaf(ak, v.x, acc.x);
            acc.y = fmaf(ak, v.y, acc.y);
            acc.z = fmaf(ak, v.z, acc.z);
            acc.w = fmaf(ak, v.w, acc.w);
        }
        ((float4*)(sQ + q * H_SZ))[c4] = acc;
    }
    __syncthreads();

    // drnorm + residual per row
    for (int r = warp; r < 9; r += 8) {
        const float* o = sQ + r * H_SZ;
        float s = 0.f, sq = 0.f;
        #pragma unroll
        for (int i = 0; i < 16; ++i) {
            float v = o[lane + 32 * i];
            s += v; sq += v * v;
        }
        #pragma unroll
        for (int off = 16; off; off >>= 1) {
            s  += __shfl_down_sync(0xffffffffu, s, off);
            sq += __shfl_down_sync(0xffffffffu, sq, off);
        }
        float mu  = __shfl_sync(0xffffffffu, s,  0) * (1.f / 512.f);
        float msq = __shfl_sync(0xffffffffu, sq, 0) * (1.f / 512.f);
        float inv = rsqrtf(msq - mu * mu + 1e-5f);
        float* nf = sQ + r * H_SZ;
        const float* vres = sK + r * H_SZ;
        #pragma unroll
        for (int i = 0; i < 16; ++i) {
            int h = lane + 32 * i;
            nf[h] = vres[h] + __ldg(gamma + h) * (nf[h] - mu) * inv + __ldg(beta + h);
        }
    }
    __syncthreads();

    // agg + split -> (mh, ml)
    for (int i = tid; i < NODES * H_SZ / 2; i += 256) {
        int h2 = i & 255;
        int rn = i / 256;
        float2 a = *(float2*)(sQ + rn * H_SZ + 2 * h2);
        float v0, v1;
        if (rn == 8) { v0 = a.x; v1 = a.y; }
        else {
            int src = (rn & 1) ? (rn >> 1) : (rn >> 1) + 4;
            float2 c = *(float2*)(sQ + src * H_SZ + 2 * h2);
            v0 = 0.5f * (a.x + c.x);
            v1 = 0.5f * (a.y + c.y);
        }
        __half2 h, l;
        split2(v0, v1, h, l);
        ((__half2*)(mh + base))[i] = h;
        ((__half2*)(ml + base))[i] = l;
    }
}

// ============================================================================
// last-layer attention: only query row 8 is needed downstream.
// V[ROWS x 512] (vo gemm), Q8[B x 512] (qk gemm on node-8 rows only).
// Writes nf row 8 split into (mh, ml) at base + 8*512.
// ============================================================================
#define AL_SMEM ((2 * NODES * H_SZ + H_SZ) * 4 + 512)

__global__ __launch_bounds__(256)
void attn_last(const float* __restrict__ V, const float* __restrict__ Q8,
               const __half* __restrict__ vh, const __half* __restrict__ vl,
               const float* __restrict__ gamma, const float* __restrict__ beta,
               __half* __restrict__ mh, __half* __restrict__ ml)
{
    extern __shared__ float sm[];
    float* sK = sm;                        // v (fp32)           9*512
    float* sV = sm + NODES * H_SZ;         // V                  9*512
    float* sC = sm + 2 * NODES * H_SZ;     // Q8 row, then ctx   512
    float* sS = sm + 2 * NODES * H_SZ + H_SZ;   // scores 9 + red 16 + mu/inv

    const int b   = blockIdx.x;
    const int tid = threadIdx.x;
    const int warp = tid >> 5, lane = tid & 31;
    const size_t base = (size_t)b * NODES * H_SZ;

    const __half2* K2h = (const __half2*)(vh + base);
    const __half2* K2l = (const __half2*)(vl + base);
    for (int i = tid; i < NODES * H_SZ / 2; i += 256) {
        float2 h = __half22float2(K2h[i]);
        float2 l = __half22float2(K2l[i]);
        sK[2*i]   = h.x + l.x;
        sK[2*i+1] = h.y + l.y;
    }
    const float4* V4 = (const float4*)(V + base);
    for (int i = tid; i < NODES * H_SZ / 4; i += 256)
        ((float4*)sV)[i] = V4[i];
    if (tid < 128)
        ((float4*)sC)[tid] = ((const float4*)(Q8 + (size_t)b * H_SZ))[tid];
    __syncthreads();

    const float scale = 0.044194173824159216f;
    for (int kk = warp; kk < 9; kk += 8) {
        const float4* Q4 = (const float4*)sC;
        const float4* K4 = (const float4*)(sK + kk * H_SZ);
        float s = 0.f;
        #pragma unroll
        for (int h4 = 0; h4 < 4; ++h4) {
            float4 qv = Q4[lane + 32 * h4];
            float4 kv = K4[lane + 32 * h4];
            s += qv.x * kv.x + qv.y * kv.y + qv.z * kv.z + qv.w * kv.w;
        }
        #pragma unroll
        for (int o = 16; o; o >>= 1) s += __shfl_down_sync(0xffffffffu, s, o);
        if (lane == 0) sS[kk] = s * scale;
    }
    __syncthreads();

    if (tid == 0) {
        float mx = -1e30f;
        #pragma unroll
        for (int k = 0; k < 9; ++k) mx = fmaxf(mx, sS[k]);
        float sum = 0.f;
        #pragma unroll
        for (int k = 0; k < 9; ++k) { float e = expf(sS[k] - mx); sS[k] = e; sum += e; }
        float inv = 1.f / sum;
        #pragma unroll
        for (int k = 0; k < 9; ++k) sS[k] *= inv;
    }
    __syncthreads();

    // ctx row -> sC (Q dead)
    if (tid < 128) {
        float4 acc = make_float4(0.f, 0.f, 0.f, 0.f);
        #pragma unroll
        for (int k = 0; k < 9; ++k) {
            float4 v = ((const float4*)(sV + k * H_SZ))[tid];
            float ak = sS[k];
            acc.x = fmaf(ak, v.x, acc.x);
            acc.y = fmaf(ak, v.y, acc.y);
            acc.z = fmaf(ak, v.z, acc.z);
            acc.w = fmaf(ak, v.w, acc.w);
        }
        ((float4*)sC)[tid] = acc;
    }
    __syncthreads();

    // block drnorm over sC[512]
    {
        float v1 = sC[tid], v2 = sC[tid + 256];
        float s = v1 + v2, sq = v1 * v1 + v2 * v2;
        #pragma unroll
        for (int o = 16; o; o >>= 1) {
            s  += __shfl_down_sync(0xffffffffu, s, o);
            sq += __shfl_down_sync(0xffffffffu, sq, o);
        }
        float* red = sS + 9;
        if (lane == 0) { red[warp] = s; red[warp + 8] = sq; }
        __syncthreads();
        if (tid == 0) {
            float S = 0.f, SQ = 0.f;
            #pragma unroll
            for (int w = 0; w < 8; ++w) { S += red[w]; SQ += red[w + 8]; }
            float mu = S * (1.f / 512.f);
            float var = SQ * (1.f / 512.f) - mu * mu;
            red[16] = mu;
            red[17] = rsqrtf(var + 1e-5f);
        }
        __syncthreads();
        float mu = red[16], inv = red[17];
        const float* vres = sK + 8 * H_SZ;
        __half2* oh = (__half2*)(mh + base + 8 * H_SZ);
        __half2* ol = (__half2*)(ml + base + 8 * H_SZ);
        // each thread writes one half2 (cols 2*tid, 2*tid+1)
        float c0 = sC[2 * tid], c1 = sC[2 * tid + 1];
        float n0 = vres[2 * tid]     + __ldg(gamma + 2 * tid)     * (c0 - mu) * inv + __ldg(beta + 2 * tid);
        float n1 = vres[2 * tid + 1] + __ldg(gamma + 2 * tid + 1) * (c1 - mu) * inv + __ldg(beta + 2 * tid + 1);
        __half2 h, l;
        split2(n0, n1, h, l);
        oh[tid] = h;
        ol[tid] = l;
    }
}

// ============================================================================
// host orchestration
// ============================================================================
template<int EPI>
static void launch_hg(const __half* Ah, const __half* Al, const __half* Bh, const __half* Bl,
                      const float* bias, float* C, __half* Ch, __half* Cl,
                      int M, int N, int lda)
{
    cudaFuncSetAttribute(hgemm3<EPI>, cudaFuncAttributeMaxDynamicSharedMemorySize, HG_SMEM);
    dim3 grid(N / 128, M / 64);
    hgemm3<EPI><<<grid, 256, HG_SMEM>>>(Ah, Al, Bh, Bl, bias, C, Ch, Cl, N, lda);
}

struct Ptrs {
    __half *mh, *ml, *ah, *al, *nh, *nl, *xh, *xl, *wh, *wl;
    float *f;
};

static void run_attention(const Ptrs& P, int layer, const float* gamma, const float* beta)
{
    const size_t wb = OFF_ATT + (size_t)layer * 2 * 262144;
    launch_hg<0>(P.ah, P.al, P.wh + wb, P.wl + wb, nullptr, P.f, nullptr, nullptr, ROWS, 1024, 512);
    cudaFuncSetAttribute(attn_fused, cudaFuncAttributeMaxDynamicSharedMemorySize, AF_SMEM);
    attn_fused<<<B_SZ, 256, AF_SMEM>>>(P.f, P.ah, P.al, gamma, beta, P.mh, P.ml);
}

extern "C" void kernel_launch(void* const* d_in, const int* in_sizes, int n_in,
                              void* d_out, int out_size)
{
    const float* x      = (const float*)d_in[0];
    const float* W_in   = (const float*)d_in[1];
    const float* b_in   = (const float*)d_in[2];
    const float* W_dr   = (const float*)d_in[3];
    const float* b_dr   = (const float*)d_in[4];
    const float* W_hyp  = (const float*)d_in[5];
    const float* b_hyp  = (const float*)d_in[6];
    const float* Wq_r   = (const float*)d_in[7];
    const float* Wq_i   = (const float*)d_in[8];
    const float* Wq_j   = (const float*)d_in[9];
    const float* Wq_k   = (const float*)d_in[10];
    const float* b_quat = (const float*)d_in[11];
    const float* W_low  = (const float*)d_in[12];
    const float* W_high = (const float*)d_in[13];
    const float* b_wav  = (const float*)d_in[14];
    const float* aWq    = (const float*)d_in[15];
    const float* aWk    = (const float*)d_in[16];
    const float* aWv    = (const float*)d_in[17];
    const float* aWo    = (const float*)d_in[18];
    const float* gamma  = (const float*)d_in[19];
    const float* beta   = (const float*)d_in[20];
    const float* W_out  = (const float*)d_in[21];
    const float* b_out  = (const float*)d_in[22];
    float* out = (float*)d_out;

    Ptrs P;
    cudaGetSymbolAddress((void**)&P.mh, g_mh); cudaGetSymbolAddress((void**)&P.ml, g_ml);
    cudaGetSymbolAddress((void**)&P.ah, g_ah); cudaGetSymbolAddress((void**)&P.al, g_al);
    cudaGetSymbolAddress((void**)&P.nh, g_nh); cudaGetSymbolAddress((void**)&P.nl, g_nl);
    cudaGetSymbolAddress((void**)&P.xh, g_xh); cudaGetSymbolAddress((void**)&P.xl, g_xl);
    cudaGetSymbolAddress((void**)&P.wh, g_wh); cudaGetSymbolAddress((void**)&P.wl, g_wl);
    cudaGetSymbolAddress((void**)&P.f,  g_f);

    prep_weights<<<(WTS_TOTAL + 255) / 256, 256>>>(
        W_in, W_dr, W_hyp, Wq_r, Wq_i, Wq_j, Wq_k, W_low, W_high, W_out, P.wh, P.wl);
    split_copy<<<(B_SZ * H_SZ / 4 + 255) / 256, 256>>>((const float4*)x, P.xh, P.xl, B_SZ * H_SZ / 4);

    const int AGG_BLOCKS = (B_SZ * NODES * 256 + 255) / 256;

    launch_hg<1>(P.xh, P.xl, P.wh + OFF_WIN, P.wl + OFF_WIN, b_in, nullptr, P.mh, P.ml, B_SZ, 4608, 512);
    launch_hg<2>(P.mh, P.ml, P.wh + OFF_WDR, P.wl + OFF_WDR, b_dr, nullptr, P.nh, P.nl, ROWS, 512, 512);
    agg_hl<<<AGG_BLOCKS, 256>>>((const __half2*)P.nh, (const __half2*)P.nl, (__half2*)P.mh, (__half2*)P.ml);
    launch_hg<2>(P.mh, P.ml, P.wh + OFF_WHYP, P.wl + OFF_WHYP, b_hyp, nullptr, P.ah, P.al, ROWS, 512, 512);

    combine_attn<<<dim3(32, 32, 6), dim3(16, 16)>>>(aWq, aWk, aWv, aWo, P.wh, P.wl);

    run_attention(P, 0, gamma, beta);
    launch_hg<2>(P.mh, P.ml, P.wh + OFF_QUAT, P.wl + OFF_QUAT, b_quat, nullptr, P.ah, P.al, ROWS, 512, 512);

    run_attention(P, 1, gamma + 512, beta + 512);
    launch_hg<2>(P.mh, P.ml, P.wh + OFF_WAV, P.wl + OFF_WAV, b_wav, nullptr, P.ah, P.al, ROWS, 512, 512);

    // ---- last layer: VO full + QK on node-8 rows only + attn_last ----
    {
        const size_t wb = OFF_ATT + (size_t)2 * 2 * 262144;
        // V = v @ Wvo  (all rows) -> f[0..BH)
        launch_hg<0>(P.ah, P.al, P.wh + wb + 262144, P.wl + wb + 262144,
                     nullptr, P.f, nullptr, nullptr, ROWS, 512, 512);
        // Q8 = v8 @ Wqk (node-8 rows, strided A) -> f[BH..BH+B*512)
        launch_hg<0>(P.ah + 8 * H_SZ, P.al + 8 * H_SZ, P.wh + wb, P.wl + wb,
                     nullptr, P.f + BH, nullptr, nullptr, B_SZ, 512, NODES * H_SZ);
        cudaFuncSetAttribute(attn_last, cudaFuncAttributeMaxDynamicSharedMemorySize, AL_SMEM);
        attn_last<<<B_SZ, 256, AL_SMEM>>>(P.f, P.f + BH, P.ah, P.al,
                                          gamma + 1024, beta + 1024, P.mh, P.ml);
    }

    // out = nf[:,8,:] @ W_out + b_out
    launch_hg<3>(P.mh + 8 * H_SZ, P.ml + 8 * H_SZ, P.wh + OFF_WOUT, P.wl + OFF_WOUT,
                 b_out, out, nullptr, nullptr, B_SZ, 128, NODES * H_SZ);
}

// round 15
// speedup vs baseline: 1.2420x; 1.0095x over previous
#include <cuda_runtime.h>
#include <cuda_fp16.h>
#include <math.h>
#include <stdint.h>

#define B_SZ   16384
#define H_SZ   512
#define NODES  9
#define ROWS   (B_SZ * NODES)         // 147456
#define BH     (ROWS * H_SZ)          // 75497472

// ---------------- scratch (device globals; no allocation) ----------------
__device__ __half g_mh[BH], g_ml[BH];
__device__ __half g_ah[BH], g_al[BH];
__device__ __half g_nh[BH], g_nl[BH];
__device__ __half g_xh[B_SZ * H_SZ], g_xl[B_SZ * H_SZ];
__device__ float  g_f[2ull * BH];

// weights [N,K] K-major, K=512, hi/lo half pairs
#define OFF_WIN   0                    // 4608*512
#define OFF_WDR   2359296
#define OFF_WHYP  2621440
#define OFF_QUAT  2883584
#define OFF_WAV   3145728
#define OFF_ATT   3407872              // per layer: {Bt_qk, Bt_vo} contiguous (1024x512)
#define OFF_WOUT  6553600              // 128*512
#define WTS_TOTAL 6619136
__device__ __half g_wh[WTS_TOTAL], g_wl[WTS_TOTAL];

// ============================================================================
// helpers
// ============================================================================
__device__ __forceinline__ uint32_t smem_u32(const void* p) {
    uint32_t a;
    asm("{ .reg .u64 t; cvta.to.shared.u64 t, %1; cvt.u32.u64 %0, t; }" : "=r"(a) : "l"(p));
    return a;
}
__device__ __forceinline__ void cp_async16(uint32_t dst, const void* src) {
    asm volatile("cp.async.cg.shared.global [%0], [%1], 16;" :: "r"(dst), "l"(src) : "memory");
}
__device__ __forceinline__ void cp_commit() {
    asm volatile("cp.async.commit_group;" ::: "memory");
}
__device__ __forceinline__ void cp_wait1() {
    asm volatile("cp.async.wait_group 1;" ::: "memory");
}
__device__ __forceinline__ void ldm_x4(uint32_t addr, uint32_t& r0, uint32_t& r1,
                                       uint32_t& r2, uint32_t& r3) {
    asm volatile("ldmatrix.sync.aligned.m8n8.x4.shared.b16 {%0,%1,%2,%3}, [%4];"
                 : "=r"(r0), "=r"(r1), "=r"(r2), "=r"(r3) : "r"(addr));
}
__device__ __forceinline__ void mma_f16(float* c, const uint32_t* a, const uint32_t* b) {
    asm volatile(
        "mma.sync.aligned.m16n8k16.row.col.f32.f16.f16.f32 "
        "{%0,%1,%2,%3}, {%4,%5,%6,%7}, {%8,%9}, {%0,%1,%2,%3};"
        : "+f"(c[0]), "+f"(c[1]), "+f"(c[2]), "+f"(c[3])
        : "r"(a[0]), "r"(a[1]), "r"(a[2]), "r"(a[3]), "r"(b[0]), "r"(b[1]));
}
__device__ __forceinline__ void split2(float d0, float d1, __half2& h, __half2& l) {
    __half h0 = __float2half_rn(d0), h1 = __float2half_rn(d1);
    h = __halves2half2(h0, h1);
    l = __floats2half2_rn(d0 - __half2float(h0), d1 - __half2float(h1));
}

// ============================================================================
// fp16x3 GEMM (unchanged since R13): C[M,N] = A[M,512] @ Bt[N,512]^T
// ============================================================================
#define A_ST 8192
#define B_ST 16384
#define HG_SMEM (2 * (2 * A_ST + 2 * B_ST) + 1024)

template<int EPI>
__global__ __launch_bounds__(256, 2)
void hgemm3(const __half* __restrict__ Ah, const __half* __restrict__ Al,
            const __half* __restrict__ Bh, const __half* __restrict__ Bl,
            const float* __restrict__ bias, float* __restrict__ C,
            __half* __restrict__ Ch, __half* __restrict__ Cl,
            int N, int lda)
{
    extern __shared__ char smraw[];
    const uint32_t base = (smem_u32(smraw) + 1023) & ~1023u;
    const uint32_t sAh = base;
    const uint32_t sAl = base + 2 * A_ST;
    const uint32_t sBh = base + 4 * A_ST;
    const uint32_t sBl = base + 4 * A_ST + 2 * B_ST;

    const int col0 = blockIdx.x * 128;
    const int row0 = blockIdx.y * 64;

    const int tid    = threadIdx.x;
    const int lane   = tid & 31;
    const int wid    = tid >> 5;
    const int warp_m = wid >> 2;
    const int warp_n = wid & 3;

    const int lm = tid >> 3;
    const int lq = tid & 7;

    const int mat = lane >> 3;
    const int mr  = lane & 7;
    int rbA[2], s7A[2];
    #pragma unroll
    for (int mf = 0; mf < 2; ++mf) {
        int m = warp_m * 32 + mf * 16 + (mat & 1) * 8 + mr;
        rbA[mf] = m * 128; s7A[mf] = m & 7;
    }
    const int qaA = mat >> 1;
    int rbB[2], s7B[2];
    #pragma unroll
    for (int p = 0; p < 2; ++p) {
        int n = warp_n * 32 + (2 * p + (mat >> 1)) * 8 + mr;
        rbB[p] = n * 128; s7B[p] = n & 7;
    }
    const int qaB = mat & 1;

    float acc[2][4][4];
    #pragma unroll
    for (int i = 0; i < 2; ++i)
        #pragma unroll
        for (int j = 0; j < 4; ++j)
            #pragma unroll
            for (int k = 0; k < 4; ++k) acc[i][j][k] = 0.f;

    #pragma unroll
    for (int st = 0; st < 2; ++st) {
        #pragma unroll
        for (int i = 0; i < 2; ++i) {
            const int row = lm + i * 32;
            const uint32_t d = st * A_ST + row * 128 + (((lq ^ (row & 7)) << 4));
            const size_t oa = (size_t)(row0 + row) * lda + st * 64 + lq * 8;
            cp_async16(sAh + d, Ah + oa);
            cp_async16(sAl + d, Al + oa);
        }
        #pragma unroll
        for (int i = 0; i < 4; ++i) {
            const int row = lm + i * 32;
            const uint32_t d = st * B_ST + row * 128 + (((lq ^ (row & 7)) << 4));
            const size_t ob = (size_t)(col0 + row) * 512 + st * 64 + lq * 8;
            cp_async16(sBh + d, Bh + ob);
            cp_async16(sBl + d, Bl + ob);
        }
        cp_commit();
    }

    #pragma unroll 1
    for (int t = 0; t < 8; ++t) {
        cp_wait1();
        __syncthreads();

        const uint32_t pAh = sAh + (t & 1) * A_ST;
        const uint32_t pAl = sAl + (t & 1) * A_ST;
        const uint32_t pBh = sBh + (t & 1) * B_ST;
        const uint32_t pBl = sBl + (t & 1) * B_ST;

        #pragma unroll
        for (int ks = 0; ks < 4; ++ks) {
            uint32_t ah[2][4], al[2][4];
            #pragma unroll
            for (int mf = 0; mf < 2; ++mf) {
                const uint32_t off = rbA[mf] + (((2 * ks + qaA) ^ s7A[mf]) << 4);
                ldm_x4(pAh + off, ah[mf][0], ah[mf][1], ah[mf][2], ah[mf][3]);
                ldm_x4(pAl + off, al[mf][0], al[mf][1], al[mf][2], al[mf][3]);
            }
            #pragma unroll
            for (int p = 0; p < 2; ++p) {
                uint32_t bh[2][2], bl[2][2];
                const uint32_t off = rbB[p] + (((2 * ks + qaB) ^ s7B[p]) << 4);
                ldm_x4(pBh + off, bh[0][0], bh[0][1], bh[1][0], bh[1][1]);
                ldm_x4(pBl + off, bl[0][0], bl[0][1], bl[1][0], bl[1][1]);
                #pragma unroll
                for (int mf = 0; mf < 2; ++mf)
                    #pragma unroll
                    for (int q = 0; q < 2; ++q) {
                        float* a_ = acc[mf][2 * p + q];
                        mma_f16(a_, ah[mf], bh[q]);
                        mma_f16(a_, ah[mf], bl[q]);
                        mma_f16(a_, al[mf], bh[q]);
                    }
            }
        }
        __syncthreads();
        if (t + 2 < 8) {
            const int st = t & 1;
            #pragma unroll
            for (int i = 0; i < 2; ++i) {
                const int row = lm + i * 32;
                const uint32_t d = st * A_ST + row * 128 + (((lq ^ (row & 7)) << 4));
                const size_t oa = (size_t)(row0 + row) * lda + (t + 2) * 64 + lq * 8;
                cp_async16(sAh + d, Ah + oa);
                cp_async16(sAl + d, Al + oa);
            }
            #pragma unroll
            for (int i = 0; i < 4; ++i) {
                const int row = lm + i * 32;
                const uint32_t d = st * B_ST + row * 128 + (((lq ^ (row & 7)) << 4));
                const size_t ob = (size_t)(col0 + row) * 512 + (t + 2) * 64 + lq * 8;
                cp_async16(sBh + d, Bh + ob);
                cp_async16(sBl + d, Bl + ob);
            }
        }
        cp_commit();
    }

    const int g  = lane >> 2;
    const int t4 = lane & 3;
    #pragma unroll
    for (int mf = 0; mf < 2; ++mf) {
        #pragma unroll
        for (int nf = 0; nf < 4; ++nf) {
            const int r1 = row0 + warp_m * 32 + mf * 16 + g;
            const int cc = col0 + warp_n * 32 + nf * 8 + t4 * 2;
            float d[4] = {acc[mf][nf][0], acc[mf][nf][1], acc[mf][nf][2], acc[mf][nf][3]};
            if (EPI != 0) {
                float b0 = __ldg(bias + cc), b1 = __ldg(bias + cc + 1);
                d[0] += b0; d[1] += b1; d[2] += b0; d[3] += b1;
                #pragma unroll
                for (int i = 0; i < 4; ++i) {
                    if (EPI == 1)      d[i] = d[i] > 0.f ? d[i] : 0.01f * d[i];
                    else if (EPI == 2) d[i] = tanhf(d[i]);
                }
            }
            if (EPI == 0 || EPI == 3) {
                *(float2*)(C + (size_t)r1 * N + cc)       = make_float2(d[0], d[1]);
                *(float2*)(C + (size_t)(r1 + 8) * N + cc) = make_float2(d[2], d[3]);
            } else {
                __half2 h, l;
                split2(d[0], d[1], h, l);
                *(__half2*)(Ch + (size_t)r1 * N + cc) = h;
                *(__half2*)(Cl + (size_t)r1 * N + cc) = l;
                split2(d[2], d[3], h, l);
                *(__half2*)(Ch + (size_t)(r1 + 8) * N + cc) = h;
                *(__half2*)(Cl + (size_t)(r1 + 8) * N + cc) = l;
            }
        }
    }
}

// ============================================================================
// weight prep (non-attention weights)
// ============================================================================
__constant__ int   c_which[16] = {0,1,2,3, 1,0,3,2, 2,3,0,1, 3,2,1,0};
__constant__ float c_sign [16] = {1.f,-1.f,-1.f,-1.f,
                                  1.f, 1.f, 1.f,-1.f,
                                  1.f,-1.f, 1.f, 1.f,
                                  1.f, 1.f,-1.f, 1.f};

__global__ void prep_weights(
    const float* __restrict__ W_in,  const float* __restrict__ W_dr,
    const float* __restrict__ W_hyp, const float* __restrict__ Wq_r,
    const float* __restrict__ Wq_i,  const float* __restrict__ Wq_j,
    const float* __restrict__ Wq_k,  const float* __restrict__ W_low,
    const float* __restrict__ W_high,const float* __restrict__ W_out,
    __half* __restrict__ oh, __half* __restrict__ ol)
{
    int idx = blockIdx.x * 256 + threadIdx.x;
    if (idx >= WTS_TOTAL) return;
    if (idx >= OFF_ATT && idx < OFF_WOUT) return;
    float v;
    if (idx < OFF_WDR) {
        int n = idx >> 9, k = idx & 511;
        v = W_in[(size_t)k * 4608 + n];
    } else if (idx < OFF_WHYP) {
        int r = idx - OFF_WDR, n = r >> 9, k = r & 511;
        v = W_dr[(size_t)k * 512 + n];
    } else if (idx < OFF_QUAT) {
        int r = idx - OFF_WHYP, n = r >> 9, k = r & 511;
        v = W_hyp[(size_t)k * 512 + n];
    } else if (idx < OFF_WAV) {
        int r = idx - OFF_QUAT, n = r >> 9, k = r & 511;
        int co = n >> 7, ho = n & 127, ci = k >> 7, hi = k & 127;
        const float* mats[4] = {Wq_r, Wq_i, Wq_j, Wq_k};
        int sel = co * 4 + ci;
        v = c_sign[sel] * mats[c_which[sel]][hi * 128 + ho];
    } else if (idx < OFF_ATT) {
        int r = idx - OFF_WAV, n = r >> 9, k = r & 511;
        int ho = n >> 1, po = n & 1, hi = k >> 1, pi = k & 1;
        float wl = W_low[hi * 256 + ho], wh = W_high[hi * 256 + ho];
        v = (pi == po) ? 0.5f * (wl + wh) : 0.5f * (wl - wh);
    } else {
        int r = idx - OFF_WOUT, n = r >> 9, k = r & 511;
        v = W_out[(size_t)k * 128 + n];
    }
    __half h = __float2half_rn(v);
    oh[idx] = h;
    ol[idx] = __float2half_rn(v - __half2float(h));
}

__global__ void combine_attn(const float* __restrict__ aWq, const float* __restrict__ aWk,
                             const float* __restrict__ aWv, const float* __restrict__ aWo,
                             __half* __restrict__ oh, __half* __restrict__ ol)
{
    __shared__ float As[16][17], Bs[16][17];
    const int z = blockIdx.z, l = z >> 1, type = z & 1;
    const int tx = threadIdx.x, ty = threadIdx.y;
    const size_t wl_off = (size_t)l * 262144;
    const float* Wq = aWq + wl_off;
    const float* Wk = aWk + wl_off;
    const float* Wv = aWv + wl_off;
    const float* Wo = aWo + wl_off;

    float acc = 0.f;
    for (int m0 = 0; m0 < 512; m0 += 16) {
        if (type == 0) {
            As[ty][tx] = Wk[(size_t)(blockIdx.y * 16 + ty) * 512 + m0 + tx];
            Bs[ty][tx] = Wq[(size_t)(blockIdx.x * 16 + ty) * 512 + m0 + tx];
        } else {
            As[ty][tx] = Wo[(size_t)(m0 + ty) * 512 + blockIdx.y * 16 + tx];
            Bs[ty][tx] = Wv[(size_t)(blockIdx.x * 16 + ty) * 512 + m0 + tx];
        }
        __syncthreads();
        if (type == 0) {
            #pragma unroll
            for (int h = 0; h < 16; ++h) acc += As[ty][h] * Bs[tx][h];
        } else {
            #pragma unroll
            for (int m = 0; m < 16; ++m) acc += Bs[tx][m] * As[m][ty];
        }
        __syncthreads();
    }
    const int n = blockIdx.y * 16 + ty;
    const int k = blockIdx.x * 16 + tx;
    const size_t o = (size_t)OFF_ATT + (size_t)z * 262144 + (size_t)n * 512 + k;
    __half h = __float2half_rn(acc);
    oh[o] = h;
    ol[o] = __float2half_rn(acc - __half2float(h));
}

__global__ void split_copy(const float4* __restrict__ in, __half* __restrict__ H,
                           __half* __restrict__ L, int n4)
{
    int i = blockIdx.x * 256 + threadIdx.x;
    if (i >= n4) return;
    float4 v = in[i];
    __half2 h, l;
    split2(v.x, v.y, h, l);
    ((__half2*)H)[2*i]   = h; ((__half2*)L)[2*i]   = l;
    split2(v.z, v.w, h, l);
    ((__half2*)H)[2*i+1] = h; ((__half2*)L)[2*i+1] = l;
}

// ============================================================================
// standalone agg (used once, after W_dr)
// ============================================================================
__global__ void agg_hl(const __half2* __restrict__ ih, const __half2* __restrict__ il,
                       __half2* __restrict__ oh, __half2* __restrict__ ol)
{
    int idx = blockIdx.x * 256 + threadIdx.x;
    const int TOT = B_SZ * NODES * 256;
    if (idx >= TOT) return;
    int h2 = idx & 255;
    int rn = (idx >> 8) % NODES;
    int b  = idx / (NODES * 256);
    size_t p = (size_t)(b * NODES + rn) * 256 + h2;
    __half2 xh = ih[p], xl = il[p];
    if (rn == 8) { oh[idx] = xh; ol[idx] = xl; return; }
    int src = (rn & 1) ? (rn >> 1) : (rn >> 1) + 4;
    size_t q = (size_t)(b * NODES + src) * 256 + h2;
    float2 fa = __half22float2(xh), fal = __half22float2(xl);
    float2 fc = __half22float2(ih[q]), fcl = __half22float2(il[q]);
    float v0 = 0.5f * ((fa.x + fal.x) + (fc.x + fcl.x));
    float v1 = 0.5f * ((fa.y + fal.y) + (fc.y + fcl.y));
    __half2 h, l;
    split2(v0, v1, h, l);
    oh[idx] = h; ol[idx] = l;
}

// ============================================================================
// fused attention + drnorm + residual + agg (layers 0,1); QV = ROWS x 1024
// 512 threads; uint4-vectorized hl conversion and output.
// ============================================================================
#define AF_SMEM (3 * NODES * H_SZ * 4 + 512)

__global__ __launch_bounds__(512)
void attn_fused(const float* __restrict__ QV,
                const __half* __restrict__ vh, const __half* __restrict__ vl,
                const float* __restrict__ gamma, const float* __restrict__ beta,
                __half* __restrict__ mh, __half* __restrict__ ml)
{
    extern __shared__ float sm[];
    float* sK = sm;                        // v (fp32)              9*512
    float* sV = sm + NODES * H_SZ;         // V                     9*512
    float* sQ = sm + 2 * NODES * H_SZ;     // Q, then ctx -> nf     9*512
    float* sS = sm + 3 * NODES * H_SZ;     // scores                96

    const int b   = blockIdx.x;
    const int tid = threadIdx.x;
    const int warp = tid >> 5, lane = tid & 31;
    const size_t base   = (size_t)b * NODES * H_SZ;
    const size_t baseQV = (size_t)b * NODES * 1024;

    // v pairs -> sK (fp32), 8 halves per task
    const uint4* Hv = (const uint4*)(vh + base);
    const uint4* Lv = (const uint4*)(vl + base);
    for (int i = tid; i < NODES * H_SZ / 8; i += 512) {
        uint4 hu = Hv[i], lu = Lv[i];
        const __half2* hp = (const __half2*)&hu;
        const __half2* lp = (const __half2*)&lu;
        float4 o0, o1;
        {
            float2 a = __half22float2(hp[0]), c = __half22float2(lp[0]);
            o0.x = a.x + c.x; o0.y = a.y + c.y;
            a = __half22float2(hp[1]); c = __half22float2(lp[1]);
            o0.z = a.x + c.x; o0.w = a.y + c.y;
            a = __half22float2(hp[2]); c = __half22float2(lp[2]);
            o1.x = a.x + c.x; o1.y = a.y + c.y;
            a = __half22float2(hp[3]); c = __half22float2(lp[3]);
            o1.z = a.x + c.x; o1.w = a.y + c.y;
        }
        ((float4*)sK)[2 * i]     = o0;
        ((float4*)sK)[2 * i + 1] = o1;
    }
    for (int i = tid; i < NODES * 128; i += 512) {
        int rn = i >> 7, c4 = i & 127;
        const float* row = QV + baseQV + (size_t)rn * 1024 + c4 * 4;
        ((float4*)sQ)[i] = *(const float4*)(row);
        ((float4*)sV)[i] = *(const float4*)(row + 512);
    }
    __syncthreads();

    const float scale = 0.044194173824159216f;   // 1/sqrt(512)
    for (int p = warp; p < 81; p += 16) {
        int q = p / 9, kk = p % 9;
        const float4* Q4 = (const float4*)(sQ + q * H_SZ);
        const float4* K4 = (const float4*)(sK + kk * H_SZ);
        float s = 0.f;
        #pragma unroll
        for (int h4 = 0; h4 < 4; ++h4) {
            float4 qv = Q4[lane + 32 * h4];
            float4 kv = K4[lane + 32 * h4];
            s += qv.x * kv.x + qv.y * kv.y + qv.z * kv.z + qv.w * kv.w;
        }
        #pragma unroll
        for (int o = 16; o; o >>= 1) s += __shfl_down_sync(0xffffffffu, s, o);
        if (lane == 0) sS[q * 9 + kk] = s * scale;
    }
    __syncthreads();

    if (tid < 9) {
        float mx = -1e30f;
        #pragma unroll
        for (int k = 0; k < 9; ++k) mx = fmaxf(mx, sS[tid * 9 + k]);
        float sum = 0.f;
        #pragma unroll
        for (int k = 0; k < 9; ++k) { float e = expf(sS[tid * 9 + k] - mx); sS[tid * 9 + k] = e; sum += e; }
        float inv = 1.f / sum;
        #pragma unroll
        for (int k = 0; k < 9; ++k) sS[tid * 9 + k] *= inv;
    }
    __syncthreads();

    // ctx -> sQ
    for (int i = tid; i < NODES * 128; i += 512) {
        int q = i >> 7, c4 = i & 127;
        const float* a = sS + q * 9;
        float4 acc = make_float4(0.f, 0.f, 0.f, 0.f);
        #pragma unroll
        for (int k = 0; k < 9; ++k) {
            float4 v = ((const float4*)(sV + k * H_SZ))[c4];
            float ak = a[k];
            acc.x = fmaf(ak, v.x, acc.x);
            acc.y = fmaf(ak, v.y, acc.y);
            acc.z = fmaf(ak, v.z, acc.z);
            acc.w = fmaf(ak, v.w, acc.w);
        }
        ((float4*)(sQ + q * H_SZ))[c4] = acc;
    }
    __syncthreads();

    // drnorm + residual per row (warps 0..8 active)
    for (int r = warp; r < 9; r += 16) {
        const float* o = sQ + r * H_SZ;
        float s = 0.f, sq = 0.f;
        #pragma unroll
        for (int i = 0; i < 16; ++i) {
            float v = o[lane + 32 * i];
            s += v; sq += v * v;
        }
        #pragma unroll
        for (int off = 16; off; off >>= 1) {
            s  += __shfl_down_sync(0xffffffffu, s, off);
            sq += __shfl_down_sync(0xffffffffu, sq, off);
        }
        float mu  = __shfl_sync(0xffffffffu, s,  0) * (1.f / 512.f);
        float msq = __shfl_sync(0xffffffffu, sq, 0) * (1.f / 512.f);
        float inv = rsqrtf(msq - mu * mu + 1e-5f);
        float* nf = sQ + r * H_SZ;
        const float* vres = sK + r * H_SZ;
        #pragma unroll
        for (int i = 0; i < 16; ++i) {
            int h = lane + 32 * i;
            nf[h] = vres[h] + __ldg(gamma + h) * (nf[h] - mu) * inv + __ldg(beta + h);
        }
    }
    __syncthreads();

    // agg + split -> (mh, ml), 8 cols per task
    uint4* OH = (uint4*)(mh + base);
    uint4* OL = (uint4*)(ml + base);
    for (int i = tid; i < NODES * H_SZ / 8; i += 512) {
        int c8 = i & 63;               // 8-col group within row
        int rn = i >> 6;
        float4 a0 = ((const float4*)(sQ + rn * H_SZ))[2 * c8];
        float4 a1 = ((const float4*)(sQ + rn * H_SZ))[2 * c8 + 1];
        if (rn != 8) {
            int src = (rn & 1) ? (rn >> 1) : (rn >> 1) + 4;
            float4 c0 = ((const float4*)(sQ + src * H_SZ))[2 * c8];
            float4 c1 = ((const float4*)(sQ + src * H_SZ))[2 * c8 + 1];
            a0.x = 0.5f * (a0.x + c0.x); a0.y = 0.5f * (a0.y + c0.y);
            a0.z = 0.5f * (a0.z + c0.z); a0.w = 0.5f * (a0.w + c0.w);
            a1.x = 0.5f * (a1.x + c1.x); a1.y = 0.5f * (a1.y + c1.y);
            a1.z = 0.5f * (a1.z + c1.z); a1.w = 0.5f * (a1.w + c1.w);
        }
        uint4 uh, ul;
        __half2* uhp = (__half2*)&uh;
        __half2* ulp = (__half2*)&ul;
        split2(a0.x, a0.y, uhp[0], ulp[0]);
        split2(a0.z, a0.w, uhp[1], ulp[1]);
        split2(a1.x, a1.y, uhp[2], ulp[2]);
        split2(a1.z, a1.w, uhp[3], ulp[3]);
        OH[i] = uh;
        OL[i] = ul;
    }
}

// ============================================================================
// last-layer attention (unchanged from R14)
// ============================================================================
#define AL_SMEM ((2 * NODES * H_SZ + H_SZ) * 4 + 512)

__global__ __launch_bounds__(256)
void attn_last(const float* __restrict__ V, const float* __restrict__ Q8,
               const __half* __restrict__ vh, const __half* __restrict__ vl,
               const float* __restrict__ gamma, const float* __restrict__ beta,
               __half* __restrict__ mh, __half* __restrict__ ml)
{
    extern __shared__ float sm[];
    float* sK = sm;
    float* sV = sm + NODES * H_SZ;
    float* sC = sm + 2 * NODES * H_SZ;
    float* sS = sm + 2 * NODES * H_SZ + H_SZ;

    const int b   = blockIdx.x;
    const int tid = threadIdx.x;
    const int warp = tid >> 5, lane = tid & 31;
    const size_t base = (size_t)b * NODES * H_SZ;

    const __half2* K2h = (const __half2*)(vh + base);
    const __half2* K2l = (const __half2*)(vl + base);
    for (int i = tid; i < NODES * H_SZ / 2; i += 256) {
        float2 h = __half22float2(K2h[i]);
        float2 l = __half22float2(K2l[i]);
        sK[2*i]   = h.x + l.x;
        sK[2*i+1] = h.y + l.y;
    }
    const float4* V4 = (const float4*)(V + base);
    for (int i = tid; i < NODES * H_SZ / 4; i += 256)
        ((float4*)sV)[i] = V4[i];
    if (tid < 128)
        ((float4*)sC)[tid] = ((const float4*)(Q8 + (size_t)b * H_SZ))[tid];
    __syncthreads();

    const float scale = 0.044194173824159216f;
    for (int kk = warp; kk < 9; kk += 8) {
        const float4* Q4 = (const float4*)sC;
        const float4* K4 = (const float4*)(sK + kk * H_SZ);
        float s = 0.f;
        #pragma unroll
        for (int h4 = 0; h4 < 4; ++h4) {
            float4 qv = Q4[lane + 32 * h4];
            float4 kv = K4[lane + 32 * h4];
            s += qv.x * kv.x + qv.y * kv.y + qv.z * kv.z + qv.w * kv.w;
        }
        #pragma unroll
        for (int o = 16; o; o >>= 1) s += __shfl_down_sync(0xffffffffu, s, o);
        if (lane == 0) sS[kk] = s * scale;
    }
    __syncthreads();

    if (tid == 0) {
        float mx = -1e30f;
        #pragma unroll
        for (int k = 0; k < 9; ++k) mx = fmaxf(mx, sS[k]);
        float sum = 0.f;
        #pragma unroll
        for (int k = 0; k < 9; ++k) { float e = expf(sS[k] - mx); sS[k] = e; sum += e; }
        float inv = 1.f / sum;
        #pragma unroll
        for (int k = 0; k < 9; ++k) sS[k] *= inv;
    }
    __syncthreads();

    if (tid < 128) {
        float4 acc = make_float4(0.f, 0.f, 0.f, 0.f);
        #pragma unroll
        for (int k = 0; k < 9; ++k) {
            float4 v = ((const float4*)(sV + k * H_SZ))[tid];
            float ak = sS[k];
            acc.x = fmaf(ak, v.x, acc.x);
            acc.y = fmaf(ak, v.y, acc.y);
            acc.z = fmaf(ak, v.z, acc.z);
            acc.w = fmaf(ak, v.w, acc.w);
        }
        ((float4*)sC)[tid] = acc;
    }
    __syncthreads();

    {
        float v1 = sC[tid], v2 = sC[tid + 256];
        float s = v1 + v2, sq = v1 * v1 + v2 * v2;
        #pragma unroll
        for (int o = 16; o; o >>= 1) {
            s  += __shfl_down_sync(0xffffffffu, s, o);
            sq += __shfl_down_sync(0xffffffffu, sq, o);
        }
        float* red = sS + 9;
        if (lane == 0) { red[warp] = s; red[warp + 8] = sq; }
        __syncthreads();
        if (tid == 0) {
            float S = 0.f, SQ = 0.f;
            #pragma unroll
            for (int w = 0; w < 8; ++w) { S += red[w]; SQ += red[w + 8]; }
            float mu = S * (1.f / 512.f);
            float var = SQ * (1.f / 512.f) - mu * mu;
            red[16] = mu;
            red[17] = rsqrtf(var + 1e-5f);
        }
        __syncthreads();
        float mu = red[16], inv = red[17];
        const float* vres = sK + 8 * H_SZ;
        __half2* oh = (__half2*)(mh + base + 8 * H_SZ);
        __half2* ol = (__half2*)(ml + base + 8 * H_SZ);
        float c0 = sC[2 * tid], c1 = sC[2 * tid + 1];
        float n0 = vres[2 * tid]     + __ldg(gamma + 2 * tid)     * (c0 - mu) * inv + __ldg(beta + 2 * tid);
        float n1 = vres[2 * tid + 1] + __ldg(gamma + 2 * tid + 1) * (c1 - mu) * inv + __ldg(beta + 2 * tid + 1);
        __half2 h, l;
        split2(n0, n1, h, l);
        oh[tid] = h;
        ol[tid] = l;
    }
}

// ============================================================================
// host orchestration
// ============================================================================
template<int EPI>
static void launch_hg(const __half* Ah, const __half* Al, const __half* Bh, const __half* Bl,
                      const float* bias, float* C, __half* Ch, __half* Cl,
                      int M, int N, int lda)
{
    cudaFuncSetAttribute(hgemm3<EPI>, cudaFuncAttributeMaxDynamicSharedMemorySize, HG_SMEM);
    dim3 grid(N / 128, M / 64);
    hgemm3<EPI><<<grid, 256, HG_SMEM>>>(Ah, Al, Bh, Bl, bias, C, Ch, Cl, N, lda);
}

struct Ptrs {
    __half *mh, *ml, *ah, *al, *nh, *nl, *xh, *xl, *wh, *wl;
    float *f;
};

static void run_attention(const Ptrs& P, int layer, const float* gamma, const float* beta)
{
    const size_t wb = OFF_ATT + (size_t)layer * 2 * 262144;
    launch_hg<0>(P.ah, P.al, P.wh + wb, P.wl + wb, nullptr, P.f, nullptr, nullptr, ROWS, 1024, 512);
    cudaFuncSetAttribute(attn_fused, cudaFuncAttributeMaxDynamicSharedMemorySize, AF_SMEM);
    attn_fused<<<B_SZ, 512, AF_SMEM>>>(P.f, P.ah, P.al, gamma, beta, P.mh, P.ml);
}

extern "C" void kernel_launch(void* const* d_in, const int* in_sizes, int n_in,
                              void* d_out, int out_size)
{
    const float* x      = (const float*)d_in[0];
    const float* W_in   = (const float*)d_in[1];
    const float* b_in   = (const float*)d_in[2];
    const float* W_dr   = (const float*)d_in[3];
    const float* b_dr   = (const float*)d_in[4];
    const float* W_hyp  = (const float*)d_in[5];
    const float* b_hyp  = (const float*)d_in[6];
    const float* Wq_r   = (const float*)d_in[7];
    const float* Wq_i   = (const float*)d_in[8];
    const float* Wq_j   = (const float*)d_in[9];
    const float* Wq_k   = (const float*)d_in[10];
    const float* b_quat = (const float*)d_in[11];
    const float* W_low  = (const float*)d_in[12];
    const float* W_high = (const float*)d_in[13];
    const float* b_wav  = (const float*)d_in[14];
    const float* aWq    = (const float*)d_in[15];
    const float* aWk    = (const float*)d_in[16];
    const float* aWv    = (const float*)d_in[17];
    const float* aWo    = (const float*)d_in[18];
    const float* gamma  = (const float*)d_in[19];
    const float* beta   = (const float*)d_in[20];
    const float* W_out  = (const float*)d_in[21];
    const float* b_out  = (const float*)d_in[22];
    float* out = (float*)d_out;

    Ptrs P;
    cudaGetSymbolAddress((void**)&P.mh, g_mh); cudaGetSymbolAddress((void**)&P.ml, g_ml);
    cudaGetSymbolAddress((void**)&P.ah, g_ah); cudaGetSymbolAddress((void**)&P.al, g_al);
    cudaGetSymbolAddress((void**)&P.nh, g_nh); cudaGetSymbolAddress((void**)&P.nl, g_nl);
    cudaGetSymbolAddress((void**)&P.xh, g_xh); cudaGetSymbolAddress((void**)&P.xl, g_xl);
    cudaGetSymbolAddress((void**)&P.wh, g_wh); cudaGetSymbolAddress((void**)&P.wl, g_wl);
    cudaGetSymbolAddress((void**)&P.f,  g_f);

    prep_weights<<<(WTS_TOTAL + 255) / 256, 256>>>(
        W_in, W_dr, W_hyp, Wq_r, Wq_i, Wq_j, Wq_k, W_low, W_high, W_out, P.wh, P.wl);
    split_copy<<<(B_SZ * H_SZ / 4 + 255) / 256, 256>>>((const float4*)x, P.xh, P.xl, B_SZ * H_SZ / 4);

    const int AGG_BLOCKS = (B_SZ * NODES * 256 + 255) / 256;

    launch_hg<1>(P.xh, P.xl, P.wh + OFF_WIN, P.wl + OFF_WIN, b_in, nullptr, P.mh, P.ml, B_SZ, 4608, 512);
    launch_hg<2>(P.mh, P.ml, P.wh + OFF_WDR, P.wl + OFF_WDR, b_dr, nullptr, P.nh, P.nl, ROWS, 512, 512);
    agg_hl<<<AGG_BLOCKS, 256>>>((const __half2*)P.nh, (const __half2*)P.nl, (__half2*)P.mh, (__half2*)P.ml);
    launch_hg<2>(P.mh, P.ml, P.wh + OFF_WHYP, P.wl + OFF_WHYP, b_hyp, nullptr, P.ah, P.al, ROWS, 512, 512);

    combine_attn<<<dim3(32, 32, 6), dim3(16, 16)>>>(aWq, aWk, aWv, aWo, P.wh, P.wl);

    run_attention(P, 0, gamma, beta);
    launch_hg<2>(P.mh, P.ml, P.wh + OFF_QUAT, P.wl + OFF_QUAT, b_quat, nullptr, P.ah, P.al, ROWS, 512, 512);

    run_attention(P, 1, gamma + 512, beta + 512);
    launch_hg<2>(P.mh, P.ml, P.wh + OFF_WAV, P.wl + OFF_WAV, b_wav, nullptr, P.ah, P.al, ROWS, 512, 512);

    // ---- last layer: VO full + QK on node-8 rows only + attn_last ----
    {
        const size_t wb = OFF_ATT + (size_t)2 * 2 * 262144;
        launch_hg<0>(P.ah, P.al, P.wh + wb + 262144, P.wl + wb + 262144,
                     nullptr, P.f, nullptr, nullptr, ROWS, 512, 512);
        launch_hg<0>(P.ah + 8 * H_SZ, P.al + 8 * H_SZ, P.wh + wb, P.wl + wb,
                     nullptr, P.f + BH, nullptr, nullptr, B_SZ, 512, NODES * H_SZ);
        cudaFuncSetAttribute(attn_last, cudaFuncAttributeMaxDynamicSharedMemorySize, AL_SMEM);
        attn_last<<<B_SZ, 256, AL_SMEM>>>(P.f, P.f + BH, P.ah, P.al,
                                          gamma + 1024, beta + 1024, P.mh, P.ml);
    }

    launch_hg<3>(P.mh + 8 * H_SZ, P.ml + 8 * H_SZ, P.wh + OFF_WOUT, P.wl + OFF_WOUT,
                 b_out, out, nullptr, nullptr, B_SZ, 128, NODES * H_SZ);
}

// round 16
// speedup vs baseline: 1.3986x; 1.1261x over previous
#include <cuda_runtime.h>
#include <cuda_fp16.h>
#include <math.h>
#include <stdint.h>

#define B_SZ   16384
#define H_SZ   512
#define NODES  9
#define ROWS   (B_SZ * NODES)         // 147456
#define BH     (ROWS * H_SZ)          // 75497472

// ---------------- scratch (device globals; no allocation) ----------------
__device__ __half g_mh[BH], g_ml[BH];
__device__ __half g_ah[BH], g_al[BH];
__device__ __half g_nh[BH], g_nl[BH];
__device__ __half g_xh[B_SZ * H_SZ], g_xl[B_SZ * H_SZ];
__device__ float  g_f[2ull * BH];

// weights [N,K] K-major, K=512, hi/lo half pairs
#define OFF_WIN   0                    // 4608*512
#define OFF_WDR   2359296
#define OFF_WHYP  2621440
#define OFF_QUAT  2883584
#define OFF_WAV   3145728
#define OFF_ATT   3407872              // per layer: {Bt_qk, Bt_vo} contiguous (1024x512)
#define OFF_WOUT  6553600              // 128*512
#define WTS_TOTAL 6619136
__device__ __half g_wh[WTS_TOTAL], g_wl[WTS_TOTAL];

// ============================================================================
// helpers
// ============================================================================
__device__ __forceinline__ uint32_t smem_u32(const void* p) {
    uint32_t a;
    asm("{ .reg .u64 t; cvta.to.shared.u64 t, %1; cvt.u32.u64 %0, t; }" : "=r"(a) : "l"(p));
    return a;
}
__device__ __forceinline__ void cp_async16(uint32_t dst, const void* src) {
    asm volatile("cp.async.cg.shared.global [%0], [%1], 16;" :: "r"(dst), "l"(src) : "memory");
}
__device__ __forceinline__ void cp_commit() {
    asm volatile("cp.async.commit_group;" ::: "memory");
}
__device__ __forceinline__ void cp_wait1() {
    asm volatile("cp.async.wait_group 1;" ::: "memory");
}
__device__ __forceinline__ void ldm_x4(uint32_t addr, uint32_t& r0, uint32_t& r1,
                                       uint32_t& r2, uint32_t& r3) {
    asm volatile("ldmatrix.sync.aligned.m8n8.x4.shared.b16 {%0,%1,%2,%3}, [%4];"
                 : "=r"(r0), "=r"(r1), "=r"(r2), "=r"(r3) : "r"(addr));
}
__device__ __forceinline__ void mma_f16(float* c, const uint32_t* a, const uint32_t* b) {
    asm volatile(
        "mma.sync.aligned.m16n8k16.row.col.f32.f16.f16.f32 "
        "{%0,%1,%2,%3}, {%4,%5,%6,%7}, {%8,%9}, {%0,%1,%2,%3};"
        : "+f"(c[0]), "+f"(c[1]), "+f"(c[2]), "+f"(c[3])
        : "r"(a[0]), "r"(a[1]), "r"(a[2]), "r"(a[3]), "r"(b[0]), "r"(b[1]));
}
__device__ __forceinline__ void split2(float d0, float d1, __half2& h, __half2& l) {
    __half h0 = __float2half_rn(d0), h1 = __float2half_rn(d1);
    h = __halves2half2(h0, h1);
    l = __floats2half2_rn(d0 - __half2float(h0), d1 - __half2float(h1));
}

// ============================================================================
// fp16 GEMM: C[M,N] = A[M,512] @ Bt[N,512]^T
// TERMS=3: (Ah+Al)(Bh+Bl) minus ll;  TERMS=2: (Ah+Al)·Bh  (weight-lo dropped)
// EPI: 0 fp32 C; 1 bias+lrelu -> HL; 2 bias+tanh -> HL; 3 bias -> fp32
// BM=64, BN=128, 256 thr, 8 warps (2x4), warp 32x32, 2-stage, 2 CTAs/SM
// ============================================================================
#define A_ST 8192
#define B_ST 16384
#define HG_SMEM3 (2 * (2 * A_ST + 2 * B_ST) + 1024)
#define HG_SMEM2 (2 * (2 * A_ST + B_ST) + 1024)

template<int EPI, int TERMS>
__global__ __launch_bounds__(256, 2)
void hgemm3(const __half* __restrict__ Ah, const __half* __restrict__ Al,
            const __half* __restrict__ Bh, const __half* __restrict__ Bl,
            const float* __restrict__ bias, float* __restrict__ C,
            __half* __restrict__ Ch, __half* __restrict__ Cl,
            int N, int lda)
{
    extern __shared__ char smraw[];
    const uint32_t base = (smem_u32(smraw) + 1023) & ~1023u;
    const uint32_t sAh = base;
    const uint32_t sAl = base + 2 * A_ST;
    const uint32_t sBh = base + 4 * A_ST;
    const uint32_t sBl = base + 4 * A_ST + 2 * B_ST;   // unused when TERMS==2

    const int col0 = blockIdx.x * 128;
    const int row0 = blockIdx.y * 64;

    const int tid    = threadIdx.x;
    const int lane   = tid & 31;
    const int wid    = tid >> 5;
    const int warp_m = wid >> 2;
    const int warp_n = wid & 3;

    const int lm = tid >> 3;
    const int lq = tid & 7;

    const int mat = lane >> 3;
    const int mr  = lane & 7;
    int rbA[2], s7A[2];
    #pragma unroll
    for (int mf = 0; mf < 2; ++mf) {
        int m = warp_m * 32 + mf * 16 + (mat & 1) * 8 + mr;
        rbA[mf] = m * 128; s7A[mf] = m & 7;
    }
    const int qaA = mat >> 1;
    int rbB[2], s7B[2];
    #pragma unroll
    for (int p = 0; p < 2; ++p) {
        int n = warp_n * 32 + (2 * p + (mat >> 1)) * 8 + mr;
        rbB[p] = n * 128; s7B[p] = n & 7;
    }
    const int qaB = mat & 1;

    float acc[2][4][4];
    #pragma unroll
    for (int i = 0; i < 2; ++i)
        #pragma unroll
        for (int j = 0; j < 4; ++j)
            #pragma unroll
            for (int k = 0; k < 4; ++k) acc[i][j][k] = 0.f;

    #pragma unroll
    for (int st = 0; st < 2; ++st) {
        #pragma unroll
        for (int i = 0; i < 2; ++i) {
            const int row = lm + i * 32;
            const uint32_t d = st * A_ST + row * 128 + (((lq ^ (row & 7)) << 4));
            const size_t oa = (size_t)(row0 + row) * lda + st * 64 + lq * 8;
            cp_async16(sAh + d, Ah + oa);
            cp_async16(sAl + d, Al + oa);
        }
        #pragma unroll
        for (int i = 0; i < 4; ++i) {
            const int row = lm + i * 32;
            const uint32_t d = st * B_ST + row * 128 + (((lq ^ (row & 7)) << 4));
            const size_t ob = (size_t)(col0 + row) * 512 + st * 64 + lq * 8;
            cp_async16(sBh + d, Bh + ob);
            if (TERMS == 3) cp_async16(sBl + d, Bl + ob);
        }
        cp_commit();
    }

    #pragma unroll 1
    for (int t = 0; t < 8; ++t) {
        cp_wait1();
        __syncthreads();

        const uint32_t pAh = sAh + (t & 1) * A_ST;
        const uint32_t pAl = sAl + (t & 1) * A_ST;
        const uint32_t pBh = sBh + (t & 1) * B_ST;
        const uint32_t pBl = sBl + (t & 1) * B_ST;

        #pragma unroll
        for (int ks = 0; ks < 4; ++ks) {
            uint32_t ah[2][4], al[2][4];
            #pragma unroll
            for (int mf = 0; mf < 2; ++mf) {
                const uint32_t off = rbA[mf] + (((2 * ks + qaA) ^ s7A[mf]) << 4);
                ldm_x4(pAh + off, ah[mf][0], ah[mf][1], ah[mf][2], ah[mf][3]);
                ldm_x4(pAl + off, al[mf][0], al[mf][1], al[mf][2], al[mf][3]);
            }
            #pragma unroll
            for (int p = 0; p < 2; ++p) {
                uint32_t bh[2][2], bl[2][2];
                const uint32_t off = rbB[p] + (((2 * ks + qaB) ^ s7B[p]) << 4);
                ldm_x4(pBh + off, bh[0][0], bh[0][1], bh[1][0], bh[1][1]);
                if (TERMS == 3)
                    ldm_x4(pBl + off, bl[0][0], bl[0][1], bl[1][0], bl[1][1]);
                #pragma unroll
                for (int mf = 0; mf < 2; ++mf)
                    #pragma unroll
                    for (int q = 0; q < 2; ++q) {
                        float* a_ = acc[mf][2 * p + q];
                        mma_f16(a_, ah[mf], bh[q]);
                        if (TERMS == 3) mma_f16(a_, ah[mf], bl[q]);
                        mma_f16(a_, al[mf], bh[q]);
                    }
            }
        }
        __syncthreads();
        if (t + 2 < 8) {
            const int st = t & 1;
            #pragma unroll
            for (int i = 0; i < 2; ++i) {
                const int row = lm + i * 32;
                const uint32_t d = st * A_ST + row * 128 + (((lq ^ (row & 7)) << 4));
                const size_t oa = (size_t)(row0 + row) * lda + (t + 2) * 64 + lq * 8;
                cp_async16(sAh + d, Ah + oa);
                cp_async16(sAl + d, Al + oa);
            }
            #pragma unroll
            for (int i = 0; i < 4; ++i) {
                const int row = lm + i * 32;
                const uint32_t d = st * B_ST + row * 128 + (((lq ^ (row & 7)) << 4));
                const size_t ob = (size_t)(col0 + row) * 512 + (t + 2) * 64 + lq * 8;
                cp_async16(sBh + d, Bh + ob);
                if (TERMS == 3) cp_async16(sBl + d, Bl + ob);
            }
        }
        cp_commit();
    }

    const int g  = lane >> 2;
    const int t4 = lane & 3;
    #pragma unroll
    for (int mf = 0; mf < 2; ++mf) {
        #pragma unroll
        for (int nf = 0; nf < 4; ++nf) {
            const int r1 = row0 + warp_m * 32 + mf * 16 + g;
            const int cc = col0 + warp_n * 32 + nf * 8 + t4 * 2;
            float d[4] = {acc[mf][nf][0], acc[mf][nf][1], acc[mf][nf][2], acc[mf][nf][3]};
            if (EPI != 0) {
                float b0 = __ldg(bias + cc), b1 = __ldg(bias + cc + 1);
                d[0] += b0; d[1] += b1; d[2] += b0; d[3] += b1;
                #pragma unroll
                for (int i = 0; i < 4; ++i) {
                    if (EPI == 1)      d[i] = d[i] > 0.f ? d[i] : 0.01f * d[i];
                    else if (EPI == 2) d[i] = tanhf(d[i]);
                }
            }
            if (EPI == 0 || EPI == 3) {
                *(float2*)(C + (size_t)r1 * N + cc)       = make_float2(d[0], d[1]);
                *(float2*)(C + (size_t)(r1 + 8) * N + cc) = make_float2(d[2], d[3]);
            } else {
                __half2 h, l;
                split2(d[0], d[1], h, l);
                *(__half2*)(Ch + (size_t)r1 * N + cc) = h;
                *(__half2*)(Cl + (size_t)r1 * N + cc) = l;
                split2(d[2], d[3], h, l);
                *(__half2*)(Ch + (size_t)(r1 + 8) * N + cc) = h;
                *(__half2*)(Cl + (size_t)(r1 + 8) * N + cc) = l;
            }
        }
    }
}

// ============================================================================
// weight prep (non-attention weights)
// ============================================================================
__constant__ int   c_which[16] = {0,1,2,3, 1,0,3,2, 2,3,0,1, 3,2,1,0};
__constant__ float c_sign [16] = {1.f,-1.f,-1.f,-1.f,
                                  1.f, 1.f, 1.f,-1.f,
                                  1.f,-1.f, 1.f, 1.f,
                                  1.f, 1.f,-1.f, 1.f};

__global__ void prep_weights(
    const float* __restrict__ W_in,  const float* __restrict__ W_dr,
    const float* __restrict__ W_hyp, const float* __restrict__ Wq_r,
    const float* __restrict__ Wq_i,  const float* __restrict__ Wq_j,
    const float* __restrict__ Wq_k,  const float* __restrict__ W_low,
    const float* __restrict__ W_high,const float* __restrict__ W_out,
    __half* __restrict__ oh, __half* __restrict__ ol)
{
    int idx = blockIdx.x * 256 + threadIdx.x;
    if (idx >= WTS_TOTAL) return;
    if (idx >= OFF_ATT && idx < OFF_WOUT) return;
    float v;
    if (idx < OFF_WDR) {
        int n = idx >> 9, k = idx & 511;
        v = W_in[(size_t)k * 4608 + n];
    } else if (idx < OFF_WHYP) {
        int r = idx - OFF_WDR, n = r >> 9, k = r & 511;
        v = W_dr[(size_t)k * 512 + n];
    } else if (idx < OFF_QUAT) {
        int r = idx - OFF_WHYP, n = r >> 9, k = r & 511;
        v = W_hyp[(size_t)k * 512 + n];
    } else if (idx < OFF_WAV) {
        int r = idx - OFF_QUAT, n = r >> 9, k = r & 511;
        int co = n >> 7, ho = n & 127, ci = k >> 7, hi = k & 127;
        const float* mats[4] = {Wq_r, Wq_i, Wq_j, Wq_k};
        int sel = co * 4 + ci;
        v = c_sign[sel] * mats[c_which[sel]][hi * 128 + ho];
    } else if (idx < OFF_ATT) {
        int r = idx - OFF_WAV, n = r >> 9, k = r & 511;
        int ho = n >> 1, po = n & 1, hi = k >> 1, pi = k & 1;
        float wl = W_low[hi * 256 + ho], wh = W_high[hi * 256 + ho];
        v = (pi == po) ? 0.5f * (wl + wh) : 0.5f * (wl - wh);
    } else {
        int r = idx - OFF_WOUT, n = r >> 9, k = r & 511;
        v = W_out[(size_t)k * 128 + n];
    }
    __half h = __float2half_rn(v);
    oh[idx] = h;
    ol[idx] = __float2half_rn(v - __half2float(h));
}

__global__ void combine_attn(const float* __restrict__ aWq, const float* __restrict__ aWk,
                             const float* __restrict__ aWv, const float* __restrict__ aWo,
                             __half* __restrict__ oh, __half* __restrict__ ol)
{
    __shared__ float As[16][17], Bs[16][17];
    const int z = blockIdx.z, l = z >> 1, type = z & 1;
    const int tx = threadIdx.x, ty = threadIdx.y;
    const size_t wl_off = (size_t)l * 262144;
    const float* Wq = aWq + wl_off;
    const float* Wk = aWk + wl_off;
    const float* Wv = aWv + wl_off;
    const float* Wo = aWo + wl_off;

    float acc = 0.f;
    for (int m0 = 0; m0 < 512; m0 += 16) {
        if (type == 0) {
            As[ty][tx] = Wk[(size_t)(blockIdx.y * 16 + ty) * 512 + m0 + tx];
            Bs[ty][tx] = Wq[(size_t)(blockIdx.x * 16 + ty) * 512 + m0 + tx];
        } else {
            As[ty][tx] = Wo[(size_t)(m0 + ty) * 512 + blockIdx.y * 16 + tx];
            Bs[ty][tx] = Wv[(size_t)(blockIdx.x * 16 + ty) * 512 + m0 + tx];
        }
        __syncthreads();
        if (type == 0) {
            #pragma unroll
            for (int h = 0; h < 16; ++h) acc += As[ty][h] * Bs[tx][h];
        } else {
            #pragma unroll
            for (int m = 0; m < 16; ++m) acc += Bs[tx][m] * As[m][ty];
        }
        __syncthreads();
    }
    const int n = blockIdx.y * 16 + ty;
    const int k = blockIdx.x * 16 + tx;
    const size_t o = (size_t)OFF_ATT + (size_t)z * 262144 + (size_t)n * 512 + k;
    __half h = __float2half_rn(acc);
    oh[o] = h;
    ol[o] = __float2half_rn(acc - __half2float(h));
}

__global__ void split_copy(const float4* __restrict__ in, __half* __restrict__ H,
                           __half* __restrict__ L, int n4)
{
    int i = blockIdx.x * 256 + threadIdx.x;
    if (i >= n4) return;
    float4 v = in[i];
    __half2 h, l;
    split2(v.x, v.y, h, l);
    ((__half2*)H)[2*i]   = h; ((__half2*)L)[2*i]   = l;
    split2(v.z, v.w, h, l);
    ((__half2*)H)[2*i+1] = h; ((__half2*)L)[2*i+1] = l;
}

// ============================================================================
// standalone agg (used once, after W_dr)
// ============================================================================
__global__ void agg_hl(const __half2* __restrict__ ih, const __half2* __restrict__ il,
                       __half2* __restrict__ oh, __half2* __restrict__ ol)
{
    int idx = blockIdx.x * 256 + threadIdx.x;
    const int TOT = B_SZ * NODES * 256;
    if (idx >= TOT) return;
    int h2 = idx & 255;
    int rn = (idx >> 8) % NODES;
    int b  = idx / (NODES * 256);
    size_t p = (size_t)(b * NODES + rn) * 256 + h2;
    __half2 xh = ih[p], xl = il[p];
    if (rn == 8) { oh[idx] = xh; ol[idx] = xl; return; }
    int src = (rn & 1) ? (rn >> 1) : (rn >> 1) + 4;
    size_t q = (size_t)(b * NODES + src) * 256 + h2;
    float2 fa = __half22float2(xh), fal = __half22float2(xl);
    float2 fc = __half22float2(ih[q]), fcl = __half22float2(il[q]);
    float v0 = 0.5f * ((fa.x + fal.x) + (fc.x + fcl.x));
    float v1 = 0.5f * ((fa.y + fal.y) + (fc.y + fcl.y));
    __half2 h, l;
    split2(v0, v1, h, l);
    oh[idx] = h; ol[idx] = l;
}

// ============================================================================
// fused attention + drnorm + residual + agg (layers 0,1); QV = ROWS x 1024
// ============================================================================
#define AF_SMEM (3 * NODES * H_SZ * 4 + 512)

__global__ __launch_bounds__(512)
void attn_fused(const float* __restrict__ QV,
                const __half* __restrict__ vh, const __half* __restrict__ vl,
                const float* __restrict__ gamma, const float* __restrict__ beta,
                __half* __restrict__ mh, __half* __restrict__ ml)
{
    extern __shared__ float sm[];
    float* sK = sm;
    float* sV = sm + NODES * H_SZ;
    float* sQ = sm + 2 * NODES * H_SZ;
    float* sS = sm + 3 * NODES * H_SZ;

    const int b   = blockIdx.x;
    const int tid = threadIdx.x;
    const int warp = tid >> 5, lane = tid & 31;
    const size_t base   = (size_t)b * NODES * H_SZ;
    const size_t baseQV = (size_t)b * NODES * 1024;

    const uint4* Hv = (const uint4*)(vh + base);
    const uint4* Lv = (const uint4*)(vl + base);
    for (int i = tid; i < NODES * H_SZ / 8; i += 512) {
        uint4 hu = Hv[i], lu = Lv[i];
        const __half2* hp = (const __half2*)&hu;
        const __half2* lp = (const __half2*)&lu;
        float4 o0, o1;
        {
            float2 a = __half22float2(hp[0]), c = __half22float2(lp[0]);
            o0.x = a.x + c.x; o0.y = a.y + c.y;
            a = __half22float2(hp[1]); c = __half22float2(lp[1]);
            o0.z = a.x + c.x; o0.w = a.y + c.y;
            a = __half22float2(hp[2]); c = __half22float2(lp[2]);
            o1.x = a.x + c.x; o1.y = a.y + c.y;
            a = __half22float2(hp[3]); c = __half22float2(lp[3]);
            o1.z = a.x + c.x; o1.w = a.y + c.y;
        }
        ((float4*)sK)[2 * i]     = o0;
        ((float4*)sK)[2 * i + 1] = o1;
    }
    for (int i = tid; i < NODES * 128; i += 512) {
        int rn = i >> 7, c4 = i & 127;
        const float* row = QV + baseQV + (size_t)rn * 1024 + c4 * 4;
        ((float4*)sQ)[i] = *(const float4*)(row);
        ((float4*)sV)[i] = *(const float4*)(row + 512);
    }
    __syncthreads();

    const float scale = 0.044194173824159216f;
    for (int p = warp; p < 81; p += 16) {
        int q = p / 9, kk = p % 9;
        const float4* Q4 = (const float4*)(sQ + q * H_SZ);
        const float4* K4 = (const float4*)(sK + kk * H_SZ);
        float s = 0.f;
        #pragma unroll
        for (int h4 = 0; h4 < 4; ++h4) {
            float4 qv = Q4[lane + 32 * h4];
            float4 kv = K4[lane + 32 * h4];
            s += qv.x * kv.x + qv.y * kv.y + qv.z * kv.z + qv.w * kv.w;
        }
        #pragma unroll
        for (int o = 16; o; o >>= 1) s += __shfl_down_sync(0xffffffffu, s, o);
        if (lane == 0) sS[q * 9 + kk] = s * scale;
    }
    __syncthreads();

    if (tid < 9) {
        float mx = -1e30f;
        #pragma unroll
        for (int k = 0; k < 9; ++k) mx = fmaxf(mx, sS[tid * 9 + k]);
        float sum = 0.f;
        #pragma unroll
        for (int k = 0; k < 9; ++k) { float e = expf(sS[tid * 9 + k] - mx); sS[tid * 9 + k] = e; sum += e; }
        float inv = 1.f / sum;
        #pragma unroll
        for (int k = 0; k < 9; ++k) sS[tid * 9 + k] *= inv;
    }
    __syncthreads();

    for (int i = tid; i < NODES * 128; i += 512) {
        int q = i >> 7, c4 = i & 127;
        const float* a = sS + q * 9;
        float4 acc = make_float4(0.f, 0.f, 0.f, 0.f);
        #pragma unroll
        for (int k = 0; k < 9; ++k) {
            float4 v = ((const float4*)(sV + k * H_SZ))[c4];
            float ak = a[k];
            acc.x = fmaf(ak, v.x, acc.x);
            acc.y = fmaf(ak, v.y, acc.y);
            acc.z = fmaf(ak, v.z, acc.z);
            acc.w = fmaf(ak, v.w, acc.w);
        }
        ((float4*)(sQ + q * H_SZ))[c4] = acc;
    }
    __syncthreads();

    for (int r = warp; r < 9; r += 16) {
        const float* o = sQ + r * H_SZ;
        float s = 0.f, sq = 0.f;
        #pragma unroll
        for (int i = 0; i < 16; ++i) {
            float v = o[lane + 32 * i];
            s += v; sq += v * v;
        }
        #pragma unroll
        for (int off = 16; off; off >>= 1) {
            s  += __shfl_down_sync(0xffffffffu, s, off);
            sq += __shfl_down_sync(0xffffffffu, sq, off);
        }
        float mu  = __shfl_sync(0xffffffffu, s,  0) * (1.f / 512.f);
        float msq = __shfl_sync(0xffffffffu, sq, 0) * (1.f / 512.f);
        float inv = rsqrtf(msq - mu * mu + 1e-5f);
        float* nf = sQ + r * H_SZ;
        const float* vres = sK + r * H_SZ;
        #pragma unroll
        for (int i = 0; i < 16; ++i) {
            int h = lane + 32 * i;
            nf[h] = vres[h] + __ldg(gamma + h) * (nf[h] - mu) * inv + __ldg(beta + h);
        }
    }
    __syncthreads();

    uint4* OH = (uint4*)(mh + base);
    uint4* OL = (uint4*)(ml + base);
    for (int i = tid; i < NODES * H_SZ / 8; i += 512) {
        int c8 = i & 63;
        int rn = i >> 6;
        float4 a0 = ((const float4*)(sQ + rn * H_SZ))[2 * c8];
        float4 a1 = ((const float4*)(sQ + rn * H_SZ))[2 * c8 + 1];
        if (rn != 8) {
            int src = (rn & 1) ? (rn >> 1) : (rn >> 1) + 4;
            float4 c0 = ((const float4*)(sQ + src * H_SZ))[2 * c8];
            float4 c1 = ((const float4*)(sQ + src * H_SZ))[2 * c8 + 1];
            a0.x = 0.5f * (a0.x + c0.x); a0.y = 0.5f * (a0.y + c0.y);
            a0.z = 0.5f * (a0.z + c0.z); a0.w = 0.5f * (a0.w + c0.w);
            a1.x = 0.5f * (a1.x + c1.x); a1.y = 0.5f * (a1.y + c1.y);
            a1.z = 0.5f * (a1.z + c1.z); a1.w = 0.5f * (a1.w + c1.w);
        }
        uint4 uh, ul;
        __half2* uhp = (__half2*)&uh;
        __half2* ulp = (__half2*)&ul;
        split2(a0.x, a0.y, uhp[0], ulp[0]);
        split2(a0.z, a0.w, uhp[1], ulp[1]);
        split2(a1.x, a1.y, uhp[2], ulp[2]);
        split2(a1.z, a1.w, uhp[3], ulp[3]);
        OH[i] = uh;
        OL[i] = ul;
    }
}

// ============================================================================
// last-layer attention (unchanged)
// ============================================================================
#define AL_SMEM ((2 * NODES * H_SZ + H_SZ) * 4 + 512)

__global__ __launch_bounds__(256)
void attn_last(const float* __restrict__ V, const float* __restrict__ Q8,
               const __half* __restrict__ vh, const __half* __restrict__ vl,
               const float* __restrict__ gamma, const float* __restrict__ beta,
               __half* __restrict__ mh, __half* __restrict__ ml)
{
    extern __shared__ float sm[];
    float* sK = sm;
    float* sV = sm + NODES * H_SZ;
    float* sC = sm + 2 * NODES * H_SZ;
    float* sS = sm + 2 * NODES * H_SZ + H_SZ;

    const int b   = blockIdx.x;
    const int tid = threadIdx.x;
    const int warp = tid >> 5, lane = tid & 31;
    const size_t base = (size_t)b * NODES * H_SZ;

    const __half2* K2h = (const __half2*)(vh + base);
    const __half2* K2l = (const __half2*)(vl + base);
    for (int i = tid; i < NODES * H_SZ / 2; i += 256) {
        float2 h = __half22float2(K2h[i]);
        float2 l = __half22float2(K2l[i]);
        sK[2*i]   = h.x + l.x;
        sK[2*i+1] = h.y + l.y;
    }
    const float4* V4 = (const float4*)(V + base);
    for (int i = tid; i < NODES * H_SZ / 4; i += 256)
        ((float4*)sV)[i] = V4[i];
    if (tid < 128)
        ((float4*)sC)[tid] = ((const float4*)(Q8 + (size_t)b * H_SZ))[tid];
    __syncthreads();

    const float scale = 0.044194173824159216f;
    for (int kk = warp; kk < 9; kk += 8) {
        const float4* Q4 = (const float4*)sC;
        const float4* K4 = (const float4*)(sK + kk * H_SZ);
        float s = 0.f;
        #pragma unroll
        for (int h4 = 0; h4 < 4; ++h4) {
            float4 qv = Q4[lane + 32 * h4];
            float4 kv = K4[lane + 32 * h4];
            s += qv.x * kv.x + qv.y * kv.y + qv.z * kv.z + qv.w * kv.w;
        }
        #pragma unroll
        for (int o = 16; o; o >>= 1) s += __shfl_down_sync(0xffffffffu, s, o);
        if (lane == 0) sS[kk] = s * scale;
    }
    __syncthreads();

    if (tid == 0) {
        float mx = -1e30f;
        #pragma unroll
        for (int k = 0; k < 9; ++k) mx = fmaxf(mx, sS[k]);
        float sum = 0.f;
        #pragma unroll
        for (int k = 0; k < 9; ++k) { float e = expf(sS[k] - mx); sS[k] = e; sum += e; }
        float inv = 1.f / sum;
        #pragma unroll
        for (int k = 0; k < 9; ++k) sS[k] *= inv;
    }
    __syncthreads();

    if (tid < 128) {
        float4 acc = make_float4(0.f, 0.f, 0.f, 0.f);
        #pragma unroll
        for (int k = 0; k < 9; ++k) {
            float4 v = ((const float4*)(sV + k * H_SZ))[tid];
            float ak = sS[k];
            acc.x = fmaf(ak, v.x, acc.x);
            acc.y = fmaf(ak, v.y, acc.y);
            acc.z = fmaf(ak, v.z, acc.z);
            acc.w = fmaf(ak, v.w, acc.w);
        }
        ((float4*)sC)[tid] = acc;
    }
    __syncthreads();

    {
        float v1 = sC[tid], v2 = sC[tid + 256];
        float s = v1 + v2, sq = v1 * v1 + v2 * v2;
        #pragma unroll
        for (int o = 16; o; o >>= 1) {
            s  += __shfl_down_sync(0xffffffffu, s, o);
            sq += __shfl_down_sync(0xffffffffu, sq, o);
        }
        float* red = sS + 9;
        if (lane == 0) { red[warp] = s; red[warp + 8] = sq; }
        __syncthreads();
        if (tid == 0) {
            float S = 0.f, SQ = 0.f;
            #pragma unroll
            for (int w = 0; w < 8; ++w) { S += red[w]; SQ += red[w + 8]; }
            float mu = S * (1.f / 512.f);
            float var = SQ * (1.f / 512.f) - mu * mu;
            red[16] = mu;
            red[17] = rsqrtf(var + 1e-5f);
        }
        __syncthreads();
        float mu = red[16], inv = red[17];
        const float* vres = sK + 8 * H_SZ;
        __half2* oh = (__half2*)(mh + base + 8 * H_SZ);
        __half2* ol = (__half2*)(ml + base + 8 * H_SZ);
        float c0 = sC[2 * tid], c1 = sC[2 * tid + 1];
        float n0 = vres[2 * tid]     + __ldg(gamma + 2 * tid)     * (c0 - mu) * inv + __ldg(beta + 2 * tid);
        float n1 = vres[2 * tid + 1] + __ldg(gamma + 2 * tid + 1) * (c1 - mu) * inv + __ldg(beta + 2 * tid + 1);
        __half2 h, l;
        split2(n0, n1, h, l);
        oh[tid] = h;
        ol[tid] = l;
    }
}

// ============================================================================
// host orchestration
// ============================================================================
template<int EPI, int TERMS>
static void launch_hgT(const __half* Ah, const __half* Al, const __half* Bh, const __half* Bl,
                       const float* bias, float* C, __half* Ch, __half* Cl,
                       int M, int N, int lda)
{
    const int SM = (TERMS == 3) ? HG_SMEM3 : HG_SMEM2;
    cudaFuncSetAttribute(hgemm3<EPI, TERMS>, cudaFuncAttributeMaxDynamicSharedMemorySize, SM);
    dim3 grid(N / 128, M / 64);
    hgemm3<EPI, TERMS><<<grid, 256, SM>>>(Ah, Al, Bh, Bl, bias, C, Ch, Cl, N, lda);
}

struct Ptrs {
    __half *mh, *ml, *ah, *al, *nh, *nl, *xh, *xl, *wh, *wl;
    float *f;
};

// attention layer: ONE N=1024 GEMM (QK|VO, 2-term) + fused elementwise -> m pair
static void run_attention(const Ptrs& P, int layer, const float* gamma, const float* beta)
{
    const size_t wb = OFF_ATT + (size_t)layer * 2 * 262144;
    launch_hgT<0, 2>(P.ah, P.al, P.wh + wb, P.wl + wb, nullptr, P.f, nullptr, nullptr, ROWS, 1024, 512);
    cudaFuncSetAttribute(attn_fused, cudaFuncAttributeMaxDynamicSharedMemorySize, AF_SMEM);
    attn_fused<<<B_SZ, 512, AF_SMEM>>>(P.f, P.ah, P.al, gamma, beta, P.mh, P.ml);
}

extern "C" void kernel_launch(void* const* d_in, const int* in_sizes, int n_in,
                              void* d_out, int out_size)
{
    const float* x      = (const float*)d_in[0];
    const float* W_in   = (const float*)d_in[1];
    const float* b_in   = (const float*)d_in[2];
    const float* W_dr   = (const float*)d_in[3];
    const float* b_dr   = (const float*)d_in[4];
    const float* W_hyp  = (const float*)d_in[5];
    const float* b_hyp  = (const float*)d_in[6];
    const float* Wq_r   = (const float*)d_in[7];
    const float* Wq_i   = (const float*)d_in[8];
    const float* Wq_j   = (const float*)d_in[9];
    const float* Wq_k   = (const float*)d_in[10];
    const float* b_quat = (const float*)d_in[11];
    const float* W_low  = (const float*)d_in[12];
    const float* W_high = (const float*)d_in[13];
    const float* b_wav  = (const float*)d_in[14];
    const float* aWq    = (const float*)d_in[15];
    const float* aWk    = (const float*)d_in[16];
    const float* aWv    = (const float*)d_in[17];
    const float* aWo    = (const float*)d_in[18];
    const float* gamma  = (const float*)d_in[19];
    const float* beta   = (const float*)d_in[20];
    const float* W_out  = (const float*)d_in[21];
    const float* b_out  = (const float*)d_in[22];
    float* out = (float*)d_out;

    Ptrs P;
    cudaGetSymbolAddress((void**)&P.mh, g_mh); cudaGetSymbolAddress((void**)&P.ml, g_ml);
    cudaGetSymbolAddress((void**)&P.ah, g_ah); cudaGetSymbolAddress((void**)&P.al, g_al);
    cudaGetSymbolAddress((void**)&P.nh, g_nh); cudaGetSymbolAddress((void**)&P.nl, g_nl);
    cudaGetSymbolAddress((void**)&P.xh, g_xh); cudaGetSymbolAddress((void**)&P.xl, g_xl);
    cudaGetSymbolAddress((void**)&P.wh, g_wh); cudaGetSymbolAddress((void**)&P.wl, g_wl);
    cudaGetSymbolAddress((void**)&P.f,  g_f);

    prep_weights<<<(WTS_TOTAL + 255) / 256, 256>>>(
        W_in, W_dr, W_hyp, Wq_r, Wq_i, Wq_j, Wq_k, W_low, W_high, W_out, P.wh, P.wl);
    split_copy<<<(B_SZ * H_SZ / 4 + 255) / 256, 256>>>((const float4*)x, P.xh, P.xl, B_SZ * H_SZ / 4);

    const int AGG_BLOCKS = (B_SZ * NODES * 256 + 255) / 256;

    launch_hgT<1, 3>(P.xh, P.xl, P.wh + OFF_WIN, P.wl + OFF_WIN, b_in, nullptr, P.mh, P.ml, B_SZ, 4608, 512);
    launch_hgT<2, 3>(P.mh, P.ml, P.wh + OFF_WDR, P.wl + OFF_WDR, b_dr, nullptr, P.nh, P.nl, ROWS, 512, 512);
    agg_hl<<<AGG_BLOCKS, 256>>>((const __half2*)P.nh, (const __half2*)P.nl, (__half2*)P.mh, (__half2*)P.ml);
    launch_hgT<2, 3>(P.mh, P.ml, P.wh + OFF_WHYP, P.wl + OFF_WHYP, b_hyp, nullptr, P.ah, P.al, ROWS, 512, 512);

    combine_attn<<<dim3(32, 32, 6), dim3(16, 16)>>>(aWq, aWk, aWv, aWo, P.wh, P.wl);

    run_attention(P, 0, gamma, beta);
    launch_hgT<2, 3>(P.mh, P.ml, P.wh + OFF_QUAT, P.wl + OFF_QUAT, b_quat, nullptr, P.ah, P.al, ROWS, 512, 512);

    run_attention(P, 1, gamma + 512, beta + 512);
    launch_hgT<2, 3>(P.mh, P.ml, P.wh + OFF_WAV, P.wl + OFF_WAV, b_wav, nullptr, P.ah, P.al, ROWS, 512, 512);

    // ---- last layer: VO full (2-term) + QK node-8 rows (2-term) + attn_last ----
    {
        const size_t wb = OFF_ATT + (size_t)2 * 2 * 262144;
        launch_hgT<0, 2>(P.ah, P.al, P.wh + wb + 262144, P.wl + wb + 262144,
                         nullptr, P.f, nullptr, nullptr, ROWS, 512, 512);
        launch_hgT<0, 2>(P.ah + 8 * H_SZ, P.al + 8 * H_SZ, P.wh + wb, P.wl + wb,
                         nullptr, P.f + BH, nullptr, nullptr, B_SZ, 512, NODES * H_SZ);
        cudaFuncSetAttribute(attn_last, cudaFuncAttributeMaxDynamicSharedMemorySize, AL_SMEM);
        attn_last<<<B_SZ, 256, AL_SMEM>>>(P.f, P.f + BH, P.ah, P.al,
                                          gamma + 1024, beta + 1024, P.mh, P.ml);
    }

    launch_hgT<3, 3>(P.mh + 8 * H_SZ, P.ml + 8 * H_SZ, P.wh + OFF_WOUT, P.wl + OFF_WOUT,
                     b_out, out, nullptr, nullptr, B_SZ, 128, NODES * H_SZ);
}

// round 17
// speedup vs baseline: 1.5835x; 1.1322x over previous
#include <cuda_runtime.h>
#include <cuda_fp16.h>
#include <math.h>
#include <stdint.h>

#define B_SZ   16384
#define H_SZ   512
#define NODES  9
#define ROWS   (B_SZ * NODES)         // 147456
#define BH     (ROWS * H_SZ)          // 75497472

// ---------------- scratch (device globals; no allocation) ----------------
__device__ __half g_mh[BH], g_ml[BH];
__device__ __half g_ah[BH], g_al[BH];
__device__ __half g_nh[BH], g_nl[BH];
__device__ __half g_xh[B_SZ * H_SZ], g_xl[B_SZ * H_SZ];
__device__ float  g_f[2ull * BH];

// weights [N,K] K-major, K=512, hi/lo half pairs
#define OFF_WIN   0                    // 4608*512
#define OFF_WDR   2359296
#define OFF_WHYP  2621440
#define OFF_QUAT  2883584
#define OFF_WAV   3145728
#define OFF_ATT   3407872              // per layer: {Bt_qk, Bt_vo} contiguous (1024x512)
#define OFF_WOUT  6553600              // 128*512
#define WTS_TOTAL 6619136
__device__ __half g_wh[WTS_TOTAL], g_wl[WTS_TOTAL];

// ============================================================================
// helpers
// ============================================================================
__device__ __forceinline__ uint32_t smem_u32(const void* p) {
    uint32_t a;
    asm("{ .reg .u64 t; cvta.to.shared.u64 t, %1; cvt.u32.u64 %0, t; }" : "=r"(a) : "l"(p));
    return a;
}
__device__ __forceinline__ void cp_async16(uint32_t dst, const void* src) {
    asm volatile("cp.async.cg.shared.global [%0], [%1], 16;" :: "r"(dst), "l"(src) : "memory");
}
__device__ __forceinline__ void cp_commit() {
    asm volatile("cp.async.commit_group;" ::: "memory");
}
__device__ __forceinline__ void cp_wait1() {
    asm volatile("cp.async.wait_group 1;" ::: "memory");
}
__device__ __forceinline__ void ldm_x4(uint32_t addr, uint32_t& r0, uint32_t& r1,
                                       uint32_t& r2, uint32_t& r3) {
    asm volatile("ldmatrix.sync.aligned.m8n8.x4.shared.b16 {%0,%1,%2,%3}, [%4];"
                 : "=r"(r0), "=r"(r1), "=r"(r2), "=r"(r3) : "r"(addr));
}
__device__ __forceinline__ void mma_f16(float* c, const uint32_t* a, const uint32_t* b) {
    asm volatile(
        "mma.sync.aligned.m16n8k16.row.col.f32.f16.f16.f32 "
        "{%0,%1,%2,%3}, {%4,%5,%6,%7}, {%8,%9}, {%0,%1,%2,%3};"
        : "+f"(c[0]), "+f"(c[1]), "+f"(c[2]), "+f"(c[3])
        : "r"(a[0]), "r"(a[1]), "r"(a[2]), "r"(a[3]), "r"(b[0]), "r"(b[1]));
}
__device__ __forceinline__ void split2(float d0, float d1, __half2& h, __half2& l) {
    __half h0 = __float2half_rn(d0), h1 = __float2half_rn(d1);
    h = __halves2half2(h0, h1);
    l = __floats2half2_rn(d0 - __half2float(h0), d1 - __half2float(h1));
}

// ============================================================================
// fp16 GEMM: C[M,N] = A[M,512] @ Bt[N,512]^T
// TERMS=3: AhBh + AhBl + AlBh;  TERMS=2: AhBh + AlBh (weight-lo dropped)
// EPI: 0 fp32 C; 1 bias+lrelu -> HL; 2 bias+tanh -> HL; 3 bias -> fp32
// BM=64, BN=128, 256 thr, 8 warps (2x4), warp 32x32, 2-stage, 2 CTAs/SM
// ============================================================================
#define A_ST 8192
#define B_ST 16384
#define HG_SMEM3 (2 * (2 * A_ST + 2 * B_ST) + 1024)
#define HG_SMEM2 (2 * (2 * A_ST + B_ST) + 1024)

template<int EPI, int TERMS>
__global__ __launch_bounds__(256, 2)
void hgemm3(const __half* __restrict__ Ah, const __half* __restrict__ Al,
            const __half* __restrict__ Bh, const __half* __restrict__ Bl,
            const float* __restrict__ bias, float* __restrict__ C,
            __half* __restrict__ Ch, __half* __restrict__ Cl,
            int N, int lda)
{
    extern __shared__ char smraw[];
    const uint32_t base = (smem_u32(smraw) + 1023) & ~1023u;
    const uint32_t sAh = base;
    const uint32_t sAl = base + 2 * A_ST;
    const uint32_t sBh = base + 4 * A_ST;
    const uint32_t sBl = base + 4 * A_ST + 2 * B_ST;   // unused when TERMS==2

    const int col0 = blockIdx.x * 128;
    const int row0 = blockIdx.y * 64;

    const int tid    = threadIdx.x;
    const int lane   = tid & 31;
    const int wid    = tid >> 5;
    const int warp_m = wid >> 2;
    const int warp_n = wid & 3;

    const int lm = tid >> 3;
    const int lq = tid & 7;

    const int mat = lane >> 3;
    const int mr  = lane & 7;
    int rbA[2], s7A[2];
    #pragma unroll
    for (int mf = 0; mf < 2; ++mf) {
        int m = warp_m * 32 + mf * 16 + (mat & 1) * 8 + mr;
        rbA[mf] = m * 128; s7A[mf] = m & 7;
    }
    const int qaA = mat >> 1;
    int rbB[2], s7B[2];
    #pragma unroll
    for (int p = 0; p < 2; ++p) {
        int n = warp_n * 32 + (2 * p + (mat >> 1)) * 8 + mr;
        rbB[p] = n * 128; s7B[p] = n & 7;
    }
    const int qaB = mat & 1;

    float acc[2][4][4];
    #pragma unroll
    for (int i = 0; i < 2; ++i)
        #pragma unroll
        for (int j = 0; j < 4; ++j)
            #pragma unroll
            for (int k = 0; k < 4; ++k) acc[i][j][k] = 0.f;

    #pragma unroll
    for (int st = 0; st < 2; ++st) {
        #pragma unroll
        for (int i = 0; i < 2; ++i) {
            const int row = lm + i * 32;
            const uint32_t d = st * A_ST + row * 128 + (((lq ^ (row & 7)) << 4));
            const size_t oa = (size_t)(row0 + row) * lda + st * 64 + lq * 8;
            cp_async16(sAh + d, Ah + oa);
            cp_async16(sAl + d, Al + oa);
        }
        #pragma unroll
        for (int i = 0; i < 4; ++i) {
            const int row = lm + i * 32;
            const uint32_t d = st * B_ST + row * 128 + (((lq ^ (row & 7)) << 4));
            const size_t ob = (size_t)(col0 + row) * 512 + st * 64 + lq * 8;
            cp_async16(sBh + d, Bh + ob);
            if (TERMS == 3) cp_async16(sBl + d, Bl + ob);
        }
        cp_commit();
    }

    #pragma unroll 1
    for (int t = 0; t < 8; ++t) {
        cp_wait1();
        __syncthreads();

        const uint32_t pAh = sAh + (t & 1) * A_ST;
        const uint32_t pAl = sAl + (t & 1) * A_ST;
        const uint32_t pBh = sBh + (t & 1) * B_ST;
        const uint32_t pBl = sBl + (t & 1) * B_ST;

        #pragma unroll
        for (int ks = 0; ks < 4; ++ks) {
            uint32_t ah[2][4], al[2][4];
            #pragma unroll
            for (int mf = 0; mf < 2; ++mf) {
                const uint32_t off = rbA[mf] + (((2 * ks + qaA) ^ s7A[mf]) << 4);
                ldm_x4(pAh + off, ah[mf][0], ah[mf][1], ah[mf][2], ah[mf][3]);
                ldm_x4(pAl + off, al[mf][0], al[mf][1], al[mf][2], al[mf][3]);
            }
            #pragma unroll
            for (int p = 0; p < 2; ++p) {
                uint32_t bh[2][2], bl[2][2];
                const uint32_t off = rbB[p] + (((2 * ks + qaB) ^ s7B[p]) << 4);
                ldm_x4(pBh + off, bh[0][0], bh[0][1], bh[1][0], bh[1][1]);
                if (TERMS == 3)
                    ldm_x4(pBl + off, bl[0][0], bl[0][1], bl[1][0], bl[1][1]);
                #pragma unroll
                for (int mf = 0; mf < 2; ++mf)
                    #pragma unroll
                    for (int q = 0; q < 2; ++q) {
                        float* a_ = acc[mf][2 * p + q];
                        mma_f16(a_, ah[mf], bh[q]);
                        if (TERMS == 3) mma_f16(a_, ah[mf], bl[q]);
                        mma_f16(a_, al[mf], bh[q]);
                    }
            }
        }
        __syncthreads();
        if (t + 2 < 8) {
            const int st = t & 1;
            #pragma unroll
            for (int i = 0; i < 2; ++i) {
                const int row = lm + i * 32;
                const uint32_t d = st * A_ST + row * 128 + (((lq ^ (row & 7)) << 4));
                const size_t oa = (size_t)(row0 + row) * lda + (t + 2) * 64 + lq * 8;
                cp_async16(sAh + d, Ah + oa);
                cp_async16(sAl + d, Al + oa);
            }
            #pragma unroll
            for (int i = 0; i < 4; ++i) {
                const int row = lm + i * 32;
                const uint32_t d = st * B_ST + row * 128 + (((lq ^ (row & 7)) << 4));
                const size_t ob = (size_t)(col0 + row) * 512 + (t + 2) * 64 + lq * 8;
                cp_async16(sBh + d, Bh + ob);
                if (TERMS == 3) cp_async16(sBl + d, Bl + ob);
            }
        }
        cp_commit();
    }

    const int g  = lane >> 2;
    const int t4 = lane & 3;
    #pragma unroll
    for (int mf = 0; mf < 2; ++mf) {
        #pragma unroll
        for (int nf = 0; nf < 4; ++nf) {
            const int r1 = row0 + warp_m * 32 + mf * 16 + g;
            const int cc = col0 + warp_n * 32 + nf * 8 + t4 * 2;
            float d[4] = {acc[mf][nf][0], acc[mf][nf][1], acc[mf][nf][2], acc[mf][nf][3]};
            if (EPI != 0) {
                float b0 = __ldg(bias + cc), b1 = __ldg(bias + cc + 1);
                d[0] += b0; d[1] += b1; d[2] += b0; d[3] += b1;
                #pragma unroll
                for (int i = 0; i < 4; ++i) {
                    if (EPI == 1)      d[i] = d[i] > 0.f ? d[i] : 0.01f * d[i];
                    else if (EPI == 2) d[i] = tanhf(d[i]);
                }
            }
            if (EPI == 0 || EPI == 3) {
                *(float2*)(C + (size_t)r1 * N + cc)       = make_float2(d[0], d[1]);
                *(float2*)(C + (size_t)(r1 + 8) * N + cc) = make_float2(d[2], d[3]);
            } else {
                __half2 h, l;
                split2(d[0], d[1], h, l);
                *(__half2*)(Ch + (size_t)r1 * N + cc) = h;
                *(__half2*)(Cl + (size_t)r1 * N + cc) = l;
                split2(d[2], d[3], h, l);
                *(__half2*)(Ch + (size_t)(r1 + 8) * N + cc) = h;
                *(__half2*)(Cl + (size_t)(r1 + 8) * N + cc) = l;
            }
        }
    }
}

// ============================================================================
// weight prep (non-attention weights)
// ============================================================================
__constant__ int   c_which[16] = {0,1,2,3, 1,0,3,2, 2,3,0,1, 3,2,1,0};
__constant__ float c_sign [16] = {1.f,-1.f,-1.f,-1.f,
                                  1.f, 1.f, 1.f,-1.f,
                                  1.f,-1.f, 1.f, 1.f,
                                  1.f, 1.f,-1.f, 1.f};

__global__ void prep_weights(
    const float* __restrict__ W_in,  const float* __restrict__ W_dr,
    const float* __restrict__ W_hyp, const float* __restrict__ Wq_r,
    const float* __restrict__ Wq_i,  const float* __restrict__ Wq_j,
    const float* __restrict__ Wq_k,  const float* __restrict__ W_low,
    const float* __restrict__ W_high,const float* __restrict__ W_out,
    __half* __restrict__ oh, __half* __restrict__ ol)
{
    int idx = blockIdx.x * 256 + threadIdx.x;
    if (idx >= WTS_TOTAL) return;
    if (idx >= OFF_ATT && idx < OFF_WOUT) return;
    float v;
    if (idx < OFF_WDR) {
        int n = idx >> 9, k = idx & 511;
        v = W_in[(size_t)k * 4608 + n];
    } else if (idx < OFF_WHYP) {
        int r = idx - OFF_WDR, n = r >> 9, k = r & 511;
        v = W_dr[(size_t)k * 512 + n];
    } else if (idx < OFF_QUAT) {
        int r = idx - OFF_WHYP, n = r >> 9, k = r & 511;
        v = W_hyp[(size_t)k * 512 + n];
    } else if (idx < OFF_WAV) {
        int r = idx - OFF_QUAT, n = r >> 9, k = r & 511;
        int co = n >> 7, ho = n & 127, ci = k >> 7, hi = k & 127;
        const float* mats[4] = {Wq_r, Wq_i, Wq_j, Wq_k};
        int sel = co * 4 + ci;
        v = c_sign[sel] * mats[c_which[sel]][hi * 128 + ho];
    } else if (idx < OFF_ATT) {
        int r = idx - OFF_WAV, n = r >> 9, k = r & 511;
        int ho = n >> 1, po = n & 1, hi = k >> 1, pi = k & 1;
        float wl = W_low[hi * 256 + ho], wh = W_high[hi * 256 + ho];
        v = (pi == po) ? 0.5f * (wl + wh) : 0.5f * (wl - wh);
    } else {
        int r = idx - OFF_WOUT, n = r >> 9, k = r & 511;
        v = W_out[(size_t)k * 128 + n];
    }
    __half h = __float2half_rn(v);
    oh[idx] = h;
    ol[idx] = __float2half_rn(v - __half2float(h));
}

__global__ void combine_attn(const float* __restrict__ aWq, const float* __restrict__ aWk,
                             const float* __restrict__ aWv, const float* __restrict__ aWo,
                             __half* __restrict__ oh, __half* __restrict__ ol)
{
    __shared__ float As[16][17], Bs[16][17];
    const int z = blockIdx.z, l = z >> 1, type = z & 1;
    const int tx = threadIdx.x, ty = threadIdx.y;
    const size_t wl_off = (size_t)l * 262144;
    const float* Wq = aWq + wl_off;
    const float* Wk = aWk + wl_off;
    const float* Wv = aWv + wl_off;
    const float* Wo = aWo + wl_off;

    float acc = 0.f;
    for (int m0 = 0; m0 < 512; m0 += 16) {
        if (type == 0) {
            As[ty][tx] = Wk[(size_t)(blockIdx.y * 16 + ty) * 512 + m0 + tx];
            Bs[ty][tx] = Wq[(size_t)(blockIdx.x * 16 + ty) * 512 + m0 + tx];
        } else {
            As[ty][tx] = Wo[(size_t)(m0 + ty) * 512 + blockIdx.y * 16 + tx];
            Bs[ty][tx] = Wv[(size_t)(blockIdx.x * 16 + ty) * 512 + m0 + tx];
        }
        __syncthreads();
        if (type == 0) {
            #pragma unroll
            for (int h = 0; h < 16; ++h) acc += As[ty][h] * Bs[tx][h];
        } else {
            #pragma unroll
            for (int m = 0; m < 16; ++m) acc += Bs[tx][m] * As[m][ty];
        }
        __syncthreads();
    }
    const int n = blockIdx.y * 16 + ty;
    const int k = blockIdx.x * 16 + tx;
    const size_t o = (size_t)OFF_ATT + (size_t)z * 262144 + (size_t)n * 512 + k;
    __half h = __float2half_rn(acc);
    oh[o] = h;
    ol[o] = __float2half_rn(acc - __half2float(h));
}

__global__ void split_copy(const float4* __restrict__ in, __half* __restrict__ H,
                           __half* __restrict__ L, int n4)
{
    int i = blockIdx.x * 256 + threadIdx.x;
    if (i >= n4) return;
    float4 v = in[i];
    __half2 h, l;
    split2(v.x, v.y, h, l);
    ((__half2*)H)[2*i]   = h; ((__half2*)L)[2*i]   = l;
    split2(v.z, v.w, h, l);
    ((__half2*)H)[2*i+1] = h; ((__half2*)L)[2*i+1] = l;
}

// ============================================================================
// standalone agg (used once, after W_dr)
// ============================================================================
__global__ void agg_hl(const __half2* __restrict__ ih, const __half2* __restrict__ il,
                       __half2* __restrict__ oh, __half2* __restrict__ ol)
{
    int idx = blockIdx.x * 256 + threadIdx.x;
    const int TOT = B_SZ * NODES * 256;
    if (idx >= TOT) return;
    int h2 = idx & 255;
    int rn = (idx >> 8) % NODES;
    int b  = idx / (NODES * 256);
    size_t p = (size_t)(b * NODES + rn) * 256 + h2;
    __half2 xh = ih[p], xl = il[p];
    if (rn == 8) { oh[idx] = xh; ol[idx] = xl; return; }
    int src = (rn & 1) ? (rn >> 1) : (rn >> 1) + 4;
    size_t q = (size_t)(b * NODES + src) * 256 + h2;
    float2 fa = __half22float2(xh), fal = __half22float2(xl);
    float2 fc = __half22float2(ih[q]), fcl = __half22float2(il[q]);
    float v0 = 0.5f * ((fa.x + fal.x) + (fc.x + fcl.x));
    float v1 = 0.5f * ((fa.y + fal.y) + (fc.y + fcl.y));
    __half2 h, l;
    split2(v0, v1, h, l);
    oh[idx] = h; ol[idx] = l;
}

// ============================================================================
// fused attention + drnorm + residual + agg (layers 0,1); QV = ROWS x 1024
// ============================================================================
#define AF_SMEM (3 * NODES * H_SZ * 4 + 512)

__global__ __launch_bounds__(512)
void attn_fused(const float* __restrict__ QV,
                const __half* __restrict__ vh, const __half* __restrict__ vl,
                const float* __restrict__ gamma, const float* __restrict__ beta,
                __half* __restrict__ mh, __half* __restrict__ ml)
{
    extern __shared__ float sm[];
    float* sK = sm;
    float* sV = sm + NODES * H_SZ;
    float* sQ = sm + 2 * NODES * H_SZ;
    float* sS = sm + 3 * NODES * H_SZ;

    const int b   = blockIdx.x;
    const int tid = threadIdx.x;
    const int warp = tid >> 5, lane = tid & 31;
    const size_t base   = (size_t)b * NODES * H_SZ;
    const size_t baseQV = (size_t)b * NODES * 1024;

    const uint4* Hv = (const uint4*)(vh + base);
    const uint4* Lv = (const uint4*)(vl + base);
    for (int i = tid; i < NODES * H_SZ / 8; i += 512) {
        uint4 hu = Hv[i], lu = Lv[i];
        const __half2* hp = (const __half2*)&hu;
        const __half2* lp = (const __half2*)&lu;
        float4 o0, o1;
        {
            float2 a = __half22float2(hp[0]), c = __half22float2(lp[0]);
            o0.x = a.x + c.x; o0.y = a.y + c.y;
            a = __half22float2(hp[1]); c = __half22float2(lp[1]);
            o0.z = a.x + c.x; o0.w = a.y + c.y;
            a = __half22float2(hp[2]); c = __half22float2(lp[2]);
            o1.x = a.x + c.x; o1.y = a.y + c.y;
            a = __half22float2(hp[3]); c = __half22float2(lp[3]);
            o1.z = a.x + c.x; o1.w = a.y + c.y;
        }
        ((float4*)sK)[2 * i]     = o0;
        ((float4*)sK)[2 * i + 1] = o1;
    }
    for (int i = tid; i < NODES * 128; i += 512) {
        int rn = i >> 7, c4 = i & 127;
        const float* row = QV + baseQV + (size_t)rn * 1024 + c4 * 4;
        ((float4*)sQ)[i] = *(const float4*)(row);
        ((float4*)sV)[i] = *(const float4*)(row + 512);
    }
    __syncthreads();

    const float scale = 0.044194173824159216f;
    for (int p = warp; p < 81; p += 16) {
        int q = p / 9, kk = p % 9;
        const float4* Q4 = (const float4*)(sQ + q * H_SZ);
        const float4* K4 = (const float4*)(sK + kk * H_SZ);
        float s = 0.f;
        #pragma unroll
        for (int h4 = 0; h4 < 4; ++h4) {
            float4 qv = Q4[lane + 32 * h4];
            float4 kv = K4[lane + 32 * h4];
            s += qv.x * kv.x + qv.y * kv.y + qv.z * kv.z + qv.w * kv.w;
        }
        #pragma unroll
        for (int o = 16; o; o >>= 1) s += __shfl_down_sync(0xffffffffu, s, o);
        if (lane == 0) sS[q * 9 + kk] = s * scale;
    }
    __syncthreads();

    if (tid < 9) {
        float mx = -1e30f;
        #pragma unroll
        for (int k = 0; k < 9; ++k) mx = fmaxf(mx, sS[tid * 9 + k]);
        float sum = 0.f;
        #pragma unroll
        for (int k = 0; k < 9; ++k) { float e = expf(sS[tid * 9 + k] - mx); sS[tid * 9 + k] = e; sum += e; }
        float inv = 1.f / sum;
        #pragma unroll
        for (int k = 0; k < 9; ++k) sS[tid * 9 + k] *= inv;
    }
    __syncthreads();

    for (int i = tid; i < NODES * 128; i += 512) {
        int q = i >> 7, c4 = i & 127;
        const float* a = sS + q * 9;
        float4 acc = make_float4(0.f, 0.f, 0.f, 0.f);
        #pragma unroll
        for (int k = 0; k < 9; ++k) {
            float4 v = ((const float4*)(sV + k * H_SZ))[c4];
            float ak = a[k];
            acc.x = fmaf(ak, v.x, acc.x);
            acc.y = fmaf(ak, v.y, acc.y);
            acc.z = fmaf(ak, v.z, acc.z);
            acc.w = fmaf(ak, v.w, acc.w);
        }
        ((float4*)(sQ + q * H_SZ))[c4] = acc;
    }
    __syncthreads();

    for (int r = warp; r < 9; r += 16) {
        const float* o = sQ + r * H_SZ;
        float s = 0.f, sq = 0.f;
        #pragma unroll
        for (int i = 0; i < 16; ++i) {
            float v = o[lane + 32 * i];
            s += v; sq += v * v;
        }
        #pragma unroll
        for (int off = 16; off; off >>= 1) {
            s  += __shfl_down_sync(0xffffffffu, s, off);
            sq += __shfl_down_sync(0xffffffffu, sq, off);
        }
        float mu  = __shfl_sync(0xffffffffu, s,  0) * (1.f / 512.f);
        float msq = __shfl_sync(0xffffffffu, sq, 0) * (1.f / 512.f);
        float inv = rsqrtf(msq - mu * mu + 1e-5f);
        float* nf = sQ + r * H_SZ;
        const float* vres = sK + r * H_SZ;
        #pragma unroll
        for (int i = 0; i < 16; ++i) {
            int h = lane + 32 * i;
            nf[h] = vres[h] + __ldg(gamma + h) * (nf[h] - mu) * inv + __ldg(beta + h);
        }
    }
    __syncthreads();

    uint4* OH = (uint4*)(mh + base);
    uint4* OL = (uint4*)(ml + base);
    for (int i = tid; i < NODES * H_SZ / 8; i += 512) {
        int c8 = i & 63;
        int rn = i >> 6;
        float4 a0 = ((const float4*)(sQ + rn * H_SZ))[2 * c8];
        float4 a1 = ((const float4*)(sQ + rn * H_SZ))[2 * c8 + 1];
        if (rn != 8) {
            int src = (rn & 1) ? (rn >> 1) : (rn >> 1) + 4;
            float4 c0 = ((const float4*)(sQ + src * H_SZ))[2 * c8];
            float4 c1 = ((const float4*)(sQ + src * H_SZ))[2 * c8 + 1];
            a0.x = 0.5f * (a0.x + c0.x); a0.y = 0.5f * (a0.y + c0.y);
            a0.z = 0.5f * (a0.z + c0.z); a0.w = 0.5f * (a0.w + c0.w);
            a1.x = 0.5f * (a1.x + c1.x); a1.y = 0.5f * (a1.y + c1.y);
            a1.z = 0.5f * (a1.z + c1.z); a1.w = 0.5f * (a1.w + c1.w);
        }
        uint4 uh, ul;
        __half2* uhp = (__half2*)&uh;
        __half2* ulp = (__half2*)&ul;
        split2(a0.x, a0.y, uhp[0], ulp[0]);
        split2(a0.z, a0.w, uhp[1], ulp[1]);
        split2(a1.x, a1.y, uhp[2], ulp[2]);
        split2(a1.z, a1.w, uhp[3], ulp[3]);
        OH[i] = uh;
        OL[i] = ul;
    }
}

// ============================================================================
// last-layer attention (unchanged)
// ============================================================================
#define AL_SMEM ((2 * NODES * H_SZ + H_SZ) * 4 + 512)

__global__ __launch_bounds__(256)
void attn_last(const float* __restrict__ V, const float* __restrict__ Q8,
               const __half* __restrict__ vh, const __half* __restrict__ vl,
               const float* __restrict__ gamma, const float* __restrict__ beta,
               __half* __restrict__ mh, __half* __restrict__ ml)
{
    extern __shared__ float sm[];
    float* sK = sm;
    float* sV = sm + NODES * H_SZ;
    float* sC = sm + 2 * NODES * H_SZ;
    float* sS = sm + 2 * NODES * H_SZ + H_SZ;

    const int b   = blockIdx.x;
    const int tid = threadIdx.x;
    const int warp = tid >> 5, lane = tid & 31;
    const size_t base = (size_t)b * NODES * H_SZ;

    const __half2* K2h = (const __half2*)(vh + base);
    const __half2* K2l = (const __half2*)(vl + base);
    for (int i = tid; i < NODES * H_SZ / 2; i += 256) {
        float2 h = __half22float2(K2h[i]);
        float2 l = __half22float2(K2l[i]);
        sK[2*i]   = h.x + l.x;
        sK[2*i+1] = h.y + l.y;
    }
    const float4* V4 = (const float4*)(V + base);
    for (int i = tid; i < NODES * H_SZ / 4; i += 256)
        ((float4*)sV)[i] = V4[i];
    if (tid < 128)
        ((float4*)sC)[tid] = ((const float4*)(Q8 + (size_t)b * H_SZ))[tid];
    __syncthreads();

    const float scale = 0.044194173824159216f;
    for (int kk = warp; kk < 9; kk += 8) {
        const float4* Q4 = (const float4*)sC;
        const float4* K4 = (const float4*)(sK + kk * H_SZ);
        float s = 0.f;
        #pragma unroll
        for (int h4 = 0; h4 < 4; ++h4) {
            float4 qv = Q4[lane + 32 * h4];
            float4 kv = K4[lane + 32 * h4];
            s += qv.x * kv.x + qv.y * kv.y + qv.z * kv.z + qv.w * kv.w;
        }
        #pragma unroll
        for (int o = 16; o; o >>= 1) s += __shfl_down_sync(0xffffffffu, s, o);
        if (lane == 0) sS[kk] = s * scale;
    }
    __syncthreads();

    if (tid == 0) {
        float mx = -1e30f;
        #pragma unroll
        for (int k = 0; k < 9; ++k) mx = fmaxf(mx, sS[k]);
        float sum = 0.f;
        #pragma unroll
        for (int k = 0; k < 9; ++k) { float e = expf(sS[k] - mx); sS[k] = e; sum += e; }
        float inv = 1.f / sum;
        #pragma unroll
        for (int k = 0; k < 9; ++k) sS[k] *= inv;
    }
    __syncthreads();

    if (tid < 128) {
        float4 acc = make_float4(0.f, 0.f, 0.f, 0.f);
        #pragma unroll
        for (int k = 0; k < 9; ++k) {
            float4 v = ((const float4*)(sV + k * H_SZ))[tid];
            float ak = sS[k];
            acc.x = fmaf(ak, v.x, acc.x);
            acc.y = fmaf(ak, v.y, acc.y);
            acc.z = fmaf(ak, v.z, acc.z);
            acc.w = fmaf(ak, v.w, acc.w);
        }
        ((float4*)sC)[tid] = acc;
    }
    __syncthreads();

    {
        float v1 = sC[tid], v2 = sC[tid + 256];
        float s = v1 + v2, sq = v1 * v1 + v2 * v2;
        #pragma unroll
        for (int o = 16; o; o >>= 1) {
            s  += __shfl_down_sync(0xffffffffu, s, o);
            sq += __shfl_down_sync(0xffffffffu, sq, o);
        }
        float* red = sS + 9;
        if (lane == 0) { red[warp] = s; red[warp + 8] = sq; }
        __syncthreads();
        if (tid == 0) {
            float S = 0.f, SQ = 0.f;
            #pragma unroll
            for (int w = 0; w < 8; ++w) { S += red[w]; SQ += red[w + 8]; }
            float mu = S * (1.f / 512.f);
            float var = SQ * (1.f / 512.f) - mu * mu;
            red[16] = mu;
            red[17] = rsqrtf(var + 1e-5f);
        }
        __syncthreads();
        float mu = red[16], inv = red[17];
        const float* vres = sK + 8 * H_SZ;
        __half2* oh = (__half2*)(mh + base + 8 * H_SZ);
        __half2* ol = (__half2*)(ml + base + 8 * H_SZ);
        float c0 = sC[2 * tid], c1 = sC[2 * tid + 1];
        float n0 = vres[2 * tid]     + __ldg(gamma + 2 * tid)     * (c0 - mu) * inv + __ldg(beta + 2 * tid);
        float n1 = vres[2 * tid + 1] + __ldg(gamma + 2 * tid + 1) * (c1 - mu) * inv + __ldg(beta + 2 * tid + 1);
        __half2 h, l;
        split2(n0, n1, h, l);
        oh[tid] = h;
        ol[tid] = l;
    }
}

// ============================================================================
// host orchestration
// ============================================================================
template<int EPI, int TERMS>
static void launch_hgT(const __half* Ah, const __half* Al, const __half* Bh, const __half* Bl,
                       const float* bias, float* C, __half* Ch, __half* Cl,
                       int M, int N, int lda)
{
    const int SM = (TERMS == 3) ? HG_SMEM3 : HG_SMEM2;
    cudaFuncSetAttribute(hgemm3<EPI, TERMS>, cudaFuncAttributeMaxDynamicSharedMemorySize, SM);
    dim3 grid(N / 128, M / 64);
    hgemm3<EPI, TERMS><<<grid, 256, SM>>>(Ah, Al, Bh, Bl, bias, C, Ch, Cl, N, lda);
}

struct Ptrs {
    __half *mh, *ml, *ah, *al, *nh, *nl, *xh, *xl, *wh, *wl;
    float *f;
};

static void run_attention(const Ptrs& P, int layer, const float* gamma, const float* beta)
{
    const size_t wb = OFF_ATT + (size_t)layer * 2 * 262144;
    launch_hgT<0, 2>(P.ah, P.al, P.wh + wb, P.wl + wb, nullptr, P.f, nullptr, nullptr, ROWS, 1024, 512);
    cudaFuncSetAttribute(attn_fused, cudaFuncAttributeMaxDynamicSharedMemorySize, AF_SMEM);
    attn_fused<<<B_SZ, 512, AF_SMEM>>>(P.f, P.ah, P.al, gamma, beta, P.mh, P.ml);
}

extern "C" void kernel_launch(void* const* d_in, const int* in_sizes, int n_in,
                              void* d_out, int out_size)
{
    const float* x      = (const float*)d_in[0];
    const float* W_in   = (const float*)d_in[1];
    const float* b_in   = (const float*)d_in[2];
    const float* W_dr   = (const float*)d_in[3];
    const float* b_dr   = (const float*)d_in[4];
    const float* W_hyp  = (const float*)d_in[5];
    const float* b_hyp  = (const float*)d_in[6];
    const float* Wq_r   = (const float*)d_in[7];
    const float* Wq_i   = (const float*)d_in[8];
    const float* Wq_j   = (const float*)d_in[9];
    const float* Wq_k   = (const float*)d_in[10];
    const float* b_quat = (const float*)d_in[11];
    const float* W_low  = (const float*)d_in[12];
    const float* W_high = (const float*)d_in[13];
    const float* b_wav  = (const float*)d_in[14];
    const float* aWq    = (const float*)d_in[15];
    const float* aWk    = (const float*)d_in[16];
    const float* aWv    = (const float*)d_in[17];
    const float* aWo    = (const float*)d_in[18];
    const float* gamma  = (const float*)d_in[19];
    const float* beta   = (const float*)d_in[20];
    const float* W_out  = (const float*)d_in[21];
    const float* b_out  = (const float*)d_in[22];
    float* out = (float*)d_out;

    Ptrs P;
    cudaGetSymbolAddress((void**)&P.mh, g_mh); cudaGetSymbolAddress((void**)&P.ml, g_ml);
    cudaGetSymbolAddress((void**)&P.ah, g_ah); cudaGetSymbolAddress((void**)&P.al, g_al);
    cudaGetSymbolAddress((void**)&P.nh, g_nh); cudaGetSymbolAddress((void**)&P.nl, g_nl);
    cudaGetSymbolAddress((void**)&P.xh, g_xh); cudaGetSymbolAddress((void**)&P.xl, g_xl);
    cudaGetSymbolAddress((void**)&P.wh, g_wh); cudaGetSymbolAddress((void**)&P.wl, g_wl);
    cudaGetSymbolAddress((void**)&P.f,  g_f);

    prep_weights<<<(WTS_TOTAL + 255) / 256, 256>>>(
        W_in, W_dr, W_hyp, Wq_r, Wq_i, Wq_j, Wq_k, W_low, W_high, W_out, P.wh, P.wl);
    split_copy<<<(B_SZ * H_SZ / 4 + 255) / 256, 256>>>((const float4*)x, P.xh, P.xl, B_SZ * H_SZ / 4);

    const int AGG_BLOCKS = (B_SZ * NODES * 256 + 255) / 256;

    // all forward GEMMs 2-term (weight-lo dropped); W_out kept 3-term
    launch_hgT<1, 2>(P.xh, P.xl, P.wh + OFF_WIN, P.wl + OFF_WIN, b_in, nullptr, P.mh, P.ml, B_SZ, 4608, 512);
    launch_hgT<2, 2>(P.mh, P.ml, P.wh + OFF_WDR, P.wl + OFF_WDR, b_dr, nullptr, P.nh, P.nl, ROWS, 512, 512);
    agg_hl<<<AGG_BLOCKS, 256>>>((const __half2*)P.nh, (const __half2*)P.nl, (__half2*)P.mh, (__half2*)P.ml);
    launch_hgT<2, 2>(P.mh, P.ml, P.wh + OFF_WHYP, P.wl + OFF_WHYP, b_hyp, nullptr, P.ah, P.al, ROWS, 512, 512);

    combine_attn<<<dim3(32, 32, 6), dim3(16, 16)>>>(aWq, aWk, aWv, aWo, P.wh, P.wl);

    run_attention(P, 0, gamma, beta);
    launch_hgT<2, 2>(P.mh, P.ml, P.wh + OFF_QUAT, P.wl + OFF_QUAT, b_quat, nullptr, P.ah, P.al, ROWS, 512, 512);

    run_attention(P, 1, gamma + 512, beta + 512);
    launch_hgT<2, 2>(P.mh, P.ml, P.wh + OFF_WAV, P.wl + OFF_WAV, b_wav, nullptr, P.ah, P.al, ROWS, 512, 512);

    // ---- last layer: VO full (2-term) + QK node-8 rows (2-term) + attn_last ----
    {
        const size_t wb = OFF_ATT + (size_t)2 * 2 * 262144;
        launch_hgT<0, 2>(P.ah, P.al, P.wh + wb + 262144, P.wl + wb + 262144,
                         nullptr, P.f, nullptr, nullptr, ROWS, 512, 512);
        launch_hgT<0, 2>(P.ah + 8 * H_SZ, P.al + 8 * H_SZ, P.wh + wb, P.wl + wb,
                         nullptr, P.f + BH, nullptr, nullptr, B_SZ, 512, NODES * H_SZ);
        cudaFuncSetAttribute(attn_last, cudaFuncAttributeMaxDynamicSharedMemorySize, AL_SMEM);
        attn_last<<<B_SZ, 256, AL_SMEM>>>(P.f, P.f + BH, P.ah, P.al,
                                          gamma + 1024, beta + 1024, P.mh, P.ml);
    }

    launch_hgT<3, 3>(P.mh + 8 * H_SZ, P.ml + 8 * H_SZ, P.wh + OFF_WOUT, P.wl + OFF_WOUT,
                     b_out, out, nullptr, nullptr, B_SZ, 128, NODES * H_SZ);
}